// round 1
// baseline (speedup 1.0000x reference)
#include <cuda_runtime.h>
#include <math.h>

// ---------------- problem constants ----------------
#define B_    2
#define T_    1024
#define C_    1024
#define H_    16
#define HD_   64
#define DC    256
#define DC1   256
#define DR    32
#define DN    32
#define DOWN  544           // DC + DC1 + DR
#define VSZ   32000
#define L_    4
#define GC    32
#define TKN   2048          // B*T
#define KVW   1536          // H*(DN+HD)
#define EPSF  1.1920929e-7f

// ---------------- scratch (device globals; no allocation allowed) ----------------
__device__ float g_x   [TKN * C_];     // residual stream
__device__ float g_x0  [TKN * C_];     // x0
__device__ float g_xn  [TKN * C_];     // normalized activations
__device__ float g_down[TKN * DOWN];
__device__ float g_kv  [TKN * KVW];
__device__ float g_qraw[TKN * C_];
__device__ float g_q   [B_ * H_ * T_ * HD_];   // [B,H,T,64]
__device__ float g_k   [B_ * H_ * T_ * HD_];
__device__ float g_v   [B_ * H_ * T_ * HD_];
__device__ float g_y   [TKN * C_];             // attn output (b,t,h*d)
__device__ float g_h   [TKN * 4096];           // mlp hidden

// ---------------- block reduce ----------------
__device__ __forceinline__ float blockReduceSum(float v) {
    __shared__ float red[32];
    int lane = threadIdx.x & 31, w = threadIdx.x >> 5;
    #pragma unroll
    for (int o = 16; o; o >>= 1) v += __shfl_xor_sync(0xffffffffu, v, o);
    if (lane == 0) red[w] = v;
    __syncthreads();
    v = (threadIdx.x < (blockDim.x >> 5)) ? red[threadIdx.x] : 0.0f;
    if (w == 0) {
        #pragma unroll
        for (int o = 16; o; o >>= 1) v += __shfl_xor_sync(0xffffffffu, v, o);
        if (lane == 0) red[0] = v;
    }
    __syncthreads();
    return red[0];
}

// ---------------- embed + rmsnorm ----------------
__global__ __launch_bounds__(256) void embed_kernel(
    const int* __restrict__ idx, const float* __restrict__ wte,
    float* __restrict__ x, float* __restrict__ x0)
{
    int i = blockIdx.x;
    const float* row = wte + (size_t)idx[i] * C_;
    float v[4]; float ss = 0.f;
    #pragma unroll
    for (int j = 0; j < 4; j++) { v[j] = row[threadIdx.x + j * 256]; ss += v[j] * v[j]; }
    ss = blockReduceSum(ss);
    float sc = rsqrtf(ss / C_ + EPSF);
    #pragma unroll
    for (int j = 0; j < 4; j++) {
        float o = v[j] * sc;
        x [(size_t)i * C_ + threadIdx.x + j * 256] = o;
        x0[(size_t)i * C_ + threadIdx.x + j * 256] = o;
    }
}

// xm = rl*x + xl*x0 (in-place into x); xn = rmsnorm(xm)
__global__ __launch_bounds__(256) void mixnorm_kernel(
    float* __restrict__ x, const float* __restrict__ x0,
    const float* __restrict__ rl, const float* __restrict__ xl, int l,
    float* __restrict__ xn)
{
    int i = blockIdx.x;
    float a = rl[l], bc = xl[l];
    float v[4]; float ss = 0.f;
    #pragma unroll
    for (int j = 0; j < 4; j++) {
        size_t p = (size_t)i * C_ + threadIdx.x + j * 256;
        v[j] = a * x[p] + bc * x0[p];
        ss += v[j] * v[j];
    }
    ss = blockReduceSum(ss);
    float sc = rsqrtf(ss / C_ + EPSF);
    #pragma unroll
    for (int j = 0; j < 4; j++) {
        size_t p = (size_t)i * C_ + threadIdx.x + j * 256;
        x[p] = v[j];
        xn[p] = v[j] * sc;
    }
}

__global__ __launch_bounds__(256) void rmsnorm_kernel(
    const float* __restrict__ x, float* __restrict__ xn)
{
    int i = blockIdx.x;
    float v[4]; float ss = 0.f;
    #pragma unroll
    for (int j = 0; j < 4; j++) {
        v[j] = x[(size_t)i * C_ + threadIdx.x + j * 256];
        ss += v[j] * v[j];
    }
    ss = blockReduceSum(ss);
    float sc = rsqrtf(ss / C_ + EPSF);
    #pragma unroll
    for (int j = 0; j < 4; j++)
        xn[(size_t)i * C_ + threadIdx.x + j * 256] = v[j] * sc;
}

// ---------------- generic fp32 GEMM: C = A(MxK) @ B(KxN), epilogues ----------------
// EPI: 0 = none, 1 = relu^2, 2 = softcap tanh.  ACC: C += result.
template<int EPI, bool ACC>
__global__ __launch_bounds__(256) void sgemm_kernel(
    const float* __restrict__ A, const float* __restrict__ Bm, float* __restrict__ C,
    int M, int N, int K, int lda, int ldb, int ldc)
{
    __shared__ float As[8][128];
    __shared__ float Bs[8][128];
    int bx = blockIdx.x, by = blockIdx.y, tid = threadIdx.x;
    int tr = tid >> 4, tc = tid & 15;
    float acc[8][8];
    #pragma unroll
    for (int m = 0; m < 8; m++)
        #pragma unroll
        for (int n = 0; n < 8; n++) acc[m][n] = 0.f;

    int rowA0 = by * 128;
    for (int k0 = 0; k0 < K; k0 += 8) {
        { // load A tile (128x8), transposed into As[k][m]
            int r = tid >> 1, c = (tid & 1) * 4;
            float4 av = *(const float4*)(A + (size_t)(rowA0 + r) * lda + k0 + c);
            As[c + 0][r] = av.x; As[c + 1][r] = av.y;
            As[c + 2][r] = av.z; As[c + 3][r] = av.w;
        }
        { // load B tile (8x128)
            int r = tid >> 5, c = (tid & 31) * 4;
            int gcol = bx * 128 + c;
            float4 bv = make_float4(0.f, 0.f, 0.f, 0.f);
            if (gcol < N)  // all our N are multiples of 4
                bv = *(const float4*)(Bm + (size_t)(k0 + r) * ldb + gcol);
            Bs[r][c + 0] = bv.x; Bs[r][c + 1] = bv.y;
            Bs[r][c + 2] = bv.z; Bs[r][c + 3] = bv.w;
        }
        __syncthreads();
        #pragma unroll
        for (int kk = 0; kk < 8; kk++) {
            float a[8], b[8];
            #pragma unroll
            for (int m = 0; m < 8; m++) a[m] = As[kk][tr * 8 + m];
            #pragma unroll
            for (int n = 0; n < 8; n++) b[n] = Bs[kk][tc * 8 + n];
            #pragma unroll
            for (int m = 0; m < 8; m++)
                #pragma unroll
                for (int n = 0; n < 8; n++)
                    acc[m][n] = fmaf(a[m], b[n], acc[m][n]);
        }
        __syncthreads();
    }
    #pragma unroll
    for (int m = 0; m < 8; m++) {
        int row = rowA0 + tr * 8 + m;
        if (row >= M) continue;
        #pragma unroll
        for (int n = 0; n < 8; n++) {
            int col = bx * 128 + tc * 8 + n;
            if (col >= N) continue;
            float v = acc[m][n];
            if (EPI == 1) { float h = fmaxf(v, 0.f); v = h * h; }
            if (EPI == 2) { v = 15.0f * tanhf(v * (1.0f / 15.0f)); }
            size_t p = (size_t)row * ldc + col;
            if (ACC) v += C[p];
            C[p] = v;
        }
    }
}

// ---------------- per-token q/k/v assembly: rope, gate, rmsnorm ----------------
__global__ __launch_bounds__(512) void prep_kernel(
    const float* __restrict__ down, const float* __restrict__ kvb,
    const float* __restrict__ qraw, const float* __restrict__ xn,
    const float* __restrict__ cosb, const float* __restrict__ sinb,
    const float* __restrict__ vg, const float* __restrict__ vetab,
    const int* __restrict__ idx,
    float* __restrict__ Q, float* __restrict__ K, float* __restrict__ V)
{
    int i = blockIdx.x;
    int b = i / T_, t = i % T_;
    int w = threadIdx.x >> 5, lane = threadIdx.x & 31;
    __shared__ float cs[16], sn[16], kr[32];

    if (threadIdx.x < 16)       cs[threadIdx.x]      = cosb[(size_t)i * 16 + threadIdx.x];
    else if (threadIdx.x < 32)  sn[threadIdx.x - 16] = sinb[(size_t)i * 16 + threadIdx.x - 16];
    __syncthreads();

    // gate[w] = 2*sigmoid( xn[i, :32] . vg[:, w] )
    float gv = xn[(size_t)i * C_ + lane] * vg[lane * H_ + w];
    #pragma unroll
    for (int o = 16; o; o >>= 1) gv += __shfl_xor_sync(0xffffffffu, gv, o);
    float gate = 2.0f / (1.0f + expf(-gv));

    if (w == 0) { // k_rope (shared across heads)
        int j = lane & 15;
        float x1 = down[(size_t)i * DOWN + 512 + j];
        float x2 = down[(size_t)i * DOWN + 528 + j];
        float cc = cs[j], ssn = sn[j];
        kr[lane] = (lane < 16) ? (x1 * cc + x2 * ssn) : (-x1 * ssn + x2 * cc);
    }
    __syncthreads();

    const float* kvrow = kvb  + (size_t)i * KVW + w * 96;
    const float* qrow  = qraw + (size_t)i * C_  + w * 64;
    const float* verow = vetab + (size_t)idx[i] * C_ + w * 64;

    // dims d0 = lane, d1 = lane + 32
    float k0v = kvrow[lane];        // k_nope
    float k1v = kr[lane];           // k_rope broadcast
    float q0v = qrow[lane];         // q_nope
    float q1v;
    {
        int j = lane & 15;
        float a = qrow[32 + j], bb = qrow[48 + j];
        float cc = cs[j], ssn = sn[j];
        q1v = (lane < 16) ? (a * cc + bb * ssn) : (-a * ssn + bb * cc);
    }
    float v0 = kvrow[32 + lane] + gate * verow[lane];
    float v1 = kvrow[64 + lane] + gate * verow[32 + lane];

    // rmsnorm over 64 dims (per head)
    float kss = k0v * k0v + k1v * k1v;
    float qss = q0v * q0v + q1v * q1v;
    #pragma unroll
    for (int o = 16; o; o >>= 1) {
        kss += __shfl_xor_sync(0xffffffffu, kss, o);
        qss += __shfl_xor_sync(0xffffffffu, qss, o);
    }
    float ksc = rsqrtf(kss * (1.0f / 64.0f) + EPSF);
    float qsc = rsqrtf(qss * (1.0f / 64.0f) + EPSF);

    size_t base = ((size_t)(b * H_ + w) * T_ + t) * 64;
    K[base + lane]      = k0v * ksc;
    K[base + 32 + lane] = k1v * ksc;
    Q[base + lane]      = q0v * qsc;
    Q[base + 32 + lane] = q1v * qsc;
    V[base + lane]      = v0;
    V[base + 32 + lane] = v1;
}

// ---------------- flash attention (fp32, causal) ----------------
__global__ __launch_bounds__(256) void attn_kernel(
    const float* __restrict__ Q, const float* __restrict__ Kt,
    const float* __restrict__ Vt, float* __restrict__ Y)
{
    int qt0 = blockIdx.x * 64;
    int bh  = blockIdx.y;
    int b = bh >> 4, h = bh & 15;
    const float* Qb = Q  + (size_t)bh * T_ * 64;
    const float* Kb = Kt + (size_t)bh * T_ * 64;
    const float* Vb = Vt + (size_t)bh * T_ * 64;

    __shared__ float qs[64][65];
    __shared__ float ks[32][65];
    __shared__ float vs[32][68];
    __shared__ float ps[64][33];

    int tid = threadIdx.x;
    int tr = tid >> 4, tc = tid & 15;

    for (int e = tid; e < 64 * 64; e += 256) {
        int r = e >> 6, c = e & 63;
        qs[r][c] = Qb[(size_t)(qt0 + r) * 64 + c];
    }
    float m[4], l[4], o[4][4];
    #pragma unroll
    for (int mm = 0; mm < 4; mm++) {
        m[mm] = -1e30f; l[mm] = 0.f;
        #pragma unroll
        for (int nn = 0; nn < 4; nn++) o[mm][nn] = 0.f;
    }
    __syncthreads();

    for (int kt0 = 0; kt0 < qt0 + 64; kt0 += 32) {
        for (int e = tid; e < 32 * 64; e += 256) {
            int r = e >> 6, c = e & 63;
            ks[r][c] = Kb[(size_t)(kt0 + r) * 64 + c];
            vs[r][c] = Vb[(size_t)(kt0 + r) * 64 + c];
        }
        __syncthreads();

        float s[4][2];
        #pragma unroll
        for (int mm = 0; mm < 4; mm++) { s[mm][0] = 0.f; s[mm][1] = 0.f; }
        #pragma unroll
        for (int d = 0; d < 64; d++) {
            float a[4], bb[2];
            #pragma unroll
            for (int mm = 0; mm < 4; mm++) a[mm] = qs[tr * 4 + mm][d];
            #pragma unroll
            for (int nn = 0; nn < 2; nn++) bb[nn] = ks[tc * 2 + nn][d];
            #pragma unroll
            for (int mm = 0; mm < 4; mm++)
                #pragma unroll
                for (int nn = 0; nn < 2; nn++)
                    s[mm][nn] = fmaf(a[mm], bb[nn], s[mm][nn]);
        }
        bool edge = (kt0 + 32 > qt0);
        #pragma unroll
        for (int mm = 0; mm < 4; mm++)
            #pragma unroll
            for (int nn = 0; nn < 2; nn++) {
                s[mm][nn] *= 0.125f;
                if (edge) {
                    int qg = qt0 + tr * 4 + mm, kg = kt0 + tc * 2 + nn;
                    if (kg > qg) s[mm][nn] = -1e30f;
                }
            }
        #pragma unroll
        for (int mm = 0; mm < 4; mm++) {
            float rmax = fmaxf(s[mm][0], s[mm][1]);
            #pragma unroll
            for (int off = 1; off < 16; off <<= 1)
                rmax = fmaxf(rmax, __shfl_xor_sync(0xffffffffu, rmax, off));
            float mn = fmaxf(m[mm], rmax);
            float corr = expf(m[mm] - mn);
            float p0 = expf(s[mm][0] - mn);
            float p1 = expf(s[mm][1] - mn);
            float rs = p0 + p1;
            #pragma unroll
            for (int off = 1; off < 16; off <<= 1)
                rs += __shfl_xor_sync(0xffffffffu, rs, off);
            l[mm] = l[mm] * corr + rs;
            m[mm] = mn;
            ps[tr * 4 + mm][tc * 2 + 0] = p0;
            ps[tr * 4 + mm][tc * 2 + 1] = p1;
            #pragma unroll
            for (int nn = 0; nn < 4; nn++) o[mm][nn] *= corr;
        }
        __syncthreads();
        #pragma unroll
        for (int k = 0; k < 32; k++) {
            float pv[4], vv[4];
            #pragma unroll
            for (int mm = 0; mm < 4; mm++) pv[mm] = ps[tr * 4 + mm][k];
            #pragma unroll
            for (int nn = 0; nn < 4; nn++) vv[nn] = vs[k][tc * 4 + nn];
            #pragma unroll
            for (int mm = 0; mm < 4; mm++)
                #pragma unroll
                for (int nn = 0; nn < 4; nn++)
                    o[mm][nn] = fmaf(pv[mm], vv[nn], o[mm][nn]);
        }
        __syncthreads();
    }
    #pragma unroll
    for (int mm = 0; mm < 4; mm++) {
        int q = qt0 + tr * 4 + mm;
        float inv = 1.0f / l[mm];
        #pragma unroll
        for (int nn = 0; nn < 4; nn++)
            Y[((size_t)(b * T_ + q)) * C_ + h * 64 + tc * 4 + nn] = o[mm][nn] * inv;
    }
}

// ---------------- host side ----------------
static float* sym_addr(const void* sym) {
    void* p = nullptr;
    cudaGetSymbolAddress(&p, sym);
    return (float*)p;
}

static void launch_gemm(const float* A, const float* Bm, float* C,
                        int M, int N, int K, int lda, int ldb, int ldc,
                        int epi, bool acc)
{
    dim3 grid((N + 127) / 128, (M + 127) / 128);
    if (acc)            sgemm_kernel<0, true ><<<grid, 256>>>(A, Bm, C, M, N, K, lda, ldb, ldc);
    else if (epi == 0)  sgemm_kernel<0, false><<<grid, 256>>>(A, Bm, C, M, N, K, lda, ldb, ldc);
    else if (epi == 1)  sgemm_kernel<1, false><<<grid, 256>>>(A, Bm, C, M, N, K, lda, ldb, ldc);
    else                sgemm_kernel<2, false><<<grid, 256>>>(A, Bm, C, M, N, K, lda, ldb, ldc);
}

extern "C" void kernel_launch(void* const* d_in, const int* in_sizes, int n_in,
                              void* d_out, int out_size)
{
    (void)in_sizes; (void)n_in; (void)out_size;
    const int*   idx   = (const int*)  d_in[0];
    const float* cosb  = (const float*)d_in[1];
    const float* sinb  = (const float*)d_in[2];
    const float* wte   = (const float*)d_in[3];
    const float* vetab = (const float*)d_in[4];
    const float* wd    = (const float*)d_in[5];
    const float* wukv  = (const float*)d_in[6];
    const float* wuq   = (const float*)d_in[7];
    const float* vg    = (const float*)d_in[8];
    const float* ap    = (const float*)d_in[9];
    const float* fc    = (const float*)d_in[10];
    const float* pj    = (const float*)d_in[11];
    const float* rl    = (const float*)d_in[12];
    const float* xl    = (const float*)d_in[13];
    const float* lmh   = (const float*)d_in[14];
    float* out = (float*)d_out;

    float* px    = sym_addr(g_x);
    float* px0   = sym_addr(g_x0);
    float* pxn   = sym_addr(g_xn);
    float* pdown = sym_addr(g_down);
    float* pkv   = sym_addr(g_kv);
    float* pqraw = sym_addr(g_qraw);
    float* pq    = sym_addr(g_q);
    float* pk    = sym_addr(g_k);
    float* pv    = sym_addr(g_v);
    float* py    = sym_addr(g_y);
    float* ph    = sym_addr(g_h);

    embed_kernel<<<TKN, 256>>>(idx, wte, px, px0);

    for (int l = 0; l < L_; l++) {
        mixnorm_kernel<<<TKN, 256>>>(px, px0, rl, xl, l, pxn);

        // down = xn @ wd[l]  (2048x1024 @ 1024x544)
        launch_gemm(pxn, wd + (size_t)l * C_ * DOWN, pdown,
                    TKN, DOWN, C_, C_, DOWN, DOWN, 0, false);
        // kv = c_kv @ wukv[l]  (2048x256 @ 256x1536)
        launch_gemm(pdown, wukv + (size_t)l * DC * KVW, pkv,
                    TKN, KVW, DC, DOWN, KVW, KVW, 0, false);
        // qraw = c_q @ wuq[l]  (2048x256 @ 256x1024)
        launch_gemm(pdown + DC, wuq + (size_t)l * DC1 * C_, pqraw,
                    TKN, C_, DC1, DOWN, C_, C_, 0, false);

        prep_kernel<<<TKN, 512>>>(pdown, pkv, pqraw, pxn, cosb, sinb,
                                  vg + (size_t)l * GC * H_,
                                  vetab + (size_t)l * VSZ * C_,
                                  idx, pq, pk, pv);

        attn_kernel<<<dim3(T_ / 64, B_ * H_), 256>>>(pq, pk, pv, py);

        // x += y @ attn_proj[l]
        launch_gemm(py, ap + (size_t)l * C_ * C_, px,
                    TKN, C_, C_, C_, C_, C_, 0, true);

        rmsnorm_kernel<<<TKN, 256>>>(px, pxn);

        // h = relu(xn @ fc[l])^2
        launch_gemm(pxn, fc + (size_t)l * C_ * 4096, ph,
                    TKN, 4096, C_, C_, 4096, 4096, 1, false);
        // x += h @ proj[l]
        launch_gemm(ph, pj + (size_t)l * 4096 * C_, px,
                    TKN, C_, 4096, 4096, C_, C_, 0, true);
    }

    rmsnorm_kernel<<<TKN, 256>>>(px, pxn);
    // logits = softcap(xn @ lm_head)
    launch_gemm(pxn, lmh, out, TKN, VSZ, C_, C_, VSZ, VSZ, 2, false);
}

// round 3
// speedup vs baseline: 2.4022x; 2.4022x over previous
#include <cuda_runtime.h>
#include <cuda_bf16.h>
#include <math.h>
#include <stdint.h>

// ---------------- problem constants ----------------
#define B_    2
#define T_    1024
#define C_    1024
#define H_    16
#define HD_   64
#define DC    256
#define DC1   256
#define DR    32
#define DN    32
#define DOWN  544           // DC + DC1 + DR
#define VSZ   32000
#define L_    4
#define GC    32
#define TKN   2048          // B*T
#define KVW   1536          // H*(DN+HD)
#define EPSF  1.1920929e-7f

// ---------------- scratch (device globals; no allocation allowed) ----------------
__device__ float g_x   [TKN * C_];
__device__ float g_x0  [TKN * C_];
__device__ float g_xn  [TKN * C_];
__device__ float g_down[TKN * DOWN];
__device__ float g_kv  [TKN * KVW];
__device__ float g_qraw[TKN * C_];
__device__ float g_q   [B_ * H_ * T_ * HD_];
__device__ float g_k   [B_ * H_ * T_ * HD_];
__device__ float g_v   [B_ * H_ * T_ * HD_];
__device__ float g_y   [TKN * C_];
__device__ float g_h   [TKN * 4096];

// ================= warp-MMA helpers (base sm_103 ISA: HMMA + LDSM) =================
__device__ __forceinline__ uint32_t smem_u32(const void* p) {
    uint32_t a;
    asm("{ .reg .u64 t; cvta.to.shared.u64 t, %1; cvt.u32.u64 %0, t; }" : "=r"(a) : "l"(p));
    return a;
}
__device__ __forceinline__ void ldsm_x4(uint32_t r[4], uint32_t addr) {
    asm volatile("ldmatrix.sync.aligned.m8n8.x4.shared.b16 {%0,%1,%2,%3}, [%4];"
        : "=r"(r[0]), "=r"(r[1]), "=r"(r[2]), "=r"(r[3]) : "r"(addr));
}
__device__ __forceinline__ void ldsm_x2t(uint32_t r[2], uint32_t addr) {
    asm volatile("ldmatrix.sync.aligned.m8n8.x2.trans.shared.b16 {%0,%1}, [%2];"
        : "=r"(r[0]), "=r"(r[1]) : "r"(addr));
}
__device__ __forceinline__ void mma_bf16(float c[4], const uint32_t a[4], const uint32_t b[2]) {
    asm volatile("mma.sync.aligned.m16n8k16.row.col.f32.bf16.bf16.f32 "
        "{%0,%1,%2,%3}, {%4,%5,%6,%7}, {%8,%9}, {%0,%1,%2,%3};"
        : "+f"(c[0]), "+f"(c[1]), "+f"(c[2]), "+f"(c[3])
        : "r"(a[0]), "r"(a[1]), "r"(a[2]), "r"(a[3]), "r"(b[0]), "r"(b[1]));
}

// smem layout per buffer (bytes):
//   A_hi [128][40] bf16 @ 0      (10240)
//   A_lo            @ 10240      (10240)
//   B_hi [32][136] bf16 @ 20480  (8704)
//   B_lo            @ 29184      (8704)
#define BUF_STRIDE 40960
#define GEMM_DSMEM (2 * BUF_STRIDE + 128)

// C[M,N] = A[M,K] @ B[K,N]; fp32 in/out, 3x bf16-split MMA.
// EPI: 0 none, 1 relu^2, 2 softcap. ACC: C += result.
template<int EPI, bool ACC>
__global__ __launch_bounds__(256) void gemm_mma(
    const float* __restrict__ A, const float* __restrict__ Bm, float* __restrict__ C,
    int M, int N, int K, int lda, int ldb, int ldc)
{
    extern __shared__ char dsm[];
    uint32_t sraw = smem_u32(dsm);
    uint32_t s0 = (sraw + 127u) & ~127u;
    char* sbuf = dsm + (s0 - sraw);

    int tid = threadIdx.x, wid = tid >> 5, lane = tid & 31;
    int row0 = blockIdx.y * 128, col0 = blockIdx.x * 128;
    int wm = (wid >> 2) * 64;     // warp row offset (0 / 64)
    int wn = (wid & 3) * 32;      // warp col offset (0/32/64/96)

    float c[4][4][4];
    #pragma unroll
    for (int mt = 0; mt < 4; mt++)
        #pragma unroll
        for (int nt = 0; nt < 4; nt++)
            #pragma unroll
            for (int r = 0; r < 4; r++) c[mt][nt][r] = 0.f;

    int NC = K >> 5;   // K chunks of 32
    float4 av[4], bv[4];

    // ---- chunk loaders ----
    auto load_chunk = [&](int i) {
        int k0 = i << 5;
        #pragma unroll
        for (int j = 0; j < 4; j++) {
            int idx = tid + j * 256;
            int r = idx >> 3, c4 = (idx & 7) << 2;
            av[j] = *(const float4*)(A + (size_t)(row0 + r) * lda + k0 + c4);
        }
        #pragma unroll
        for (int j = 0; j < 4; j++) {
            int idx = tid + j * 256;
            int kk = idx >> 5, n4 = (idx & 31) << 2;
            int gc = col0 + n4;
            const float* bp = Bm + (size_t)(k0 + kk) * ldb;
            if (gc + 4 <= N) {
                bv[j] = *(const float4*)(bp + gc);
            } else {
                bv[j].x = (gc + 0 < N) ? bp[gc + 0] : 0.f;
                bv[j].y = (gc + 1 < N) ? bp[gc + 1] : 0.f;
                bv[j].z = (gc + 2 < N) ? bp[gc + 2] : 0.f;
                bv[j].w = (gc + 3 < N) ? bp[gc + 3] : 0.f;
            }
        }
    };
    union U2 { __nv_bfloat16 h[4]; uint2 u; };
    auto store_chunk = [&](int b) {
        char* bp = sbuf + b * BUF_STRIDE;
        #pragma unroll
        for (int j = 0; j < 4; j++) {
            int idx = tid + j * 256;
            int r = idx >> 3, c4 = (idx & 7) << 2;
            float f[4] = { av[j].x, av[j].y, av[j].z, av[j].w };
            U2 ph, pl;
            #pragma unroll
            for (int jj = 0; jj < 4; jj++) {
                __nv_bfloat16 hv = __float2bfloat16(f[jj]);
                ph.h[jj] = hv;
                pl.h[jj] = __float2bfloat16(f[jj] - __bfloat162float(hv));
            }
            *(uint2*)(bp + r * 80 + c4 * 2)         = ph.u;
            *(uint2*)(bp + 10240 + r * 80 + c4 * 2) = pl.u;
        }
        #pragma unroll
        for (int j = 0; j < 4; j++) {
            int idx = tid + j * 256;
            int kk = idx >> 5, n4 = (idx & 31) << 2;
            float f[4] = { bv[j].x, bv[j].y, bv[j].z, bv[j].w };
            U2 ph, pl;
            #pragma unroll
            for (int jj = 0; jj < 4; jj++) {
                __nv_bfloat16 hv = __float2bfloat16(f[jj]);
                ph.h[jj] = hv;
                pl.h[jj] = __float2bfloat16(f[jj] - __bfloat162float(hv));
            }
            *(uint2*)(bp + 20480 + kk * 272 + n4 * 2) = ph.u;
            *(uint2*)(bp + 29184 + kk * 272 + n4 * 2) = pl.u;
        }
    };
    auto mma_chunk = [&](int b) {
        uint32_t base = s0 + (uint32_t)b * BUF_STRIDE;
        int arow = wm + ((lane >> 3) & 1) * 8 + (lane & 7);
        int krow = (lane & 7) + ((lane >> 3) & 1) * 8;
        #pragma unroll
        for (int kk = 0; kk < 32; kk += 16) {
            uint32_t afh[4][4], afl[4][4], bfh[4][2], bfl[4][2];
            int acol = kk + ((lane >> 4) & 1) * 8;
            #pragma unroll
            for (int mt = 0; mt < 4; mt++) {
                uint32_t ad = base + (uint32_t)((arow + mt * 16) * 80 + acol * 2);
                ldsm_x4(afh[mt], ad);
                ldsm_x4(afl[mt], ad + 10240u);
            }
            #pragma unroll
            for (int nt = 0; nt < 4; nt++) {
                uint32_t bd = base + 20480u + (uint32_t)((kk + krow) * 272 + (wn + nt * 8) * 2);
                ldsm_x2t(bfh[nt], bd);
                ldsm_x2t(bfl[nt], bd + 8704u);
            }
            #pragma unroll
            for (int mt = 0; mt < 4; mt++)
                #pragma unroll
                for (int nt = 0; nt < 4; nt++)
                    mma_bf16(c[mt][nt], afh[mt], bfh[nt]);
            #pragma unroll
            for (int mt = 0; mt < 4; mt++)
                #pragma unroll
                for (int nt = 0; nt < 4; nt++)
                    mma_bf16(c[mt][nt], afl[mt], bfh[nt]);
            #pragma unroll
            for (int mt = 0; mt < 4; mt++)
                #pragma unroll
                for (int nt = 0; nt < 4; nt++)
                    mma_bf16(c[mt][nt], afh[mt], bfl[nt]);
        }
    };

    // ---- pipelined main loop ----
    load_chunk(0);
    store_chunk(0);
    __syncthreads();
    for (int i = 0; i < NC; i++) {
        if (i + 1 < NC) load_chunk(i + 1);
        mma_chunk(i & 1);
        if (i + 1 < NC) store_chunk((i + 1) & 1);
        __syncthreads();
    }

    // ---- epilogue: write C from fragments ----
    #pragma unroll
    for (int mt = 0; mt < 4; mt++) {
        #pragma unroll
        for (int nt = 0; nt < 4; nt++) {
            #pragma unroll
            for (int half = 0; half < 2; half++) {
                int grow = row0 + wm + mt * 16 + (lane >> 2) + half * 8;
                int gcol = col0 + wn + nt * 8 + (lane & 3) * 2;
                float v0 = c[mt][nt][half * 2 + 0];
                float v1 = c[mt][nt][half * 2 + 1];
                if (EPI == 1) {
                    float h0 = fmaxf(v0, 0.f); v0 = h0 * h0;
                    float h1 = fmaxf(v1, 0.f); v1 = h1 * h1;
                }
                if (EPI == 2) {
                    v0 = 15.0f * tanhf(v0 * (1.0f / 15.0f));
                    v1 = 15.0f * tanhf(v1 * (1.0f / 15.0f));
                }
                if (gcol + 1 < N) {
                    float* p = C + (size_t)grow * ldc + gcol;
                    if (ACC) { v0 += p[0]; v1 += p[1]; }
                    *(float2*)p = make_float2(v0, v1);
                } else if (gcol < N) {
                    float* p = C + (size_t)grow * ldc + gcol;
                    if (ACC) v0 += p[0];
                    p[0] = v0;
                }
            }
        }
    }
}

// ---------------- block reduce ----------------
__device__ __forceinline__ float blockReduceSum(float v) {
    __shared__ float red[32];
    int lane = threadIdx.x & 31, w = threadIdx.x >> 5;
    #pragma unroll
    for (int o = 16; o; o >>= 1) v += __shfl_xor_sync(0xffffffffu, v, o);
    if (lane == 0) red[w] = v;
    __syncthreads();
    v = (threadIdx.x < (blockDim.x >> 5)) ? red[threadIdx.x] : 0.0f;
    if (w == 0) {
        #pragma unroll
        for (int o = 16; o; o >>= 1) v += __shfl_xor_sync(0xffffffffu, v, o);
        if (lane == 0) red[0] = v;
    }
    __syncthreads();
    return red[0];
}

// ---------------- embed + rmsnorm ----------------
__global__ __launch_bounds__(256) void embed_kernel(
    const int* __restrict__ idx, const float* __restrict__ wte,
    float* __restrict__ x, float* __restrict__ x0)
{
    int i = blockIdx.x;
    const float* row = wte + (size_t)idx[i] * C_;
    float v[4]; float ss = 0.f;
    #pragma unroll
    for (int j = 0; j < 4; j++) { v[j] = row[threadIdx.x + j * 256]; ss += v[j] * v[j]; }
    ss = blockReduceSum(ss);
    float sc = rsqrtf(ss / C_ + EPSF);
    #pragma unroll
    for (int j = 0; j < 4; j++) {
        float o = v[j] * sc;
        x [(size_t)i * C_ + threadIdx.x + j * 256] = o;
        x0[(size_t)i * C_ + threadIdx.x + j * 256] = o;
    }
}

__global__ __launch_bounds__(256) void mixnorm_kernel(
    float* __restrict__ x, const float* __restrict__ x0,
    const float* __restrict__ rl, const float* __restrict__ xl, int l,
    float* __restrict__ xn)
{
    int i = blockIdx.x;
    float a = rl[l], bc = xl[l];
    float v[4]; float ss = 0.f;
    #pragma unroll
    for (int j = 0; j < 4; j++) {
        size_t p = (size_t)i * C_ + threadIdx.x + j * 256;
        v[j] = a * x[p] + bc * x0[p];
        ss += v[j] * v[j];
    }
    ss = blockReduceSum(ss);
    float sc = rsqrtf(ss / C_ + EPSF);
    #pragma unroll
    for (int j = 0; j < 4; j++) {
        size_t p = (size_t)i * C_ + threadIdx.x + j * 256;
        x[p] = v[j];
        xn[p] = v[j] * sc;
    }
}

__global__ __launch_bounds__(256) void rmsnorm_kernel(
    const float* __restrict__ x, float* __restrict__ xn)
{
    int i = blockIdx.x;
    float v[4]; float ss = 0.f;
    #pragma unroll
    for (int j = 0; j < 4; j++) {
        v[j] = x[(size_t)i * C_ + threadIdx.x + j * 256];
        ss += v[j] * v[j];
    }
    ss = blockReduceSum(ss);
    float sc = rsqrtf(ss / C_ + EPSF);
    #pragma unroll
    for (int j = 0; j < 4; j++)
        xn[(size_t)i * C_ + threadIdx.x + j * 256] = v[j] * sc;
}

// ---------------- per-token q/k/v assembly ----------------
__global__ __launch_bounds__(512) void prep_kernel(
    const float* __restrict__ down, const float* __restrict__ kvb,
    const float* __restrict__ qraw, const float* __restrict__ xn,
    const float* __restrict__ cosb, const float* __restrict__ sinb,
    const float* __restrict__ vg, const float* __restrict__ vetab,
    const int* __restrict__ idx,
    float* __restrict__ Q, float* __restrict__ K, float* __restrict__ V)
{
    int i = blockIdx.x;
    int b = i / T_, t = i % T_;
    int w = threadIdx.x >> 5, lane = threadIdx.x & 31;
    __shared__ float cs[16], sn[16], kr[32];

    if (threadIdx.x < 16)       cs[threadIdx.x]      = cosb[(size_t)i * 16 + threadIdx.x];
    else if (threadIdx.x < 32)  sn[threadIdx.x - 16] = sinb[(size_t)i * 16 + threadIdx.x - 16];
    __syncthreads();

    float gv = xn[(size_t)i * C_ + lane] * vg[lane * H_ + w];
    #pragma unroll
    for (int o = 16; o; o >>= 1) gv += __shfl_xor_sync(0xffffffffu, gv, o);
    float gate = 2.0f / (1.0f + expf(-gv));

    if (w == 0) {
        int j = lane & 15;
        float x1 = down[(size_t)i * DOWN + 512 + j];
        float x2 = down[(size_t)i * DOWN + 528 + j];
        float cc = cs[j], ssn = sn[j];
        kr[lane] = (lane < 16) ? (x1 * cc + x2 * ssn) : (-x1 * ssn + x2 * cc);
    }
    __syncthreads();

    const float* kvrow = kvb  + (size_t)i * KVW + w * 96;
    const float* qrow  = qraw + (size_t)i * C_  + w * 64;
    const float* verow = vetab + (size_t)idx[i] * C_ + w * 64;

    float k0v = kvrow[lane];
    float k1v = kr[lane];
    float q0v = qrow[lane];
    float q1v;
    {
        int j = lane & 15;
        float a = qrow[32 + j], bb = qrow[48 + j];
        float cc = cs[j], ssn = sn[j];
        q1v = (lane < 16) ? (a * cc + bb * ssn) : (-a * ssn + bb * cc);
    }
    float v0 = kvrow[32 + lane] + gate * verow[lane];
    float v1 = kvrow[64 + lane] + gate * verow[32 + lane];

    float kss = k0v * k0v + k1v * k1v;
    float qss = q0v * q0v + q1v * q1v;
    #pragma unroll
    for (int o = 16; o; o >>= 1) {
        kss += __shfl_xor_sync(0xffffffffu, kss, o);
        qss += __shfl_xor_sync(0xffffffffu, qss, o);
    }
    float ksc = rsqrtf(kss * (1.0f / 64.0f) + EPSF);
    float qsc = rsqrtf(qss * (1.0f / 64.0f) + EPSF);

    size_t base = ((size_t)(b * H_ + w) * T_ + t) * 64;
    K[base + lane]      = k0v * ksc;
    K[base + 32 + lane] = k1v * ksc;
    Q[base + lane]      = q0v * qsc;
    Q[base + 32 + lane] = q1v * qsc;
    V[base + lane]      = v0;
    V[base + 32 + lane] = v1;
}

// ---------------- flash attention (fp32, causal) ----------------
__global__ __launch_bounds__(256) void attn_kernel(
    const float* __restrict__ Q, const float* __restrict__ Kt,
    const float* __restrict__ Vt, float* __restrict__ Y)
{
    int qt0 = blockIdx.x * 64;
    int bh  = blockIdx.y;
    int b = bh >> 4, h = bh & 15;
    const float* Qb = Q  + (size_t)bh * T_ * 64;
    const float* Kb = Kt + (size_t)bh * T_ * 64;
    const float* Vb = Vt + (size_t)bh * T_ * 64;

    __shared__ float qs[64][65];
    __shared__ float ks[32][65];
    __shared__ float vs[32][68];
    __shared__ float ps[64][33];

    int tid = threadIdx.x;
    int tr = tid >> 4, tc = tid & 15;

    for (int e = tid; e < 64 * 64; e += 256) {
        int r = e >> 6, c = e & 63;
        qs[r][c] = Qb[(size_t)(qt0 + r) * 64 + c];
    }
    float m[4], l[4], o[4][4];
    #pragma unroll
    for (int mm = 0; mm < 4; mm++) {
        m[mm] = -1e30f; l[mm] = 0.f;
        #pragma unroll
        for (int nn = 0; nn < 4; nn++) o[mm][nn] = 0.f;
    }
    __syncthreads();

    for (int kt0 = 0; kt0 < qt0 + 64; kt0 += 32) {
        for (int e = tid; e < 32 * 64; e += 256) {
            int r = e >> 6, c = e & 63;
            ks[r][c] = Kb[(size_t)(kt0 + r) * 64 + c];
            vs[r][c] = Vb[(size_t)(kt0 + r) * 64 + c];
        }
        __syncthreads();

        float s[4][2];
        #pragma unroll
        for (int mm = 0; mm < 4; mm++) { s[mm][0] = 0.f; s[mm][1] = 0.f; }
        #pragma unroll
        for (int d = 0; d < 64; d++) {
            float a[4], bb[2];
            #pragma unroll
            for (int mm = 0; mm < 4; mm++) a[mm] = qs[tr * 4 + mm][d];
            #pragma unroll
            for (int nn = 0; nn < 2; nn++) bb[nn] = ks[tc * 2 + nn][d];
            #pragma unroll
            for (int mm = 0; mm < 4; mm++)
                #pragma unroll
                for (int nn = 0; nn < 2; nn++)
                    s[mm][nn] = fmaf(a[mm], bb[nn], s[mm][nn]);
        }
        bool edge = (kt0 + 32 > qt0);
        #pragma unroll
        for (int mm = 0; mm < 4; mm++)
            #pragma unroll
            for (int nn = 0; nn < 2; nn++) {
                s[mm][nn] *= 0.125f;
                if (edge) {
                    int qg = qt0 + tr * 4 + mm, kg = kt0 + tc * 2 + nn;
                    if (kg > qg) s[mm][nn] = -1e30f;
                }
            }
        #pragma unroll
        for (int mm = 0; mm < 4; mm++) {
            float rmax = fmaxf(s[mm][0], s[mm][1]);
            #pragma unroll
            for (int off = 1; off < 16; off <<= 1)
                rmax = fmaxf(rmax, __shfl_xor_sync(0xffffffffu, rmax, off));
            float mn = fmaxf(m[mm], rmax);
            float corr = expf(m[mm] - mn);
            float p0 = expf(s[mm][0] - mn);
            float p1 = expf(s[mm][1] - mn);
            float rs = p0 + p1;
            #pragma unroll
            for (int off = 1; off < 16; off <<= 1)
                rs += __shfl_xor_sync(0xffffffffu, rs, off);
            l[mm] = l[mm] * corr + rs;
            m[mm] = mn;
            ps[tr * 4 + mm][tc * 2 + 0] = p0;
            ps[tr * 4 + mm][tc * 2 + 1] = p1;
            #pragma unroll
            for (int nn = 0; nn < 4; nn++) o[mm][nn] *= corr;
        }
        __syncthreads();
        #pragma unroll
        for (int k = 0; k < 32; k++) {
            float pv[4], vv[4];
            #pragma unroll
            for (int mm = 0; mm < 4; mm++) pv[mm] = ps[tr * 4 + mm][k];
            #pragma unroll
            for (int nn = 0; nn < 4; nn++) vv[nn] = vs[k][tc * 4 + nn];
            #pragma unroll
            for (int mm = 0; mm < 4; mm++)
                #pragma unroll
                for (int nn = 0; nn < 4; nn++)
                    o[mm][nn] = fmaf(pv[mm], vv[nn], o[mm][nn]);
        }
        __syncthreads();
    }
    #pragma unroll
    for (int mm = 0; mm < 4; mm++) {
        int q = qt0 + tr * 4 + mm;
        float inv = 1.0f / l[mm];
        #pragma unroll
        for (int nn = 0; nn < 4; nn++)
            Y[((size_t)(b * T_ + q)) * C_ + h * 64 + tc * 4 + nn] = o[mm][nn] * inv;
    }
}

// ---------------- host side ----------------
static float* sym_addr(const void* sym) {
    void* p = nullptr;
    cudaGetSymbolAddress(&p, sym);
    return (float*)p;
}

static void launch_gemm(const float* A, const float* Bm, float* C,
                        int M, int N, int K, int lda, int ldb, int ldc,
                        int epi, bool acc)
{
    dim3 grid((N + 127) / 128, (M + 127) / 128);
    if (acc)            gemm_mma<0, true ><<<grid, 256, GEMM_DSMEM>>>(A, Bm, C, M, N, K, lda, ldb, ldc);
    else if (epi == 0)  gemm_mma<0, false><<<grid, 256, GEMM_DSMEM>>>(A, Bm, C, M, N, K, lda, ldb, ldc);
    else if (epi == 1)  gemm_mma<1, false><<<grid, 256, GEMM_DSMEM>>>(A, Bm, C, M, N, K, lda, ldb, ldc);
    else                gemm_mma<2, false><<<grid, 256, GEMM_DSMEM>>>(A, Bm, C, M, N, K, lda, ldb, ldc);
}

extern "C" void kernel_launch(void* const* d_in, const int* in_sizes, int n_in,
                              void* d_out, int out_size)
{
    (void)in_sizes; (void)n_in; (void)out_size;
    const int*   idx   = (const int*)  d_in[0];
    const float* cosb  = (const float*)d_in[1];
    const float* sinb  = (const float*)d_in[2];
    const float* wte   = (const float*)d_in[3];
    const float* vetab = (const float*)d_in[4];
    const float* wd    = (const float*)d_in[5];
    const float* wukv  = (const float*)d_in[6];
    const float* wuq   = (const float*)d_in[7];
    const float* vg    = (const float*)d_in[8];
    const float* ap    = (const float*)d_in[9];
    const float* fc    = (const float*)d_in[10];
    const float* pj    = (const float*)d_in[11];
    const float* rl    = (const float*)d_in[12];
    const float* xl    = (const float*)d_in[13];
    const float* lmh   = (const float*)d_in[14];
    float* out = (float*)d_out;

    static bool attr_done = false;
    if (!attr_done) {
        cudaFuncSetAttribute(gemm_mma<0, false>, cudaFuncAttributeMaxDynamicSharedMemorySize, GEMM_DSMEM);
        cudaFuncSetAttribute(gemm_mma<0, true >, cudaFuncAttributeMaxDynamicSharedMemorySize, GEMM_DSMEM);
        cudaFuncSetAttribute(gemm_mma<1, false>, cudaFuncAttributeMaxDynamicSharedMemorySize, GEMM_DSMEM);
        cudaFuncSetAttribute(gemm_mma<2, false>, cudaFuncAttributeMaxDynamicSharedMemorySize, GEMM_DSMEM);
        attr_done = true;
    }

    float* px    = sym_addr(g_x);
    float* px0   = sym_addr(g_x0);
    float* pxn   = sym_addr(g_xn);
    float* pdown = sym_addr(g_down);
    float* pkv   = sym_addr(g_kv);
    float* pqraw = sym_addr(g_qraw);
    float* pq    = sym_addr(g_q);
    float* pk    = sym_addr(g_k);
    float* pv    = sym_addr(g_v);
    float* py    = sym_addr(g_y);
    float* ph    = sym_addr(g_h);

    embed_kernel<<<TKN, 256>>>(idx, wte, px, px0);

    for (int l = 0; l < L_; l++) {
        mixnorm_kernel<<<TKN, 256>>>(px, px0, rl, xl, l, pxn);

        launch_gemm(pxn, wd + (size_t)l * C_ * DOWN, pdown,
                    TKN, DOWN, C_, C_, DOWN, DOWN, 0, false);
        launch_gemm(pdown, wukv + (size_t)l * DC * KVW, pkv,
                    TKN, KVW, DC, DOWN, KVW, KVW, 0, false);
        launch_gemm(pdown + DC, wuq + (size_t)l * DC1 * C_, pqraw,
                    TKN, C_, DC1, DOWN, C_, C_, 0, false);

        prep_kernel<<<TKN, 512>>>(pdown, pkv, pqraw, pxn, cosb, sinb,
                                  vg + (size_t)l * GC * H_,
                                  vetab + (size_t)l * VSZ * C_,
                                  idx, pq, pk, pv);

        attn_kernel<<<dim3(T_ / 64, B_ * H_), 256>>>(pq, pk, pv, py);

        launch_gemm(py, ap + (size_t)l * C_ * C_, px,
                    TKN, C_, C_, C_, C_, C_, 0, true);

        rmsnorm_kernel<<<TKN, 256>>>(px, pxn);

        launch_gemm(pxn, fc + (size_t)l * C_ * 4096, ph,
                    TKN, 4096, C_, C_, 4096, 4096, 1, false);
        launch_gemm(ph, pj + (size_t)l * 4096 * C_, px,
                    TKN, C_, 4096, 4096, C_, C_, 0, true);
    }

    rmsnorm_kernel<<<TKN, 256>>>(px, pxn);
    launch_gemm(pxn, lmh, out, TKN, VSZ, C_, C_, VSZ, VSZ, 2, false);
}

// round 4
// speedup vs baseline: 2.7193x; 1.1320x over previous
#include <cuda_runtime.h>
#include <cuda_bf16.h>
#include <math.h>
#include <stdint.h>

// ---------------- problem constants ----------------
#define B_    2
#define T_    1024
#define C_    1024
#define H_    16
#define HD_   64
#define DC    256
#define DC1   256
#define DR    32
#define DN    32
#define DOWN  544
#define VSZ   32000
#define L_    4
#define GC    32
#define TKN   2048
#define KVW   1536
#define EPSF  1.1920929e-7f

// ---------------- fp32 scratch ----------------
__device__ float g_x   [TKN * C_];
__device__ float g_x0  [TKN * C_];
__device__ float g_xn  [TKN * C_];
__device__ float g_down[TKN * DOWN];
__device__ float g_kv  [TKN * KVW];
__device__ float g_qraw[TKN * C_];
__device__ float g_q   [B_ * H_ * T_ * HD_];
__device__ float g_k   [B_ * H_ * T_ * HD_];
__device__ float g_v   [B_ * H_ * T_ * HD_];

// ---------------- bf16 hi/lo split buffers ----------------
__device__ __nv_bfloat16 s_wd_h  [L_ * C_ * DOWN],  s_wd_l  [L_ * C_ * DOWN];
__device__ __nv_bfloat16 s_wukv_h[L_ * DC * KVW],   s_wukv_l[L_ * DC * KVW];
__device__ __nv_bfloat16 s_wuq_h [L_ * DC1 * C_],   s_wuq_l [L_ * DC1 * C_];
__device__ __nv_bfloat16 s_ap_h  [L_ * C_ * C_],    s_ap_l  [L_ * C_ * C_];
__device__ __nv_bfloat16 s_fc_h  [L_ * C_ * 4096],  s_fc_l  [L_ * C_ * 4096];
__device__ __nv_bfloat16 s_pj_h  [L_ * 4096 * C_],  s_pj_l  [L_ * 4096 * C_];
__device__ __nv_bfloat16 s_lmh_h [C_ * VSZ],        s_lmh_l [C_ * VSZ];
__device__ __nv_bfloat16 s_xn_h  [TKN * C_],        s_xn_l  [TKN * C_];
__device__ __nv_bfloat16 s_dn_h  [TKN * DOWN],      s_dn_l  [TKN * DOWN];
__device__ __nv_bfloat16 s_h_h   [TKN * 4096],      s_h_l   [TKN * 4096];
__device__ __nv_bfloat16 s_y_h   [TKN * C_],        s_y_l   [TKN * C_];

// ================= helpers =================
__device__ __forceinline__ uint32_t smem_u32(const void* p) {
    uint32_t a;
    asm("{ .reg .u64 t; cvta.to.shared.u64 t, %1; cvt.u32.u64 %0, t; }" : "=r"(a) : "l"(p));
    return a;
}
__device__ __forceinline__ void ldsm_x4(uint32_t r[4], uint32_t addr) {
    asm volatile("ldmatrix.sync.aligned.m8n8.x4.shared.b16 {%0,%1,%2,%3}, [%4];"
        : "=r"(r[0]), "=r"(r[1]), "=r"(r[2]), "=r"(r[3]) : "r"(addr));
}
__device__ __forceinline__ void ldsm_x2t(uint32_t r[2], uint32_t addr) {
    asm volatile("ldmatrix.sync.aligned.m8n8.x2.trans.shared.b16 {%0,%1}, [%2];"
        : "=r"(r[0]), "=r"(r[1]) : "r"(addr));
}
__device__ __forceinline__ void mma_bf16(float c[4], const uint32_t a[4], const uint32_t b[2]) {
    asm volatile("mma.sync.aligned.m16n8k16.row.col.f32.bf16.bf16.f32 "
        "{%0,%1,%2,%3}, {%4,%5,%6,%7}, {%8,%9}, {%0,%1,%2,%3};"
        : "+f"(c[0]), "+f"(c[1]), "+f"(c[2]), "+f"(c[3])
        : "r"(a[0]), "r"(a[1]), "r"(a[2]), "r"(a[3]), "r"(b[0]), "r"(b[1]));
}
__device__ __forceinline__ void cp16(uint32_t dst, const void* src) {
    asm volatile("cp.async.cg.shared.global [%0], [%1], 16;" :: "r"(dst), "l"(src));
}
__device__ __forceinline__ void cp16z(uint32_t dst, const void* src, uint32_t ssize) {
    asm volatile("cp.async.cg.shared.global [%0], [%1], 16, %2;" :: "r"(dst), "l"(src), "r"(ssize));
}
#define CP_COMMIT() asm volatile("cp.async.commit_group;" ::: "memory")
#define CP_WAIT1()  asm volatile("cp.async.wait_group 1;" ::: "memory")
__device__ __forceinline__ uint32_t pack_bf2(__nv_bfloat16 a, __nv_bfloat16 b) {
    union { __nv_bfloat16 h[2]; uint32_t u; } u;
    u.h[0] = a; u.h[1] = b;
    return u.u;
}

// smem layout per stage: A_hi[128][40] @0 (10240) | A_lo @10240 | B_hi[32][136] @20480 (8704) | B_lo @29184
#define STG_STRIDE 37888
#define GEMM_DSMEM (3 * STG_STRIDE + 128)

// C[M,N] = A[M,K] @ B[K,N]; bf16 hi/lo inputs, fp32 (+optional bf16 split) output.
// EPI: 0 none, 1 relu^2, 2 softcap.
template<int EPI, bool ACC, bool WSPLIT, bool WF32>
__global__ __launch_bounds__(256, 2) void gemm_bf16(
    const __nv_bfloat16* __restrict__ Ah, const __nv_bfloat16* __restrict__ Al,
    const __nv_bfloat16* __restrict__ Bh, const __nv_bfloat16* __restrict__ Bl,
    float* __restrict__ C, __nv_bfloat16* __restrict__ Ch, __nv_bfloat16* __restrict__ Cl,
    int M, int N, int K, int lda, int ldb, int ldc)
{
    extern __shared__ char dsm[];
    uint32_t sraw = smem_u32(dsm);
    uint32_t s0 = (sraw + 127u) & ~127u;

    int tid = threadIdx.x, wid = tid >> 5, lane = tid & 31;
    int row0 = blockIdx.x * 128, col0 = blockIdx.y * 128;
    int wm = (wid >> 2) * 64;
    int wn = (wid & 3) * 32;

    float c[4][4][4];
    #pragma unroll
    for (int mt = 0; mt < 4; mt++)
        #pragma unroll
        for (int nt = 0; nt < 4; nt++)
            #pragma unroll
            for (int r = 0; r < 4; r++) c[mt][nt][r] = 0.f;

    int NC = K >> 5;

    auto issue_copy = [&](int i, int stg) {
        int k0 = i << 5;
        uint32_t sb = s0 + (uint32_t)stg * STG_STRIDE;
        #pragma unroll
        for (int e0 = 0; e0 < 2; e0++) {
            int e = tid + e0 * 256;
            int r = e >> 2, seg = e & 3;
            uint32_t d = sb + (uint32_t)(r * 80 + seg * 16);
            const __nv_bfloat16* srch = Ah + (size_t)(row0 + r) * lda + k0 + seg * 8;
            const __nv_bfloat16* srcl = Al + (size_t)(row0 + r) * lda + k0 + seg * 8;
            cp16(d, srch);
            cp16(d + 10240u, srcl);
        }
        #pragma unroll
        for (int e0 = 0; e0 < 2; e0++) {
            int e = tid + e0 * 256;
            int kk = e >> 4, seg = e & 15;
            int gc = col0 + seg * 8;
            uint32_t d = sb + 20480u + (uint32_t)(kk * 272 + seg * 16);
            int rem = N - gc;
            uint32_t sz = rem >= 8 ? 16u : (rem > 0 ? (uint32_t)(rem * 2) : 0u);
            cp16z(d, Bh + (size_t)(k0 + kk) * ldb + gc, sz);
            cp16z(d + 8704u, Bl + (size_t)(k0 + kk) * ldb + gc, sz);
        }
    };

    auto mma_chunk = [&](int stg) {
        uint32_t base = s0 + (uint32_t)stg * STG_STRIDE;
        int arow = wm + ((lane >> 3) & 1) * 8 + (lane & 7);
        int krow = lane & 15;
        #pragma unroll
        for (int kk = 0; kk < 32; kk += 16) {
            uint32_t af[4][4], bh[4][2], bl[4][2];
            int acol = kk + ((lane >> 4) & 1) * 8;
            #pragma unroll
            for (int mt = 0; mt < 4; mt++)
                ldsm_x4(af[mt], base + (uint32_t)((arow + mt * 16) * 80 + acol * 2));
            #pragma unroll
            for (int nt = 0; nt < 4; nt++) {
                uint32_t bd = base + 20480u + (uint32_t)((kk + krow) * 272 + (wn + nt * 8) * 2);
                ldsm_x2t(bh[nt], bd);
                ldsm_x2t(bl[nt], bd + 8704u);
            }
            #pragma unroll
            for (int mt = 0; mt < 4; mt++)
                #pragma unroll
                for (int nt = 0; nt < 4; nt++)
                    mma_bf16(c[mt][nt], af[mt], bh[nt]);
            #pragma unroll
            for (int mt = 0; mt < 4; mt++)
                #pragma unroll
                for (int nt = 0; nt < 4; nt++)
                    mma_bf16(c[mt][nt], af[mt], bl[nt]);
            #pragma unroll
            for (int mt = 0; mt < 4; mt++)
                ldsm_x4(af[mt], base + 10240u + (uint32_t)((arow + mt * 16) * 80 + acol * 2));
            #pragma unroll
            for (int mt = 0; mt < 4; mt++)
                #pragma unroll
                for (int nt = 0; nt < 4; nt++)
                    mma_bf16(c[mt][nt], af[mt], bh[nt]);
        }
    };

    issue_copy(0, 0); CP_COMMIT();
    issue_copy(1, 1); CP_COMMIT();
    for (int i = 0; i < NC; i++) {
        CP_WAIT1();
        __syncthreads();
        mma_chunk(i % 3);
        __syncthreads();
        if (i + 2 < NC) issue_copy(i + 2, (i + 2) % 3);
        CP_COMMIT();
    }

    // ---- epilogue ----
    #pragma unroll
    for (int mt = 0; mt < 4; mt++) {
        #pragma unroll
        for (int nt = 0; nt < 4; nt++) {
            #pragma unroll
            for (int half = 0; half < 2; half++) {
                int grow = row0 + wm + mt * 16 + (lane >> 2) + half * 8;
                int gcol = col0 + wn + nt * 8 + (lane & 3) * 2;
                float v0 = c[mt][nt][half * 2 + 0];
                float v1 = c[mt][nt][half * 2 + 1];
                if (EPI == 1) {
                    float h0 = fmaxf(v0, 0.f); v0 = h0 * h0;
                    float h1 = fmaxf(v1, 0.f); v1 = h1 * h1;
                }
                if (EPI == 2) {
                    v0 = 15.0f * tanhf(v0 * (1.0f / 15.0f));
                    v1 = 15.0f * tanhf(v1 * (1.0f / 15.0f));
                }
                if (gcol + 1 < N) {
                    size_t p = (size_t)grow * ldc + gcol;
                    if (ACC) { v0 += C[p]; v1 += C[p + 1]; }
                    if (WF32) *(float2*)(C + p) = make_float2(v0, v1);
                    if (WSPLIT) {
                        __nv_bfloat16 h0 = __float2bfloat16(v0);
                        __nv_bfloat16 h1 = __float2bfloat16(v1);
                        *(uint32_t*)(Ch + p) = pack_bf2(h0, h1);
                        *(uint32_t*)(Cl + p) = pack_bf2(
                            __float2bfloat16(v0 - __bfloat162float(h0)),
                            __float2bfloat16(v1 - __bfloat162float(h1)));
                    }
                } else if (gcol < N) {
                    size_t p = (size_t)grow * ldc + gcol;
                    if (ACC) v0 += C[p];
                    if (WF32) C[p] = v0;
                    if (WSPLIT) {
                        __nv_bfloat16 h0 = __float2bfloat16(v0);
                        Ch[p] = h0;
                        Cl[p] = __float2bfloat16(v0 - __bfloat162float(h0));
                    }
                }
            }
        }
    }
}

// ---------------- weight split ----------------
__global__ __launch_bounds__(256) void split_kernel(
    const float* __restrict__ src, __nv_bfloat16* __restrict__ hi,
    __nv_bfloat16* __restrict__ lo, int n4)
{
    int i = blockIdx.x * blockDim.x + threadIdx.x;
    if (i >= n4) return;
    float4 v = ((const float4*)src)[i];
    float f[4] = { v.x, v.y, v.z, v.w };
    union { __nv_bfloat16 h[4]; uint2 u; } ph, pl;
    #pragma unroll
    for (int j = 0; j < 4; j++) {
        __nv_bfloat16 hv = __float2bfloat16(f[j]);
        ph.h[j] = hv;
        pl.h[j] = __float2bfloat16(f[j] - __bfloat162float(hv));
    }
    ((uint2*)hi)[i] = ph.u;
    ((uint2*)lo)[i] = pl.u;
}

// ---------------- block reduce ----------------
__device__ __forceinline__ float blockReduceSum(float v) {
    __shared__ float red[32];
    int lane = threadIdx.x & 31, w = threadIdx.x >> 5;
    #pragma unroll
    for (int o = 16; o; o >>= 1) v += __shfl_xor_sync(0xffffffffu, v, o);
    if (lane == 0) red[w] = v;
    __syncthreads();
    v = (threadIdx.x < (blockDim.x >> 5)) ? red[threadIdx.x] : 0.0f;
    if (w == 0) {
        #pragma unroll
        for (int o = 16; o; o >>= 1) v += __shfl_xor_sync(0xffffffffu, v, o);
        if (lane == 0) red[0] = v;
    }
    __syncthreads();
    return red[0];
}

// ---------------- embed + norms (fused split writes) ----------------
__global__ __launch_bounds__(256) void embed_kernel(
    const int* __restrict__ idx, const float* __restrict__ wte,
    float* __restrict__ x, float* __restrict__ x0)
{
    int i = blockIdx.x;
    const float* row = wte + (size_t)idx[i] * C_;
    float v[4]; float ss = 0.f;
    #pragma unroll
    for (int j = 0; j < 4; j++) { v[j] = row[threadIdx.x + j * 256]; ss += v[j] * v[j]; }
    ss = blockReduceSum(ss);
    float sc = rsqrtf(ss / C_ + EPSF);
    #pragma unroll
    for (int j = 0; j < 4; j++) {
        float o = v[j] * sc;
        x [(size_t)i * C_ + threadIdx.x + j * 256] = o;
        x0[(size_t)i * C_ + threadIdx.x + j * 256] = o;
    }
}

__global__ __launch_bounds__(256) void mixnorm_kernel(
    float* __restrict__ x, const float* __restrict__ x0,
    const float* __restrict__ rl, const float* __restrict__ xl, int l,
    float* __restrict__ xn, __nv_bfloat16* __restrict__ xnh, __nv_bfloat16* __restrict__ xnl)
{
    int i = blockIdx.x;
    float a = rl[l], bc = xl[l];
    float v[4]; float ss = 0.f;
    #pragma unroll
    for (int j = 0; j < 4; j++) {
        size_t p = (size_t)i * C_ + threadIdx.x + j * 256;
        v[j] = a * x[p] + bc * x0[p];
        ss += v[j] * v[j];
    }
    ss = blockReduceSum(ss);
    float sc = rsqrtf(ss / C_ + EPSF);
    #pragma unroll
    for (int j = 0; j < 4; j++) {
        size_t p = (size_t)i * C_ + threadIdx.x + j * 256;
        float o = v[j] * sc;
        x[p] = v[j];
        xn[p] = o;
        __nv_bfloat16 hv = __float2bfloat16(o);
        xnh[p] = hv;
        xnl[p] = __float2bfloat16(o - __bfloat162float(hv));
    }
}

__global__ __launch_bounds__(256) void rmsnorm_kernel(
    const float* __restrict__ x, float* __restrict__ xn,
    __nv_bfloat16* __restrict__ xnh, __nv_bfloat16* __restrict__ xnl)
{
    int i = blockIdx.x;
    float v[4]; float ss = 0.f;
    #pragma unroll
    for (int j = 0; j < 4; j++) {
        v[j] = x[(size_t)i * C_ + threadIdx.x + j * 256];
        ss += v[j] * v[j];
    }
    ss = blockReduceSum(ss);
    float sc = rsqrtf(ss / C_ + EPSF);
    #pragma unroll
    for (int j = 0; j < 4; j++) {
        size_t p = (size_t)i * C_ + threadIdx.x + j * 256;
        float o = v[j] * sc;
        xn[p] = o;
        __nv_bfloat16 hv = __float2bfloat16(o);
        xnh[p] = hv;
        xnl[p] = __float2bfloat16(o - __bfloat162float(hv));
    }
}

// ---------------- per-token q/k/v assembly ----------------
__global__ __launch_bounds__(512) void prep_kernel(
    const float* __restrict__ down, const float* __restrict__ kvb,
    const float* __restrict__ qraw, const float* __restrict__ xn,
    const float* __restrict__ cosb, const float* __restrict__ sinb,
    const float* __restrict__ vg, const float* __restrict__ vetab,
    const int* __restrict__ idx,
    float* __restrict__ Q, float* __restrict__ K, float* __restrict__ V)
{
    int i = blockIdx.x;
    int b = i / T_, t = i % T_;
    int w = threadIdx.x >> 5, lane = threadIdx.x & 31;
    __shared__ float cs[16], sn[16], kr[32];

    if (threadIdx.x < 16)       cs[threadIdx.x]      = cosb[(size_t)i * 16 + threadIdx.x];
    else if (threadIdx.x < 32)  sn[threadIdx.x - 16] = sinb[(size_t)i * 16 + threadIdx.x - 16];
    __syncthreads();

    float gv = xn[(size_t)i * C_ + lane] * vg[lane * H_ + w];
    #pragma unroll
    for (int o = 16; o; o >>= 1) gv += __shfl_xor_sync(0xffffffffu, gv, o);
    float gate = 2.0f / (1.0f + expf(-gv));

    if (w == 0) {
        int j = lane & 15;
        float x1 = down[(size_t)i * DOWN + 512 + j];
        float x2 = down[(size_t)i * DOWN + 528 + j];
        float cc = cs[j], ssn = sn[j];
        kr[lane] = (lane < 16) ? (x1 * cc + x2 * ssn) : (-x1 * ssn + x2 * cc);
    }
    __syncthreads();

    const float* kvrow = kvb  + (size_t)i * KVW + w * 96;
    const float* qrow  = qraw + (size_t)i * C_  + w * 64;
    const float* verow = vetab + (size_t)idx[i] * C_ + w * 64;

    float k0v = kvrow[lane];
    float k1v = kr[lane];
    float q0v = qrow[lane];
    float q1v;
    {
        int j = lane & 15;
        float a = qrow[32 + j], bb = qrow[48 + j];
        float cc = cs[j], ssn = sn[j];
        q1v = (lane < 16) ? (a * cc + bb * ssn) : (-a * ssn + bb * cc);
    }
    float v0 = kvrow[32 + lane] + gate * verow[lane];
    float v1 = kvrow[64 + lane] + gate * verow[32 + lane];

    float kss = k0v * k0v + k1v * k1v;
    float qss = q0v * q0v + q1v * q1v;
    #pragma unroll
    for (int o = 16; o; o >>= 1) {
        kss += __shfl_xor_sync(0xffffffffu, kss, o);
        qss += __shfl_xor_sync(0xffffffffu, qss, o);
    }
    float ksc = rsqrtf(kss * (1.0f / 64.0f) + EPSF);
    float qsc = rsqrtf(qss * (1.0f / 64.0f) + EPSF);

    size_t base = ((size_t)(b * H_ + w) * T_ + t) * 64;
    K[base + lane]      = k0v * ksc;
    K[base + 32 + lane] = k1v * ksc;
    Q[base + lane]      = q0v * qsc;
    Q[base + 32 + lane] = q1v * qsc;
    V[base + lane]      = v0;
    V[base + 32 + lane] = v1;
}

// ---------------- flash attention (fp32, causal) -> bf16 split output ----------------
__global__ __launch_bounds__(256) void attn_kernel(
    const float* __restrict__ Q, const float* __restrict__ Kt,
    const float* __restrict__ Vt,
    __nv_bfloat16* __restrict__ Yh, __nv_bfloat16* __restrict__ Yl)
{
    int qt0 = blockIdx.x * 64;
    int bh  = blockIdx.y;
    int b = bh >> 4, h = bh & 15;
    const float* Qb = Q  + (size_t)bh * T_ * 64;
    const float* Kb = Kt + (size_t)bh * T_ * 64;
    const float* Vb = Vt + (size_t)bh * T_ * 64;

    __shared__ float qs[64][65];
    __shared__ float ks[32][65];
    __shared__ float vs[32][68];
    __shared__ float ps[64][33];

    int tid = threadIdx.x;
    int tr = tid >> 4, tc = tid & 15;

    for (int e = tid; e < 64 * 64; e += 256) {
        int r = e >> 6, c = e & 63;
        qs[r][c] = Qb[(size_t)(qt0 + r) * 64 + c];
    }
    float m[4], l[4], o[4][4];
    #pragma unroll
    for (int mm = 0; mm < 4; mm++) {
        m[mm] = -1e30f; l[mm] = 0.f;
        #pragma unroll
        for (int nn = 0; nn < 4; nn++) o[mm][nn] = 0.f;
    }
    __syncthreads();

    for (int kt0 = 0; kt0 < qt0 + 64; kt0 += 32) {
        for (int e = tid; e < 32 * 64; e += 256) {
            int r = e >> 6, c = e & 63;
            ks[r][c] = Kb[(size_t)(kt0 + r) * 64 + c];
            vs[r][c] = Vb[(size_t)(kt0 + r) * 64 + c];
        }
        __syncthreads();

        float s[4][2];
        #pragma unroll
        for (int mm = 0; mm < 4; mm++) { s[mm][0] = 0.f; s[mm][1] = 0.f; }
        #pragma unroll
        for (int d = 0; d < 64; d++) {
            float a[4], bb[2];
            #pragma unroll
            for (int mm = 0; mm < 4; mm++) a[mm] = qs[tr * 4 + mm][d];
            #pragma unroll
            for (int nn = 0; nn < 2; nn++) bb[nn] = ks[tc * 2 + nn][d];
            #pragma unroll
            for (int mm = 0; mm < 4; mm++)
                #pragma unroll
                for (int nn = 0; nn < 2; nn++)
                    s[mm][nn] = fmaf(a[mm], bb[nn], s[mm][nn]);
        }
        bool edge = (kt0 + 32 > qt0);
        #pragma unroll
        for (int mm = 0; mm < 4; mm++)
            #pragma unroll
            for (int nn = 0; nn < 2; nn++) {
                s[mm][nn] *= 0.125f;
                if (edge) {
                    int qg = qt0 + tr * 4 + mm, kg = kt0 + tc * 2 + nn;
                    if (kg > qg) s[mm][nn] = -1e30f;
                }
            }
        #pragma unroll
        for (int mm = 0; mm < 4; mm++) {
            float rmax = fmaxf(s[mm][0], s[mm][1]);
            #pragma unroll
            for (int off = 1; off < 16; off <<= 1)
                rmax = fmaxf(rmax, __shfl_xor_sync(0xffffffffu, rmax, off));
            float mn = fmaxf(m[mm], rmax);
            float corr = expf(m[mm] - mn);
            float p0 = expf(s[mm][0] - mn);
            float p1 = expf(s[mm][1] - mn);
            float rs = p0 + p1;
            #pragma unroll
            for (int off = 1; off < 16; off <<= 1)
                rs += __shfl_xor_sync(0xffffffffu, rs, off);
            l[mm] = l[mm] * corr + rs;
            m[mm] = mn;
            ps[tr * 4 + mm][tc * 2 + 0] = p0;
            ps[tr * 4 + mm][tc * 2 + 1] = p1;
            #pragma unroll
            for (int nn = 0; nn < 4; nn++) o[mm][nn] *= corr;
        }
        __syncthreads();
        #pragma unroll
        for (int k = 0; k < 32; k++) {
            float pv[4], vv[4];
            #pragma unroll
            for (int mm = 0; mm < 4; mm++) pv[mm] = ps[tr * 4 + mm][k];
            #pragma unroll
            for (int nn = 0; nn < 4; nn++) vv[nn] = vs[k][tc * 4 + nn];
            #pragma unroll
            for (int mm = 0; mm < 4; mm++)
                #pragma unroll
                for (int nn = 0; nn < 4; nn++)
                    o[mm][nn] = fmaf(pv[mm], vv[nn], o[mm][nn]);
        }
        __syncthreads();
    }
    #pragma unroll
    for (int mm = 0; mm < 4; mm++) {
        int q = qt0 + tr * 4 + mm;
        float inv = 1.0f / l[mm];
        #pragma unroll
        for (int nn = 0; nn < 4; nn += 2) {
            size_t p = ((size_t)(b * T_ + q)) * C_ + h * 64 + tc * 4 + nn;
            float v0 = o[mm][nn] * inv, v1 = o[mm][nn + 1] * inv;
            __nv_bfloat16 h0 = __float2bfloat16(v0);
            __nv_bfloat16 h1 = __float2bfloat16(v1);
            *(uint32_t*)(Yh + p) = pack_bf2(h0, h1);
            *(uint32_t*)(Yl + p) = pack_bf2(
                __float2bfloat16(v0 - __bfloat162float(h0)),
                __float2bfloat16(v1 - __bfloat162float(h1)));
        }
    }
}

// ---------------- host side ----------------
template<typename Tp>
static Tp* sym_addr(const void* sym) {
    void* p = nullptr;
    cudaGetSymbolAddress(&p, sym);
    return (Tp*)p;
}
typedef __nv_bfloat16 bf;

struct GemmArgs {
    const bf *Ah, *Al, *Bh, *Bl;
    float* C; bf *Ch, *Cl;
    int M, N, K, lda, ldb, ldc;
};

template<int EPI, bool ACC, bool WSPLIT, bool WF32>
static void launch_g(const GemmArgs& a) {
    static bool done = false;
    if (!done) {
        cudaFuncSetAttribute(gemm_bf16<EPI, ACC, WSPLIT, WF32>,
                             cudaFuncAttributeMaxDynamicSharedMemorySize, GEMM_DSMEM);
        done = true;
    }
    dim3 grid(a.M / 128, (a.N + 127) / 128);
    gemm_bf16<EPI, ACC, WSPLIT, WF32><<<grid, 256, GEMM_DSMEM>>>(
        a.Ah, a.Al, a.Bh, a.Bl, a.C, a.Ch, a.Cl, a.M, a.N, a.K, a.lda, a.ldb, a.ldc);
}

static void split_w(const float* src, bf* hi, bf* lo, size_t n) {
    int n4 = (int)(n / 4);
    split_kernel<<<(n4 + 255) / 256, 256>>>(src, hi, lo, n4);
}

extern "C" void kernel_launch(void* const* d_in, const int* in_sizes, int n_in,
                              void* d_out, int out_size)
{
    (void)in_sizes; (void)n_in; (void)out_size;
    const int*   idx   = (const int*)  d_in[0];
    const float* cosb  = (const float*)d_in[1];
    const float* sinb  = (const float*)d_in[2];
    const float* wte   = (const float*)d_in[3];
    const float* vetab = (const float*)d_in[4];
    const float* wd    = (const float*)d_in[5];
    const float* wukv  = (const float*)d_in[6];
    const float* wuq   = (const float*)d_in[7];
    const float* vg    = (const float*)d_in[8];
    const float* ap    = (const float*)d_in[9];
    const float* fc    = (const float*)d_in[10];
    const float* pj    = (const float*)d_in[11];
    const float* rl    = (const float*)d_in[12];
    const float* xl    = (const float*)d_in[13];
    const float* lmh   = (const float*)d_in[14];
    float* out = (float*)d_out;

    float* px    = sym_addr<float>(g_x);
    float* px0   = sym_addr<float>(g_x0);
    float* pxn   = sym_addr<float>(g_xn);
    float* pdown = sym_addr<float>(g_down);
    float* pkv   = sym_addr<float>(g_kv);
    float* pqraw = sym_addr<float>(g_qraw);
    float* pq    = sym_addr<float>(g_q);
    float* pk    = sym_addr<float>(g_k);
    float* pv    = sym_addr<float>(g_v);

    bf *wdh = sym_addr<bf>(s_wd_h),   *wdl = sym_addr<bf>(s_wd_l);
    bf *ukh = sym_addr<bf>(s_wukv_h), *ukl = sym_addr<bf>(s_wukv_l);
    bf *uqh = sym_addr<bf>(s_wuq_h),  *uql = sym_addr<bf>(s_wuq_l);
    bf *aph = sym_addr<bf>(s_ap_h),   *apl = sym_addr<bf>(s_ap_l);
    bf *fch = sym_addr<bf>(s_fc_h),   *fcl = sym_addr<bf>(s_fc_l);
    bf *pjh = sym_addr<bf>(s_pj_h),   *pjl = sym_addr<bf>(s_pj_l);
    bf *lmh_h = sym_addr<bf>(s_lmh_h), *lmh_l = sym_addr<bf>(s_lmh_l);
    bf *xnh = sym_addr<bf>(s_xn_h),   *xnl = sym_addr<bf>(s_xn_l);
    bf *dnh = sym_addr<bf>(s_dn_h),   *dnl = sym_addr<bf>(s_dn_l);
    bf *hhh = sym_addr<bf>(s_h_h),    *hhl = sym_addr<bf>(s_h_l);
    bf *yh  = sym_addr<bf>(s_y_h),    *yl  = sym_addr<bf>(s_y_l);

    // weight splits (cheap, once per call)
    split_w(wd,   wdh, wdl, (size_t)L_ * C_ * DOWN);
    split_w(wukv, ukh, ukl, (size_t)L_ * DC * KVW);
    split_w(wuq,  uqh, uql, (size_t)L_ * DC1 * C_);
    split_w(ap,   aph, apl, (size_t)L_ * C_ * C_);
    split_w(fc,   fch, fcl, (size_t)L_ * C_ * 4096);
    split_w(pj,   pjh, pjl, (size_t)L_ * 4096 * C_);
    split_w(lmh,  lmh_h, lmh_l, (size_t)C_ * VSZ);

    embed_kernel<<<TKN, 256>>>(idx, wte, px, px0);

    for (int l = 0; l < L_; l++) {
        mixnorm_kernel<<<TKN, 256>>>(px, px0, rl, xl, l, pxn, xnh, xnl);

        // down = xn @ wd[l]  -> fp32 + split
        launch_g<0, false, true, true>({ xnh, xnl,
            wdh + (size_t)l * C_ * DOWN, wdl + (size_t)l * C_ * DOWN,
            pdown, dnh, dnl, TKN, DOWN, C_, C_, DOWN, DOWN });
        // kv = down[:, :256] @ wukv[l] -> fp32
        launch_g<0, false, false, true>({ dnh, dnl,
            ukh + (size_t)l * DC * KVW, ukl + (size_t)l * DC * KVW,
            pkv, nullptr, nullptr, TKN, KVW, DC, DOWN, KVW, KVW });
        // qraw = down[:, 256:512] @ wuq[l] -> fp32
        launch_g<0, false, false, true>({ dnh + DC, dnl + DC,
            uqh + (size_t)l * DC1 * C_, uql + (size_t)l * DC1 * C_,
            pqraw, nullptr, nullptr, TKN, C_, DC1, DOWN, C_, C_ });

        prep_kernel<<<TKN, 512>>>(pdown, pkv, pqraw, pxn, cosb, sinb,
                                  vg + (size_t)l * GC * H_,
                                  vetab + (size_t)l * VSZ * C_,
                                  idx, pq, pk, pv);

        attn_kernel<<<dim3(T_ / 64, B_ * H_), 256>>>(pq, pk, pv, yh, yl);

        // x += y @ attn_proj[l]
        launch_g<0, true, false, true>({ yh, yl,
            aph + (size_t)l * C_ * C_, apl + (size_t)l * C_ * C_,
            px, nullptr, nullptr, TKN, C_, C_, C_, C_, C_ });

        rmsnorm_kernel<<<TKN, 256>>>(px, pxn, xnh, xnl);

        // h = relu(xn @ fc[l])^2 -> split only
        launch_g<1, false, true, false>({ xnh, xnl,
            fch + (size_t)l * C_ * 4096, fcl + (size_t)l * C_ * 4096,
            nullptr, hhh, hhl, TKN, 4096, C_, C_, 4096, 4096 });
        // x += h @ proj[l]
        launch_g<0, true, false, true>({ hhh, hhl,
            pjh + (size_t)l * 4096 * C_, pjl + (size_t)l * 4096 * C_,
            px, nullptr, nullptr, TKN, C_, 4096, 4096, C_, C_ });
    }

    rmsnorm_kernel<<<TKN, 256>>>(px, pxn, xnh, xnl);
    // logits = softcap(xn @ lm_head)
    launch_g<2, false, false, true>({ xnh, xnl, lmh_h, lmh_l,
        out, nullptr, nullptr, TKN, VSZ, C_, C_, VSZ, VSZ });
}

// round 6
// speedup vs baseline: 2.9984x; 1.1026x over previous
#include <cuda_runtime.h>
#include <cuda_bf16.h>
#include <math.h>
#include <stdint.h>

// ---------------- problem constants ----------------
#define B_    2
#define T_    1024
#define C_    1024
#define H_    16
#define HD_   64
#define DC    256
#define DC1   256
#define DR    32
#define DN    32
#define DOWN  544
#define VSZ   32000
#define L_    4
#define GC    32
#define TKN   2048
#define KVW   1536
#define EPSF  1.1920929e-7f

// ---------------- fp32 scratch ----------------
__device__ float g_x   [TKN * C_];
__device__ float g_x0  [TKN * C_];
__device__ float g_xn  [TKN * C_];
__device__ float g_down[TKN * DOWN];
__device__ float g_kv  [TKN * KVW];
__device__ float g_qraw[TKN * C_];
__device__ float g_q   [B_ * H_ * T_ * HD_];
__device__ float g_k   [B_ * H_ * T_ * HD_];
__device__ float g_v   [B_ * H_ * T_ * HD_];

// ---------------- bf16 hi/lo split buffers ----------------
__device__ __nv_bfloat16 s_wd_h  [L_ * C_ * DOWN],  s_wd_l  [L_ * C_ * DOWN];
__device__ __nv_bfloat16 s_wukv_h[L_ * DC * KVW],   s_wukv_l[L_ * DC * KVW];
__device__ __nv_bfloat16 s_wuq_h [L_ * DC1 * C_],   s_wuq_l [L_ * DC1 * C_];
__device__ __nv_bfloat16 s_ap_h  [L_ * C_ * C_],    s_ap_l  [L_ * C_ * C_];
__device__ __nv_bfloat16 s_fc_h  [L_ * C_ * 4096],  s_fc_l  [L_ * C_ * 4096];
__device__ __nv_bfloat16 s_pj_h  [L_ * 4096 * C_],  s_pj_l  [L_ * 4096 * C_];
__device__ __nv_bfloat16 s_lmh_h [C_ * VSZ],        s_lmh_l [C_ * VSZ];
__device__ __nv_bfloat16 s_xn_h  [TKN * C_],        s_xn_l  [TKN * C_];
__device__ __nv_bfloat16 s_dn_h  [TKN * DOWN],      s_dn_l  [TKN * DOWN];
__device__ __nv_bfloat16 s_h_h   [TKN * 4096],      s_h_l   [TKN * 4096];
__device__ __nv_bfloat16 s_y_h   [TKN * C_],        s_y_l   [TKN * C_];

// ================= helpers =================
__device__ __forceinline__ uint32_t smem_u32(const void* p) {
    uint32_t a;
    asm("{ .reg .u64 t; cvta.to.shared.u64 t, %1; cvt.u32.u64 %0, t; }" : "=r"(a) : "l"(p));
    return a;
}
__device__ __forceinline__ void ldsm_x4(uint32_t r[4], uint32_t addr) {
    asm volatile("ldmatrix.sync.aligned.m8n8.x4.shared.b16 {%0,%1,%2,%3}, [%4];"
        : "=r"(r[0]), "=r"(r[1]), "=r"(r[2]), "=r"(r[3]) : "r"(addr));
}
__device__ __forceinline__ void ldsm_x2t(uint32_t r[2], uint32_t addr) {
    asm volatile("ldmatrix.sync.aligned.m8n8.x2.trans.shared.b16 {%0,%1}, [%2];"
        : "=r"(r[0]), "=r"(r[1]) : "r"(addr));
}
__device__ __forceinline__ void mma_bf16(float c[4], const uint32_t a[4], const uint32_t b[2]) {
    asm volatile("mma.sync.aligned.m16n8k16.row.col.f32.bf16.bf16.f32 "
        "{%0,%1,%2,%3}, {%4,%5,%6,%7}, {%8,%9}, {%0,%1,%2,%3};"
        : "+f"(c[0]), "+f"(c[1]), "+f"(c[2]), "+f"(c[3])
        : "r"(a[0]), "r"(a[1]), "r"(a[2]), "r"(a[3]), "r"(b[0]), "r"(b[1]));
}
__device__ __forceinline__ void cp16(uint32_t dst, const void* src) {
    asm volatile("cp.async.cg.shared.global [%0], [%1], 16;" :: "r"(dst), "l"(src));
}
__device__ __forceinline__ void cp16z(uint32_t dst, const void* src, uint32_t ssize) {
    asm volatile("cp.async.cg.shared.global [%0], [%1], 16, %2;" :: "r"(dst), "l"(src), "r"(ssize));
}
#define CP_COMMIT() asm volatile("cp.async.commit_group;" ::: "memory")
#define CP_WAIT1()  asm volatile("cp.async.wait_group 1;" ::: "memory")
__device__ __forceinline__ uint32_t pack_bf2(__nv_bfloat16 a, __nv_bfloat16 b) {
    union { __nv_bfloat16 h[2]; uint32_t u; } u;
    u.h[0] = a; u.h[1] = b;
    return u.u;
}

// smem per stage: A_hi[TM][40] | A_lo | B_hi[32][136] | B_lo
// TM=128: stride 37888; TM=64: stride 27648. 3 stages.
// C[M,N] = A[M,K] @ B[K,N]; bf16 hi/lo inputs, fp32 (+optional bf16 split) output.
template<int TM, int EPI, bool ACC, bool WSPLIT, bool WF32>
__global__ __launch_bounds__(256, 2) void gemm_bf16(
    const __nv_bfloat16* __restrict__ Ah, const __nv_bfloat16* __restrict__ Al,
    const __nv_bfloat16* __restrict__ Bh, const __nv_bfloat16* __restrict__ Bl,
    float* __restrict__ C, __nv_bfloat16* __restrict__ Ch, __nv_bfloat16* __restrict__ Cl,
    int M, int N, int K, int lda, int ldb, int ldc)
{
    constexpr int MT     = TM / 32;          // m-subtiles (16 rows) per warp
    constexpr int A_SZ   = TM * 80;          // bytes per A half
    constexpr int B_OFF  = 2 * A_SZ;
    constexpr int STRIDE = B_OFF + 17408;

    extern __shared__ char dsm[];
    uint32_t sraw = smem_u32(dsm);
    uint32_t s0 = (sraw + 127u) & ~127u;

    int tid = threadIdx.x, wid = tid >> 5, lane = tid & 31;
    int row0 = blockIdx.x * TM, col0 = blockIdx.y * 128;
    int wm = (wid >> 2) * (TM / 2);
    int wn = (wid & 3) * 32;

    float c[MT][4][4];
    #pragma unroll
    for (int mt = 0; mt < MT; mt++)
        #pragma unroll
        for (int nt = 0; nt < 4; nt++)
            #pragma unroll
            for (int r = 0; r < 4; r++) c[mt][nt][r] = 0.f;

    int NC = K >> 5;

    auto issue_copy = [&](int i, int stg) {
        int k0 = i << 5;
        uint32_t sb = s0 + (uint32_t)stg * STRIDE;
        #pragma unroll
        for (int e = tid; e < TM * 4; e += 256) {
            int r = e >> 2, seg = e & 3;
            uint32_t d = sb + (uint32_t)(r * 80 + seg * 16);
            cp16(d,                    Ah + (size_t)(row0 + r) * lda + k0 + seg * 8);
            cp16(d + (uint32_t)A_SZ,   Al + (size_t)(row0 + r) * lda + k0 + seg * 8);
        }
        #pragma unroll
        for (int e0 = 0; e0 < 2; e0++) {
            int e = tid + e0 * 256;
            int kk = e >> 4, seg = e & 15;
            int gc = col0 + seg * 8;
            uint32_t d = sb + (uint32_t)B_OFF + (uint32_t)(kk * 272 + seg * 16);
            int rem = N - gc;
            uint32_t sz = rem >= 8 ? 16u : (rem > 0 ? (uint32_t)(rem * 2) : 0u);
            cp16z(d,         Bh + (size_t)(k0 + kk) * ldb + gc, sz);
            cp16z(d + 8704u, Bl + (size_t)(k0 + kk) * ldb + gc, sz);
        }
    };

    auto mma_chunk = [&](int stg) {
        uint32_t base = s0 + (uint32_t)stg * STRIDE;
        int arow = wm + ((lane >> 3) & 1) * 8 + (lane & 7);
        int krow = lane & 15;
        #pragma unroll
        for (int kk = 0; kk < 32; kk += 16) {
            uint32_t af[MT][4], bh[4][2], bl[4][2];
            int acol = kk + ((lane >> 4) & 1) * 8;
            #pragma unroll
            for (int mt = 0; mt < MT; mt++)
                ldsm_x4(af[mt], base + (uint32_t)((arow + mt * 16) * 80 + acol * 2));
            #pragma unroll
            for (int nt = 0; nt < 4; nt++) {
                uint32_t bd = base + (uint32_t)B_OFF + (uint32_t)((kk + krow) * 272 + (wn + nt * 8) * 2);
                ldsm_x2t(bh[nt], bd);
                ldsm_x2t(bl[nt], bd + 8704u);
            }
            #pragma unroll
            for (int mt = 0; mt < MT; mt++)
                #pragma unroll
                for (int nt = 0; nt < 4; nt++)
                    mma_bf16(c[mt][nt], af[mt], bh[nt]);
            #pragma unroll
            for (int mt = 0; mt < MT; mt++)
                #pragma unroll
                for (int nt = 0; nt < 4; nt++)
                    mma_bf16(c[mt][nt], af[mt], bl[nt]);
            #pragma unroll
            for (int mt = 0; mt < MT; mt++)
                ldsm_x4(af[mt], base + (uint32_t)A_SZ + (uint32_t)((arow + mt * 16) * 80 + acol * 2));
            #pragma unroll
            for (int mt = 0; mt < MT; mt++)
                #pragma unroll
                for (int nt = 0; nt < 4; nt++)
                    mma_bf16(c[mt][nt], af[mt], bh[nt]);
        }
    };

    issue_copy(0, 0); CP_COMMIT();
    issue_copy(1, 1); CP_COMMIT();
    for (int i = 0; i < NC; i++) {
        CP_WAIT1();
        __syncthreads();
        mma_chunk(i % 3);
        // stage written below is (i+2)%3, distinct from (i)%3 being read and
        // (i+1)%3 in flight; top-of-loop barrier orders reuse -> no 2nd barrier.
        if (i + 2 < NC) issue_copy(i + 2, (i + 2) % 3);
        CP_COMMIT();
    }

    // ---- epilogue ----
    #pragma unroll
    for (int mt = 0; mt < MT; mt++) {
        #pragma unroll
        for (int nt = 0; nt < 4; nt++) {
            #pragma unroll
            for (int half = 0; half < 2; half++) {
                int grow = row0 + wm + mt * 16 + (lane >> 2) + half * 8;
                int gcol = col0 + wn + nt * 8 + (lane & 3) * 2;
                float v0 = c[mt][nt][half * 2 + 0];
                float v1 = c[mt][nt][half * 2 + 1];
                if (EPI == 1) {
                    float h0 = fmaxf(v0, 0.f); v0 = h0 * h0;
                    float h1 = fmaxf(v1, 0.f); v1 = h1 * h1;
                }
                if (EPI == 2) {
                    v0 = 15.0f * tanhf(v0 * (1.0f / 15.0f));
                    v1 = 15.0f * tanhf(v1 * (1.0f / 15.0f));
                }
                if (gcol + 1 < N) {
                    size_t p = (size_t)grow * ldc + gcol;
                    if (ACC) { v0 += C[p]; v1 += C[p + 1]; }
                    if (WF32) *(float2*)(C + p) = make_float2(v0, v1);
                    if (WSPLIT) {
                        __nv_bfloat16 h0 = __float2bfloat16(v0);
                        __nv_bfloat16 h1 = __float2bfloat16(v1);
                        *(uint32_t*)(Ch + p) = pack_bf2(h0, h1);
                        *(uint32_t*)(Cl + p) = pack_bf2(
                            __float2bfloat16(v0 - __bfloat162float(h0)),
                            __float2bfloat16(v1 - __bfloat162float(h1)));
                    }
                } else if (gcol < N) {
                    size_t p = (size_t)grow * ldc + gcol;
                    if (ACC) v0 += C[p];
                    if (WF32) C[p] = v0;
                    if (WSPLIT) {
                        __nv_bfloat16 h0 = __float2bfloat16(v0);
                        Ch[p] = h0;
                        Cl[p] = __float2bfloat16(v0 - __bfloat162float(h0));
                    }
                }
            }
        }
    }
}

// ---------------- weight split ----------------
__global__ __launch_bounds__(256) void split_kernel(
    const float* __restrict__ src, __nv_bfloat16* __restrict__ hi,
    __nv_bfloat16* __restrict__ lo, int n4)
{
    int i = blockIdx.x * blockDim.x + threadIdx.x;
    if (i >= n4) return;
    float4 v = ((const float4*)src)[i];
    float f[4] = { v.x, v.y, v.z, v.w };
    union { __nv_bfloat16 h[4]; uint2 u; } ph, pl;
    #pragma unroll
    for (int j = 0; j < 4; j++) {
        __nv_bfloat16 hv = __float2bfloat16(f[j]);
        ph.h[j] = hv;
        pl.h[j] = __float2bfloat16(f[j] - __bfloat162float(hv));
    }
    ((uint2*)hi)[i] = ph.u;
    ((uint2*)lo)[i] = pl.u;
}

// ---------------- block reduce ----------------
__device__ __forceinline__ float blockReduceSum(float v) {
    __shared__ float red[32];
    int lane = threadIdx.x & 31, w = threadIdx.x >> 5;
    #pragma unroll
    for (int o = 16; o; o >>= 1) v += __shfl_xor_sync(0xffffffffu, v, o);
    if (lane == 0) red[w] = v;
    __syncthreads();
    v = (threadIdx.x < (blockDim.x >> 5)) ? red[threadIdx.x] : 0.0f;
    if (w == 0) {
        #pragma unroll
        for (int o = 16; o; o >>= 1) v += __shfl_xor_sync(0xffffffffu, v, o);
        if (lane == 0) red[0] = v;
    }
    __syncthreads();
    return red[0];
}

// ---------------- embed + norms (fused split writes) ----------------
__global__ __launch_bounds__(256) void embed_kernel(
    const int* __restrict__ idx, const float* __restrict__ wte,
    float* __restrict__ x, float* __restrict__ x0)
{
    int i = blockIdx.x;
    const float* row = wte + (size_t)idx[i] * C_;
    float v[4]; float ss = 0.f;
    #pragma unroll
    for (int j = 0; j < 4; j++) { v[j] = row[threadIdx.x + j * 256]; ss += v[j] * v[j]; }
    ss = blockReduceSum(ss);
    float sc = rsqrtf(ss / C_ + EPSF);
    #pragma unroll
    for (int j = 0; j < 4; j++) {
        float o = v[j] * sc;
        x [(size_t)i * C_ + threadIdx.x + j * 256] = o;
        x0[(size_t)i * C_ + threadIdx.x + j * 256] = o;
    }
}

__global__ __launch_bounds__(256) void mixnorm_kernel(
    float* __restrict__ x, const float* __restrict__ x0,
    const float* __restrict__ rl, const float* __restrict__ xl, int l,
    float* __restrict__ xn, __nv_bfloat16* __restrict__ xnh, __nv_bfloat16* __restrict__ xnl)
{
    int i = blockIdx.x;
    float a = rl[l], bc = xl[l];
    float v[4]; float ss = 0.f;
    #pragma unroll
    for (int j = 0; j < 4; j++) {
        size_t p = (size_t)i * C_ + threadIdx.x + j * 256;
        v[j] = a * x[p] + bc * x0[p];
        ss += v[j] * v[j];
    }
    ss = blockReduceSum(ss);
    float sc = rsqrtf(ss / C_ + EPSF);
    #pragma unroll
    for (int j = 0; j < 4; j++) {
        size_t p = (size_t)i * C_ + threadIdx.x + j * 256;
        float o = v[j] * sc;
        x[p] = v[j];
        xn[p] = o;
        __nv_bfloat16 hv = __float2bfloat16(o);
        xnh[p] = hv;
        xnl[p] = __float2bfloat16(o - __bfloat162float(hv));
    }
}

__global__ __launch_bounds__(256) void rmsnorm_kernel(
    const float* __restrict__ x, float* __restrict__ xn,
    __nv_bfloat16* __restrict__ xnh, __nv_bfloat16* __restrict__ xnl)
{
    int i = blockIdx.x;
    float v[4]; float ss = 0.f;
    #pragma unroll
    for (int j = 0; j < 4; j++) {
        v[j] = x[(size_t)i * C_ + threadIdx.x + j * 256];
        ss += v[j] * v[j];
    }
    ss = blockReduceSum(ss);
    float sc = rsqrtf(ss / C_ + EPSF);
    #pragma unroll
    for (int j = 0; j < 4; j++) {
        size_t p = (size_t)i * C_ + threadIdx.x + j * 256;
        float o = v[j] * sc;
        xn[p] = o;
        __nv_bfloat16 hv = __float2bfloat16(o);
        xnh[p] = hv;
        xnl[p] = __float2bfloat16(o - __bfloat162float(hv));
    }
}

// ---------------- per-token q/k/v assembly ----------------
__global__ __launch_bounds__(512) void prep_kernel(
    const float* __restrict__ down, const float* __restrict__ kvb,
    const float* __restrict__ qraw, const float* __restrict__ xn,
    const float* __restrict__ cosb, const float* __restrict__ sinb,
    const float* __restrict__ vg, const float* __restrict__ vetab,
    const int* __restrict__ idx,
    float* __restrict__ Q, float* __restrict__ K, float* __restrict__ V)
{
    int i = blockIdx.x;
    int b = i / T_, t = i % T_;
    int w = threadIdx.x >> 5, lane = threadIdx.x & 31;
    __shared__ float cs[16], sn[16], kr[32];

    if (threadIdx.x < 16)       cs[threadIdx.x]      = cosb[(size_t)i * 16 + threadIdx.x];
    else if (threadIdx.x < 32)  sn[threadIdx.x - 16] = sinb[(size_t)i * 16 + threadIdx.x - 16];
    __syncthreads();

    float gv = xn[(size_t)i * C_ + lane] * vg[lane * H_ + w];
    #pragma unroll
    for (int o = 16; o; o >>= 1) gv += __shfl_xor_sync(0xffffffffu, gv, o);
    float gate = 2.0f / (1.0f + expf(-gv));

    if (w == 0) {
        int j = lane & 15;
        float x1 = down[(size_t)i * DOWN + 512 + j];
        float x2 = down[(size_t)i * DOWN + 528 + j];
        float cc = cs[j], ssn = sn[j];
        kr[lane] = (lane < 16) ? (x1 * cc + x2 * ssn) : (-x1 * ssn + x2 * cc);
    }
    __syncthreads();

    const float* kvrow = kvb  + (size_t)i * KVW + w * 96;
    const float* qrow  = qraw + (size_t)i * C_  + w * 64;
    const float* verow = vetab + (size_t)idx[i] * C_ + w * 64;

    float k0v = kvrow[lane];
    float k1v = kr[lane];
    float q0v = qrow[lane];
    float q1v;
    {
        int j = lane & 15;
        float a = qrow[32 + j], bb = qrow[48 + j];
        float cc = cs[j], ssn = sn[j];
        q1v = (lane < 16) ? (a * cc + bb * ssn) : (-a * ssn + bb * cc);
    }
    float v0 = kvrow[32 + lane] + gate * verow[lane];
    float v1 = kvrow[64 + lane] + gate * verow[32 + lane];

    float kss = k0v * k0v + k1v * k1v;
    float qss = q0v * q0v + q1v * q1v;
    #pragma unroll
    for (int o = 16; o; o >>= 1) {
        kss += __shfl_xor_sync(0xffffffffu, kss, o);
        qss += __shfl_xor_sync(0xffffffffu, qss, o);
    }
    float ksc = rsqrtf(kss * (1.0f / 64.0f) + EPSF);
    float qsc = rsqrtf(qss * (1.0f / 64.0f) + EPSF);

    size_t base = ((size_t)(b * H_ + w) * T_ + t) * 64;
    K[base + lane]      = k0v * ksc;
    K[base + 32 + lane] = k1v * ksc;
    Q[base + lane]      = q0v * qsc;
    Q[base + 32 + lane] = q1v * qsc;
    V[base + lane]      = v0;
    V[base + 32 + lane] = v1;
}

// ---------------- flash attention (fp32, causal) -> bf16 split output ----------------
__global__ __launch_bounds__(256) void attn_kernel(
    const float* __restrict__ Q, const float* __restrict__ Kt,
    const float* __restrict__ Vt,
    __nv_bfloat16* __restrict__ Yh, __nv_bfloat16* __restrict__ Yl)
{
    int qt0 = blockIdx.x * 64;
    int bh  = blockIdx.y;
    int b = bh >> 4, h = bh & 15;
    const float* Qb = Q  + (size_t)bh * T_ * 64;
    const float* Kb = Kt + (size_t)bh * T_ * 64;
    const float* Vb = Vt + (size_t)bh * T_ * 64;

    __shared__ float qs[64][65];
    __shared__ float ks[32][65];
    __shared__ float vs[32][68];
    __shared__ float ps[64][33];

    int tid = threadIdx.x;
    int tr = tid >> 4, tc = tid & 15;

    for (int e = tid; e < 64 * 64; e += 256) {
        int r = e >> 6, c = e & 63;
        qs[r][c] = Qb[(size_t)(qt0 + r) * 64 + c];
    }
    float m[4], l[4], o[4][4];
    #pragma unroll
    for (int mm = 0; mm < 4; mm++) {
        m[mm] = -1e30f; l[mm] = 0.f;
        #pragma unroll
        for (int nn = 0; nn < 4; nn++) o[mm][nn] = 0.f;
    }
    __syncthreads();

    for (int kt0 = 0; kt0 < qt0 + 64; kt0 += 32) {
        for (int e = tid; e < 32 * 64; e += 256) {
            int r = e >> 6, c = e & 63;
            ks[r][c] = Kb[(size_t)(kt0 + r) * 64 + c];
            vs[r][c] = Vb[(size_t)(kt0 + r) * 64 + c];
        }
        __syncthreads();

        float s[4][2];
        #pragma unroll
        for (int mm = 0; mm < 4; mm++) { s[mm][0] = 0.f; s[mm][1] = 0.f; }
        #pragma unroll
        for (int d = 0; d < 64; d++) {
            float a[4], bb[2];
            #pragma unroll
            for (int mm = 0; mm < 4; mm++) a[mm] = qs[tr * 4 + mm][d];
            #pragma unroll
            for (int nn = 0; nn < 2; nn++) bb[nn] = ks[tc * 2 + nn][d];
            #pragma unroll
            for (int mm = 0; mm < 4; mm++)
                #pragma unroll
                for (int nn = 0; nn < 2; nn++)
                    s[mm][nn] = fmaf(a[mm], bb[nn], s[mm][nn]);
        }
        bool edge = (kt0 + 32 > qt0);
        #pragma unroll
        for (int mm = 0; mm < 4; mm++)
            #pragma unroll
            for (int nn = 0; nn < 2; nn++) {
                s[mm][nn] *= 0.125f;
                if (edge) {
                    int qg = qt0 + tr * 4 + mm, kg = kt0 + tc * 2 + nn;
                    if (kg > qg) s[mm][nn] = -1e30f;
                }
            }
        #pragma unroll
        for (int mm = 0; mm < 4; mm++) {
            float rmax = fmaxf(s[mm][0], s[mm][1]);
            #pragma unroll
            for (int off = 1; off < 16; off <<= 1)
                rmax = fmaxf(rmax, __shfl_xor_sync(0xffffffffu, rmax, off));
            float mn = fmaxf(m[mm], rmax);
            float corr = expf(m[mm] - mn);
            float p0 = expf(s[mm][0] - mn);
            float p1 = expf(s[mm][1] - mn);
            float rs = p0 + p1;
            #pragma unroll
            for (int off = 1; off < 16; off <<= 1)
                rs += __shfl_xor_sync(0xffffffffu, rs, off);
            l[mm] = l[mm] * corr + rs;
            m[mm] = mn;
            ps[tr * 4 + mm][tc * 2 + 0] = p0;
            ps[tr * 4 + mm][tc * 2 + 1] = p1;
            #pragma unroll
            for (int nn = 0; nn < 4; nn++) o[mm][nn] *= corr;
        }
        __syncthreads();
        #pragma unroll
        for (int k = 0; k < 32; k++) {
            float pv[4], vv[4];
            #pragma unroll
            for (int mm = 0; mm < 4; mm++) pv[mm] = ps[tr * 4 + mm][k];
            #pragma unroll
            for (int nn = 0; nn < 4; nn++) vv[nn] = vs[k][tc * 4 + nn];
            #pragma unroll
            for (int mm = 0; mm < 4; mm++)
                #pragma unroll
                for (int nn = 0; nn < 4; nn++)
                    o[mm][nn] = fmaf(pv[mm], vv[nn], o[mm][nn]);
        }
        __syncthreads();
    }
    #pragma unroll
    for (int mm = 0; mm < 4; mm++) {
        int q = qt0 + tr * 4 + mm;
        float inv = 1.0f / l[mm];
        #pragma unroll
        for (int nn = 0; nn < 4; nn += 2) {
            size_t p = ((size_t)(b * T_ + q)) * C_ + h * 64 + tc * 4 + nn;
            float v0 = o[mm][nn] * inv, v1 = o[mm][nn + 1] * inv;
            __nv_bfloat16 h0 = __float2bfloat16(v0);
            __nv_bfloat16 h1 = __float2bfloat16(v1);
            *(uint32_t*)(Yh + p) = pack_bf2(h0, h1);
            *(uint32_t*)(Yl + p) = pack_bf2(
                __float2bfloat16(v0 - __bfloat162float(h0)),
                __float2bfloat16(v1 - __bfloat162float(h1)));
        }
    }
}

// ---------------- host side ----------------
template<typename Tp>
static Tp* sym_addr(const void* sym) {
    void* p = nullptr;
    cudaGetSymbolAddress(&p, sym);
    return (Tp*)p;
}
typedef __nv_bfloat16 bf;

struct GemmArgs {
    const bf *Ah, *Al, *Bh, *Bl;
    float* C; bf *Ch, *Cl;
    int M, N, K, lda, ldb, ldc;
};

template<int TM, int EPI, bool ACC, bool WSPLIT, bool WF32>
static void launch_g(const GemmArgs& a) {
    constexpr int STRIDE = (2 * TM * 80) + 17408;
    constexpr int DSMEM  = 3 * STRIDE + 128;
    static bool done = false;
    if (!done) {
        cudaFuncSetAttribute(gemm_bf16<TM, EPI, ACC, WSPLIT, WF32>,
                             cudaFuncAttributeMaxDynamicSharedMemorySize, DSMEM);
        done = true;
    }
    dim3 grid(a.M / TM, (a.N + 127) / 128);
    gemm_bf16<TM, EPI, ACC, WSPLIT, WF32><<<grid, 256, DSMEM>>>(
        a.Ah, a.Al, a.Bh, a.Bl, a.C, a.Ch, a.Cl, a.M, a.N, a.K, a.lda, a.ldb, a.ldc);
}

static void split_w(const float* src, bf* hi, bf* lo, size_t n) {
    int n4 = (int)(n / 4);
    split_kernel<<<(n4 + 255) / 256, 256>>>(src, hi, lo, n4);
}

extern "C" void kernel_launch(void* const* d_in, const int* in_sizes, int n_in,
                              void* d_out, int out_size)
{
    (void)in_sizes; (void)n_in; (void)out_size;
    const int*   idx   = (const int*)  d_in[0];
    const float* cosb  = (const float*)d_in[1];
    const float* sinb  = (const float*)d_in[2];
    const float* wte   = (const float*)d_in[3];
    const float* vetab = (const float*)d_in[4];
    const float* wd    = (const float*)d_in[5];
    const float* wukv  = (const float*)d_in[6];
    const float* wuq   = (const float*)d_in[7];
    const float* vg    = (const float*)d_in[8];
    const float* ap    = (const float*)d_in[9];
    const float* fc    = (const float*)d_in[10];
    const float* pj    = (const float*)d_in[11];
    const float* rl    = (const float*)d_in[12];
    const float* xl    = (const float*)d_in[13];
    const float* lmh   = (const float*)d_in[14];
    float* out = (float*)d_out;

    float* px    = sym_addr<float>(g_x);
    float* px0   = sym_addr<float>(g_x0);
    float* pxn   = sym_addr<float>(g_xn);
    float* pdown = sym_addr<float>(g_down);
    float* pkv   = sym_addr<float>(g_kv);
    float* pqraw = sym_addr<float>(g_qraw);
    float* pq    = sym_addr<float>(g_q);
    float* pk    = sym_addr<float>(g_k);
    float* pv    = sym_addr<float>(g_v);

    bf *wdh = sym_addr<bf>(s_wd_h),   *wdl = sym_addr<bf>(s_wd_l);
    bf *ukh = sym_addr<bf>(s_wukv_h), *ukl = sym_addr<bf>(s_wukv_l);
    bf *uqh = sym_addr<bf>(s_wuq_h),  *uql = sym_addr<bf>(s_wuq_l);
    bf *aph = sym_addr<bf>(s_ap_h),   *apl = sym_addr<bf>(s_ap_l);
    bf *fch = sym_addr<bf>(s_fc_h),   *fcl = sym_addr<bf>(s_fc_l);
    bf *pjh = sym_addr<bf>(s_pj_h),   *pjl = sym_addr<bf>(s_pj_l);
    bf *lmh_h = sym_addr<bf>(s_lmh_h), *lmh_l = sym_addr<bf>(s_lmh_l);
    bf *xnh = sym_addr<bf>(s_xn_h),   *xnl = sym_addr<bf>(s_xn_l);
    bf *dnh = sym_addr<bf>(s_dn_h),   *dnl = sym_addr<bf>(s_dn_l);
    bf *hhh = sym_addr<bf>(s_h_h),    *hhl = sym_addr<bf>(s_h_l);
    bf *yh  = sym_addr<bf>(s_y_h),    *yl  = sym_addr<bf>(s_y_l);

    // weight splits (once per call)
    split_w(wd,   wdh, wdl, (size_t)L_ * C_ * DOWN);
    split_w(wukv, ukh, ukl, (size_t)L_ * DC * KVW);
    split_w(wuq,  uqh, uql, (size_t)L_ * DC1 * C_);
    split_w(ap,   aph, apl, (size_t)L_ * C_ * C_);
    split_w(fc,   fch, fcl, (size_t)L_ * C_ * 4096);
    split_w(pj,   pjh, pjl, (size_t)L_ * 4096 * C_);
    split_w(lmh,  lmh_h, lmh_l, (size_t)C_ * VSZ);

    embed_kernel<<<TKN, 256>>>(idx, wte, px, px0);

    for (int l = 0; l < L_; l++) {
        mixnorm_kernel<<<TKN, 256>>>(px, px0, rl, xl, l, pxn, xnh, xnl);

        // down = xn @ wd[l]  -> fp32 + split  (grid 32x5)
        launch_g<64, 0, false, true, true>({ xnh, xnl,
            wdh + (size_t)l * C_ * DOWN, wdl + (size_t)l * C_ * DOWN,
            pdown, dnh, dnl, TKN, DOWN, C_, C_, DOWN, DOWN });
        // kv = down[:, :256] @ wukv[l] -> fp32  (grid 32x12)
        launch_g<64, 0, false, false, true>({ dnh, dnl,
            ukh + (size_t)l * DC * KVW, ukl + (size_t)l * DC * KVW,
            pkv, nullptr, nullptr, TKN, KVW, DC, DOWN, KVW, KVW });
        // qraw = down[:, 256:512] @ wuq[l] -> fp32  (grid 32x8)
        launch_g<64, 0, false, false, true>({ dnh + DC, dnl + DC,
            uqh + (size_t)l * DC1 * C_, uql + (size_t)l * DC1 * C_,
            pqraw, nullptr, nullptr, TKN, C_, DC1, DOWN, C_, C_ });

        prep_kernel<<<TKN, 512>>>(pdown, pkv, pqraw, pxn, cosb, sinb,
                                  vg + (size_t)l * GC * H_,
                                  vetab + (size_t)l * VSZ * C_,
                                  idx, pq, pk, pv);

        attn_kernel<<<dim3(T_ / 64, B_ * H_), 256>>>(pq, pk, pv, yh, yl);

        // x += y @ attn_proj[l]  (grid 32x8)
        launch_g<64, 0, true, false, true>({ yh, yl,
            aph + (size_t)l * C_ * C_, apl + (size_t)l * C_ * C_,
            px, nullptr, nullptr, TKN, C_, C_, C_, C_, C_ });

        rmsnorm_kernel<<<TKN, 256>>>(px, pxn, xnh, xnl);

        // h = relu(xn @ fc[l])^2 -> split only  (grid 16x32)
        launch_g<128, 1, false, true, false>({ xnh, xnl,
            fch + (size_t)l * C_ * 4096, fcl + (size_t)l * C_ * 4096,
            nullptr, hhh, hhl, TKN, 4096, C_, C_, 4096, 4096 });
        // x += h @ proj[l]  (grid 32x8)
        launch_g<64, 0, true, false, true>({ hhh, hhl,
            pjh + (size_t)l * 4096 * C_, pjl + (size_t)l * 4096 * C_,
            px, nullptr, nullptr, TKN, C_, 4096, 4096, C_, C_ });
    }

    rmsnorm_kernel<<<TKN, 256>>>(px, pxn, xnh, xnl);
    // logits = softcap(xn @ lm_head)  (grid 16x250)
    launch_g<128, 2, false, false, true>({ xnh, xnl, lmh_h, lmh_l,
        out, nullptr, nullptr, TKN, VSZ, C_, C_, VSZ, VSZ });
}

// round 7
// speedup vs baseline: 3.2700x; 1.0906x over previous
#include <cuda_runtime.h>
#include <cuda_bf16.h>
#include <cuda_fp16.h>
#include <math.h>
#include <stdint.h>

// ---------------- problem constants ----------------
#define B_    2
#define T_    1024
#define C_    1024
#define H_    16
#define HD_   64
#define DC    256
#define DC1   256
#define DR    32
#define DN    32
#define DOWN  544
#define VSZ   32000
#define L_    4
#define GC    32
#define TKN   2048
#define KVW   1536
#define EPSF  1.1920929e-7f

// ---------------- fp32 scratch ----------------
__device__ float g_x   [TKN * C_];
__device__ float g_x0  [TKN * C_];
__device__ float g_xn  [TKN * C_];
__device__ float g_down[TKN * DOWN];
__device__ float g_kv  [TKN * KVW];
__device__ float g_qraw[TKN * C_];
__device__ float g_q   [B_ * H_ * T_ * HD_];
__device__ float g_k   [B_ * H_ * T_ * HD_];
__device__ float g_v   [B_ * H_ * T_ * HD_];

// ---------------- 16-bit hi/lo split buffers ----------------
__device__ __nv_bfloat16 s_wd_h  [L_ * C_ * DOWN],  s_wd_l  [L_ * C_ * DOWN];
__device__ __nv_bfloat16 s_wukv_h[L_ * DC * KVW],   s_wukv_l[L_ * DC * KVW];
__device__ __nv_bfloat16 s_wuq_h [L_ * DC1 * C_],   s_wuq_l [L_ * DC1 * C_];
__device__ __nv_bfloat16 s_ap_h  [L_ * C_ * C_],    s_ap_l  [L_ * C_ * C_];
__device__ __nv_bfloat16 s_fc_h  [L_ * C_ * 4096],  s_fc_l  [L_ * C_ * 4096];
__device__ __nv_bfloat16 s_pj_h  [L_ * 4096 * C_],  s_pj_l  [L_ * 4096 * C_];
__device__ __nv_bfloat16 s_lmh_h [C_ * VSZ];   // fp16 bits (hi only, 2-pass path)
__device__ __nv_bfloat16 s_xn_h  [TKN * C_],        s_xn_l  [TKN * C_];
__device__ __nv_bfloat16 s_dn_h  [TKN * DOWN],      s_dn_l  [TKN * DOWN];
__device__ __nv_bfloat16 s_h_h   [TKN * 4096],      s_h_l   [TKN * 4096];
__device__ __nv_bfloat16 s_y_h   [TKN * C_],        s_y_l   [TKN * C_];

// ================= helpers =================
__device__ __forceinline__ uint32_t smem_u32(const void* p) {
    uint32_t a;
    asm("{ .reg .u64 t; cvta.to.shared.u64 t, %1; cvt.u32.u64 %0, t; }" : "=r"(a) : "l"(p));
    return a;
}
__device__ __forceinline__ void ldsm_x4(uint32_t r[4], uint32_t addr) {
    asm volatile("ldmatrix.sync.aligned.m8n8.x4.shared.b16 {%0,%1,%2,%3}, [%4];"
        : "=r"(r[0]), "=r"(r[1]), "=r"(r[2]), "=r"(r[3]) : "r"(addr));
}
__device__ __forceinline__ void ldsm_x2t(uint32_t r[2], uint32_t addr) {
    asm volatile("ldmatrix.sync.aligned.m8n8.x2.trans.shared.b16 {%0,%1}, [%2];"
        : "=r"(r[0]), "=r"(r[1]) : "r"(addr));
}
__device__ __forceinline__ void mma_bf16(float c[4], const uint32_t a[4], const uint32_t b[2]) {
    asm volatile("mma.sync.aligned.m16n8k16.row.col.f32.bf16.bf16.f32 "
        "{%0,%1,%2,%3}, {%4,%5,%6,%7}, {%8,%9}, {%0,%1,%2,%3};"
        : "+f"(c[0]), "+f"(c[1]), "+f"(c[2]), "+f"(c[3])
        : "r"(a[0]), "r"(a[1]), "r"(a[2]), "r"(a[3]), "r"(b[0]), "r"(b[1]));
}
__device__ __forceinline__ void mma_f16(float c[4], const uint32_t a[4], const uint32_t b[2]) {
    asm volatile("mma.sync.aligned.m16n8k16.row.col.f32.f16.f16.f32 "
        "{%0,%1,%2,%3}, {%4,%5,%6,%7}, {%8,%9}, {%0,%1,%2,%3};"
        : "+f"(c[0]), "+f"(c[1]), "+f"(c[2]), "+f"(c[3])
        : "r"(a[0]), "r"(a[1]), "r"(a[2]), "r"(a[3]), "r"(b[0]), "r"(b[1]));
}
__device__ __forceinline__ void cp16(uint32_t dst, const void* src) {
    asm volatile("cp.async.cg.shared.global [%0], [%1], 16;" :: "r"(dst), "l"(src));
}
__device__ __forceinline__ void cp16z(uint32_t dst, const void* src, uint32_t ssize) {
    asm volatile("cp.async.cg.shared.global [%0], [%1], 16, %2;" :: "r"(dst), "l"(src), "r"(ssize));
}
#define CP_COMMIT() asm volatile("cp.async.commit_group;" ::: "memory")
#define CP_WAIT1()  asm volatile("cp.async.wait_group 1;" ::: "memory")
__device__ __forceinline__ uint32_t pack_bf2(__nv_bfloat16 a, __nv_bfloat16 b) {
    union { __nv_bfloat16 h[2]; uint32_t u; } u;
    u.h[0] = a; u.h[1] = b;
    return u.u;
}

// smem per stage: A_hi[TM][40] | A_lo | B_hi[32][136] | (B_lo if PASSES==3)
// PASSES==3: bf16 3-pass (Ah*Bh + Al*Bh + Ah*Bl)
// PASSES==2: fp16 2-pass (Ah*Bh + Al*Bh), B hi only
template<int TM, int PASSES, int EPI, bool ACC, bool WSPLIT, bool WF32>
__global__ __launch_bounds__(256, 2) void gemm_16(
    const __nv_bfloat16* __restrict__ Ah, const __nv_bfloat16* __restrict__ Al,
    const __nv_bfloat16* __restrict__ Bh, const __nv_bfloat16* __restrict__ Bl,
    float* __restrict__ C, __nv_bfloat16* __restrict__ Ch, __nv_bfloat16* __restrict__ Cl,
    int M, int N, int K, int lda, int ldb, int ldc)
{
    constexpr int MT     = TM / 32;
    constexpr int A_SZ   = TM * 80;
    constexpr int B_OFF  = 2 * A_SZ;
    constexpr int STRIDE = B_OFF + (PASSES == 3 ? 17408 : 8704);

    extern __shared__ char dsm[];
    uint32_t sraw = smem_u32(dsm);
    uint32_t s0 = (sraw + 127u) & ~127u;

    int tid = threadIdx.x, wid = tid >> 5, lane = tid & 31;
    int row0 = blockIdx.x * TM, col0 = blockIdx.y * 128;
    int wm = (wid >> 2) * (TM / 2);
    int wn = (wid & 3) * 32;

    float c[MT][4][4];
    #pragma unroll
    for (int mt = 0; mt < MT; mt++)
        #pragma unroll
        for (int nt = 0; nt < 4; nt++)
            #pragma unroll
            for (int r = 0; r < 4; r++) c[mt][nt][r] = 0.f;

    int NC = K >> 5;

    auto issue_copy = [&](int i, int stg) {
        int k0 = i << 5;
        uint32_t sb = s0 + (uint32_t)stg * STRIDE;
        #pragma unroll
        for (int e = tid; e < TM * 4; e += 256) {
            int r = e >> 2, seg = e & 3;
            uint32_t d = sb + (uint32_t)(r * 80 + seg * 16);
            cp16(d,                  Ah + (size_t)(row0 + r) * lda + k0 + seg * 8);
            cp16(d + (uint32_t)A_SZ, Al + (size_t)(row0 + r) * lda + k0 + seg * 8);
        }
        #pragma unroll
        for (int e0 = 0; e0 < 2; e0++) {
            int e = tid + e0 * 256;
            int kk = e >> 4, seg = e & 15;
            int gc = col0 + seg * 8;
            uint32_t d = sb + (uint32_t)B_OFF + (uint32_t)(kk * 272 + seg * 16);
            int rem = N - gc;
            uint32_t sz = rem >= 8 ? 16u : (rem > 0 ? (uint32_t)(rem * 2) : 0u);
            cp16z(d, Bh + (size_t)(k0 + kk) * ldb + gc, sz);
            if constexpr (PASSES == 3)
                cp16z(d + 8704u, Bl + (size_t)(k0 + kk) * ldb + gc, sz);
        }
    };

    auto mma_chunk = [&](int stg) {
        uint32_t base = s0 + (uint32_t)stg * STRIDE;
        int arow = wm + ((lane >> 3) & 1) * 8 + (lane & 7);
        int krow = lane & 15;
        #pragma unroll
        for (int kk = 0; kk < 32; kk += 16) {
            int acol = kk + ((lane >> 4) & 1) * 8;
            if constexpr (PASSES == 3) {
                uint32_t af[MT][4], bh[4][2], bl[4][2];
                #pragma unroll
                for (int mt = 0; mt < MT; mt++)
                    ldsm_x4(af[mt], base + (uint32_t)((arow + mt * 16) * 80 + acol * 2));
                #pragma unroll
                for (int nt = 0; nt < 4; nt++) {
                    uint32_t bd = base + (uint32_t)B_OFF + (uint32_t)((kk + krow) * 272 + (wn + nt * 8) * 2);
                    ldsm_x2t(bh[nt], bd);
                    ldsm_x2t(bl[nt], bd + 8704u);
                }
                #pragma unroll
                for (int mt = 0; mt < MT; mt++)
                    #pragma unroll
                    for (int nt = 0; nt < 4; nt++)
                        mma_bf16(c[mt][nt], af[mt], bh[nt]);
                #pragma unroll
                for (int mt = 0; mt < MT; mt++)
                    #pragma unroll
                    for (int nt = 0; nt < 4; nt++)
                        mma_bf16(c[mt][nt], af[mt], bl[nt]);
                #pragma unroll
                for (int mt = 0; mt < MT; mt++)
                    ldsm_x4(af[mt], base + (uint32_t)A_SZ + (uint32_t)((arow + mt * 16) * 80 + acol * 2));
                #pragma unroll
                for (int mt = 0; mt < MT; mt++)
                    #pragma unroll
                    for (int nt = 0; nt < 4; nt++)
                        mma_bf16(c[mt][nt], af[mt], bh[nt]);
            } else {
                uint32_t af[MT][4], bh[4][2];
                #pragma unroll
                for (int mt = 0; mt < MT; mt++)
                    ldsm_x4(af[mt], base + (uint32_t)((arow + mt * 16) * 80 + acol * 2));
                #pragma unroll
                for (int nt = 0; nt < 4; nt++)
                    ldsm_x2t(bh[nt], base + (uint32_t)B_OFF + (uint32_t)((kk + krow) * 272 + (wn + nt * 8) * 2));
                #pragma unroll
                for (int mt = 0; mt < MT; mt++)
                    #pragma unroll
                    for (int nt = 0; nt < 4; nt++)
                        mma_f16(c[mt][nt], af[mt], bh[nt]);
                #pragma unroll
                for (int mt = 0; mt < MT; mt++)
                    ldsm_x4(af[mt], base + (uint32_t)A_SZ + (uint32_t)((arow + mt * 16) * 80 + acol * 2));
                #pragma unroll
                for (int mt = 0; mt < MT; mt++)
                    #pragma unroll
                    for (int nt = 0; nt < 4; nt++)
                        mma_f16(c[mt][nt], af[mt], bh[nt]);
            }
        }
    };

    issue_copy(0, 0); CP_COMMIT();
    issue_copy(1, 1); CP_COMMIT();
    for (int i = 0; i < NC; i++) {
        CP_WAIT1();
        __syncthreads();
        mma_chunk(i % 3);
        if (i + 2 < NC) issue_copy(i + 2, (i + 2) % 3);
        CP_COMMIT();
    }

    // ---- epilogue ----
    #pragma unroll
    for (int mt = 0; mt < MT; mt++) {
        #pragma unroll
        for (int nt = 0; nt < 4; nt++) {
            #pragma unroll
            for (int half = 0; half < 2; half++) {
                int grow = row0 + wm + mt * 16 + (lane >> 2) + half * 8;
                int gcol = col0 + wn + nt * 8 + (lane & 3) * 2;
                float v0 = c[mt][nt][half * 2 + 0];
                float v1 = c[mt][nt][half * 2 + 1];
                if (EPI == 1) {
                    float h0 = fmaxf(v0, 0.f); v0 = h0 * h0;
                    float h1 = fmaxf(v1, 0.f); v1 = h1 * h1;
                }
                if (EPI == 2) {
                    v0 = 15.0f * tanhf(v0 * (1.0f / 15.0f));
                    v1 = 15.0f * tanhf(v1 * (1.0f / 15.0f));
                }
                if (gcol + 1 < N) {
                    size_t p = (size_t)grow * ldc + gcol;
                    if (ACC) { v0 += C[p]; v1 += C[p + 1]; }
                    if (WF32) *(float2*)(C + p) = make_float2(v0, v1);
                    if (WSPLIT) {
                        __nv_bfloat16 h0 = __float2bfloat16(v0);
                        __nv_bfloat16 h1 = __float2bfloat16(v1);
                        *(uint32_t*)(Ch + p) = pack_bf2(h0, h1);
                        *(uint32_t*)(Cl + p) = pack_bf2(
                            __float2bfloat16(v0 - __bfloat162float(h0)),
                            __float2bfloat16(v1 - __bfloat162float(h1)));
                    }
                } else if (gcol < N) {
                    size_t p = (size_t)grow * ldc + gcol;
                    if (ACC) v0 += C[p];
                    if (WF32) C[p] = v0;
                    if (WSPLIT) {
                        __nv_bfloat16 h0 = __float2bfloat16(v0);
                        Ch[p] = h0;
                        Cl[p] = __float2bfloat16(v0 - __bfloat162float(h0));
                    }
                }
            }
        }
    }
}

// ---------------- weight splits (ILP=4) ----------------
__global__ __launch_bounds__(256) void split_kernel(
    const float* __restrict__ src, __nv_bfloat16* __restrict__ hi,
    __nv_bfloat16* __restrict__ lo, int n4)
{
    int base = blockIdx.x * 1024 + threadIdx.x;
    float4 v[4]; bool ok[4];
    #pragma unroll
    for (int j = 0; j < 4; j++) {
        int i = base + j * 256;
        ok[j] = i < n4;
        if (ok[j]) v[j] = ((const float4*)src)[i];
    }
    #pragma unroll
    for (int j = 0; j < 4; j++) {
        if (!ok[j]) continue;
        int i = base + j * 256;
        float f[4] = { v[j].x, v[j].y, v[j].z, v[j].w };
        union { __nv_bfloat16 h[4]; uint2 u; } ph, pl;
        #pragma unroll
        for (int jj = 0; jj < 4; jj++) {
            __nv_bfloat16 hv = __float2bfloat16(f[jj]);
            ph.h[jj] = hv;
            pl.h[jj] = __float2bfloat16(f[jj] - __bfloat162float(hv));
        }
        ((uint2*)hi)[i] = ph.u;
        ((uint2*)lo)[i] = pl.u;
    }
}

// fp16 hi-only split (lm_head weights)
__global__ __launch_bounds__(256) void split16_kernel(
    const float* __restrict__ src, uint16_t* __restrict__ hi, int n4)
{
    int base = blockIdx.x * 1024 + threadIdx.x;
    float4 v[4]; bool ok[4];
    #pragma unroll
    for (int j = 0; j < 4; j++) {
        int i = base + j * 256;
        ok[j] = i < n4;
        if (ok[j]) v[j] = ((const float4*)src)[i];
    }
    #pragma unroll
    for (int j = 0; j < 4; j++) {
        if (!ok[j]) continue;
        int i = base + j * 256;
        float f[4] = { v[j].x, v[j].y, v[j].z, v[j].w };
        union { uint16_t h[4]; uint2 u; } ph;
        #pragma unroll
        for (int jj = 0; jj < 4; jj++)
            ph.h[jj] = __half_as_ushort(__float2half(f[jj]));
        ((uint2*)hi)[i] = ph.u;
    }
}

// ---------------- block reduce ----------------
__device__ __forceinline__ float blockReduceSum(float v) {
    __shared__ float red[32];
    int lane = threadIdx.x & 31, w = threadIdx.x >> 5;
    #pragma unroll
    for (int o = 16; o; o >>= 1) v += __shfl_xor_sync(0xffffffffu, v, o);
    if (lane == 0) red[w] = v;
    __syncthreads();
    v = (threadIdx.x < (blockDim.x >> 5)) ? red[threadIdx.x] : 0.0f;
    if (w == 0) {
        #pragma unroll
        for (int o = 16; o; o >>= 1) v += __shfl_xor_sync(0xffffffffu, v, o);
        if (lane == 0) red[0] = v;
    }
    __syncthreads();
    return red[0];
}

// ---------------- embed + norms ----------------
__global__ __launch_bounds__(256) void embed_kernel(
    const int* __restrict__ idx, const float* __restrict__ wte,
    float* __restrict__ x, float* __restrict__ x0)
{
    int i = blockIdx.x;
    const float* row = wte + (size_t)idx[i] * C_;
    float v[4]; float ss = 0.f;
    #pragma unroll
    for (int j = 0; j < 4; j++) { v[j] = row[threadIdx.x + j * 256]; ss += v[j] * v[j]; }
    ss = blockReduceSum(ss);
    float sc = rsqrtf(ss / C_ + EPSF);
    #pragma unroll
    for (int j = 0; j < 4; j++) {
        float o = v[j] * sc;
        x [(size_t)i * C_ + threadIdx.x + j * 256] = o;
        x0[(size_t)i * C_ + threadIdx.x + j * 256] = o;
    }
}

__global__ __launch_bounds__(256) void mixnorm_kernel(
    float* __restrict__ x, const float* __restrict__ x0,
    const float* __restrict__ rl, const float* __restrict__ xl, int l,
    float* __restrict__ xn, __nv_bfloat16* __restrict__ xnh, __nv_bfloat16* __restrict__ xnl)
{
    int i = blockIdx.x;
    float a = rl[l], bc = xl[l];
    float v[4]; float ss = 0.f;
    #pragma unroll
    for (int j = 0; j < 4; j++) {
        size_t p = (size_t)i * C_ + threadIdx.x + j * 256;
        v[j] = a * x[p] + bc * x0[p];
        ss += v[j] * v[j];
    }
    ss = blockReduceSum(ss);
    float sc = rsqrtf(ss / C_ + EPSF);
    #pragma unroll
    for (int j = 0; j < 4; j++) {
        size_t p = (size_t)i * C_ + threadIdx.x + j * 256;
        float o = v[j] * sc;
        x[p] = v[j];
        xn[p] = o;
        __nv_bfloat16 hv = __float2bfloat16(o);
        xnh[p] = hv;
        xnl[p] = __float2bfloat16(o - __bfloat162float(hv));
    }
}

__global__ __launch_bounds__(256) void rmsnorm_kernel(
    const float* __restrict__ x, float* __restrict__ xn,
    __nv_bfloat16* __restrict__ xnh, __nv_bfloat16* __restrict__ xnl)
{
    int i = blockIdx.x;
    float v[4]; float ss = 0.f;
    #pragma unroll
    for (int j = 0; j < 4; j++) {
        v[j] = x[(size_t)i * C_ + threadIdx.x + j * 256];
        ss += v[j] * v[j];
    }
    ss = blockReduceSum(ss);
    float sc = rsqrtf(ss / C_ + EPSF);
    #pragma unroll
    for (int j = 0; j < 4; j++) {
        size_t p = (size_t)i * C_ + threadIdx.x + j * 256;
        float o = v[j] * sc;
        xn[p] = o;
        __nv_bfloat16 hv = __float2bfloat16(o);
        xnh[p] = hv;
        xnl[p] = __float2bfloat16(o - __bfloat162float(hv));
    }
}

// final rmsnorm -> fp16 hi/lo (feeds 2-pass lm_head)
__global__ __launch_bounds__(256) void rmsnorm16_kernel(
    const float* __restrict__ x, uint16_t* __restrict__ xnh, uint16_t* __restrict__ xnl)
{
    int i = blockIdx.x;
    float v[4]; float ss = 0.f;
    #pragma unroll
    for (int j = 0; j < 4; j++) {
        v[j] = x[(size_t)i * C_ + threadIdx.x + j * 256];
        ss += v[j] * v[j];
    }
    ss = blockReduceSum(ss);
    float sc = rsqrtf(ss / C_ + EPSF);
    #pragma unroll
    for (int j = 0; j < 4; j++) {
        size_t p = (size_t)i * C_ + threadIdx.x + j * 256;
        float o = v[j] * sc;
        __half hv = __float2half(o);
        xnh[p] = __half_as_ushort(hv);
        xnl[p] = __half_as_ushort(__float2half(o - __half2float(hv)));
    }
}

// ---------------- per-token q/k/v assembly ----------------
__global__ __launch_bounds__(512) void prep_kernel(
    const float* __restrict__ down, const float* __restrict__ kvb,
    const float* __restrict__ qraw, const float* __restrict__ xn,
    const float* __restrict__ cosb, const float* __restrict__ sinb,
    const float* __restrict__ vg, const float* __restrict__ vetab,
    const int* __restrict__ idx,
    float* __restrict__ Q, float* __restrict__ K, float* __restrict__ V)
{
    int i = blockIdx.x;
    int b = i / T_, t = i % T_;
    int w = threadIdx.x >> 5, lane = threadIdx.x & 31;
    __shared__ float cs[16], sn[16], kr[32];

    if (threadIdx.x < 16)       cs[threadIdx.x]      = cosb[(size_t)i * 16 + threadIdx.x];
    else if (threadIdx.x < 32)  sn[threadIdx.x - 16] = sinb[(size_t)i * 16 + threadIdx.x - 16];
    __syncthreads();

    float gv = xn[(size_t)i * C_ + lane] * vg[lane * H_ + w];
    #pragma unroll
    for (int o = 16; o; o >>= 1) gv += __shfl_xor_sync(0xffffffffu, gv, o);
    float gate = 2.0f / (1.0f + expf(-gv));

    if (w == 0) {
        int j = lane & 15;
        float x1 = down[(size_t)i * DOWN + 512 + j];
        float x2 = down[(size_t)i * DOWN + 528 + j];
        float cc = cs[j], ssn = sn[j];
        kr[lane] = (lane < 16) ? (x1 * cc + x2 * ssn) : (-x1 * ssn + x2 * cc);
    }
    __syncthreads();

    const float* kvrow = kvb  + (size_t)i * KVW + w * 96;
    const float* qrow  = qraw + (size_t)i * C_  + w * 64;
    const float* verow = vetab + (size_t)idx[i] * C_ + w * 64;

    float k0v = kvrow[lane];
    float k1v = kr[lane];
    float q0v = qrow[lane];
    float q1v;
    {
        int j = lane & 15;
        float a = qrow[32 + j], bb = qrow[48 + j];
        float cc = cs[j], ssn = sn[j];
        q1v = (lane < 16) ? (a * cc + bb * ssn) : (-a * ssn + bb * cc);
    }
    float v0 = kvrow[32 + lane] + gate * verow[lane];
    float v1 = kvrow[64 + lane] + gate * verow[32 + lane];

    float kss = k0v * k0v + k1v * k1v;
    float qss = q0v * q0v + q1v * q1v;
    #pragma unroll
    for (int o = 16; o; o >>= 1) {
        kss += __shfl_xor_sync(0xffffffffu, kss, o);
        qss += __shfl_xor_sync(0xffffffffu, qss, o);
    }
    float ksc = rsqrtf(kss * (1.0f / 64.0f) + EPSF);
    float qsc = rsqrtf(qss * (1.0f / 64.0f) + EPSF);

    size_t base = ((size_t)(b * H_ + w) * T_ + t) * 64;
    K[base + lane]      = k0v * ksc;
    K[base + 32 + lane] = k1v * ksc;
    Q[base + lane]      = q0v * qsc;
    Q[base + 32 + lane] = q1v * qsc;
    V[base + lane]      = v0;
    V[base + 32 + lane] = v1;
}

// ---------------- flash attention (fp32, causal) -> bf16 split output ----------------
__global__ __launch_bounds__(256) void attn_kernel(
    const float* __restrict__ Q, const float* __restrict__ Kt,
    const float* __restrict__ Vt,
    __nv_bfloat16* __restrict__ Yh, __nv_bfloat16* __restrict__ Yl)
{
    int qt0 = blockIdx.x * 64;
    int bh  = blockIdx.y;
    int b = bh >> 4, h = bh & 15;
    const float* Qb = Q  + (size_t)bh * T_ * 64;
    const float* Kb = Kt + (size_t)bh * T_ * 64;
    const float* Vb = Vt + (size_t)bh * T_ * 64;

    __shared__ float qs[64][65];
    __shared__ float ks[32][65];
    __shared__ float vs[32][68];
    __shared__ float ps[64][33];

    int tid = threadIdx.x;
    int tr = tid >> 4, tc = tid & 15;

    for (int e = tid; e < 64 * 64; e += 256) {
        int r = e >> 6, c = e & 63;
        qs[r][c] = Qb[(size_t)(qt0 + r) * 64 + c];
    }
    float m[4], l[4], o[4][4];
    #pragma unroll
    for (int mm = 0; mm < 4; mm++) {
        m[mm] = -1e30f; l[mm] = 0.f;
        #pragma unroll
        for (int nn = 0; nn < 4; nn++) o[mm][nn] = 0.f;
    }
    __syncthreads();

    for (int kt0 = 0; kt0 < qt0 + 64; kt0 += 32) {
        for (int e = tid; e < 32 * 64; e += 256) {
            int r = e >> 6, c = e & 63;
            ks[r][c] = Kb[(size_t)(kt0 + r) * 64 + c];
            vs[r][c] = Vb[(size_t)(kt0 + r) * 64 + c];
        }
        __syncthreads();

        float s[4][2];
        #pragma unroll
        for (int mm = 0; mm < 4; mm++) { s[mm][0] = 0.f; s[mm][1] = 0.f; }
        #pragma unroll
        for (int d = 0; d < 64; d++) {
            float a[4], bb[2];
            #pragma unroll
            for (int mm = 0; mm < 4; mm++) a[mm] = qs[tr * 4 + mm][d];
            #pragma unroll
            for (int nn = 0; nn < 2; nn++) bb[nn] = ks[tc * 2 + nn][d];
            #pragma unroll
            for (int mm = 0; mm < 4; mm++)
                #pragma unroll
                for (int nn = 0; nn < 2; nn++)
                    s[mm][nn] = fmaf(a[mm], bb[nn], s[mm][nn]);
        }
        bool edge = (kt0 + 32 > qt0);
        #pragma unroll
        for (int mm = 0; mm < 4; mm++)
            #pragma unroll
            for (int nn = 0; nn < 2; nn++) {
                s[mm][nn] *= 0.125f;
                if (edge) {
                    int qg = qt0 + tr * 4 + mm, kg = kt0 + tc * 2 + nn;
                    if (kg > qg) s[mm][nn] = -1e30f;
                }
            }
        #pragma unroll
        for (int mm = 0; mm < 4; mm++) {
            float rmax = fmaxf(s[mm][0], s[mm][1]);
            #pragma unroll
            for (int off = 1; off < 16; off <<= 1)
                rmax = fmaxf(rmax, __shfl_xor_sync(0xffffffffu, rmax, off));
            float mn = fmaxf(m[mm], rmax);
            float corr = expf(m[mm] - mn);
            float p0 = expf(s[mm][0] - mn);
            float p1 = expf(s[mm][1] - mn);
            float rs = p0 + p1;
            #pragma unroll
            for (int off = 1; off < 16; off <<= 1)
                rs += __shfl_xor_sync(0xffffffffu, rs, off);
            l[mm] = l[mm] * corr + rs;
            m[mm] = mn;
            ps[tr * 4 + mm][tc * 2 + 0] = p0;
            ps[tr * 4 + mm][tc * 2 + 1] = p1;
            #pragma unroll
            for (int nn = 0; nn < 4; nn++) o[mm][nn] *= corr;
        }
        __syncthreads();
        #pragma unroll
        for (int k = 0; k < 32; k++) {
            float pv[4], vv[4];
            #pragma unroll
            for (int mm = 0; mm < 4; mm++) pv[mm] = ps[tr * 4 + mm][k];
            #pragma unroll
            for (int nn = 0; nn < 4; nn++) vv[nn] = vs[k][tc * 4 + nn];
            #pragma unroll
            for (int mm = 0; mm < 4; mm++)
                #pragma unroll
                for (int nn = 0; nn < 4; nn++)
                    o[mm][nn] = fmaf(pv[mm], vv[nn], o[mm][nn]);
        }
        __syncthreads();
    }
    #pragma unroll
    for (int mm = 0; mm < 4; mm++) {
        int q = qt0 + tr * 4 + mm;
        float inv = 1.0f / l[mm];
        #pragma unroll
        for (int nn = 0; nn < 4; nn += 2) {
            size_t p = ((size_t)(b * T_ + q)) * C_ + h * 64 + tc * 4 + nn;
            float v0 = o[mm][nn] * inv, v1 = o[mm][nn + 1] * inv;
            __nv_bfloat16 h0 = __float2bfloat16(v0);
            __nv_bfloat16 h1 = __float2bfloat16(v1);
            *(uint32_t*)(Yh + p) = pack_bf2(h0, h1);
            *(uint32_t*)(Yl + p) = pack_bf2(
                __float2bfloat16(v0 - __bfloat162float(h0)),
                __float2bfloat16(v1 - __bfloat162float(h1)));
        }
    }
}

// ---------------- host side ----------------
template<typename Tp>
static Tp* sym_addr(const void* sym) {
    void* p = nullptr;
    cudaGetSymbolAddress(&p, sym);
    return (Tp*)p;
}
typedef __nv_bfloat16 bf;

struct GemmArgs {
    const bf *Ah, *Al, *Bh, *Bl;
    float* C; bf *Ch, *Cl;
    int M, N, K, lda, ldb, ldc;
};

template<int TM, int PASSES, int EPI, bool ACC, bool WSPLIT, bool WF32>
static void launch_g(const GemmArgs& a) {
    constexpr int STRIDE = (2 * TM * 80) + (PASSES == 3 ? 17408 : 8704);
    constexpr int DSMEM  = 3 * STRIDE + 128;
    static bool done = false;
    if (!done) {
        cudaFuncSetAttribute(gemm_16<TM, PASSES, EPI, ACC, WSPLIT, WF32>,
                             cudaFuncAttributeMaxDynamicSharedMemorySize, DSMEM);
        done = true;
    }
    dim3 grid(a.M / TM, (a.N + 127) / 128);
    gemm_16<TM, PASSES, EPI, ACC, WSPLIT, WF32><<<grid, 256, DSMEM>>>(
        a.Ah, a.Al, a.Bh, a.Bl, a.C, a.Ch, a.Cl, a.M, a.N, a.K, a.lda, a.ldb, a.ldc);
}

static void split_w(const float* src, bf* hi, bf* lo, size_t n) {
    int n4 = (int)(n / 4);
    split_kernel<<<(n4 + 1023) / 1024, 256>>>(src, hi, lo, n4);
}

extern "C" void kernel_launch(void* const* d_in, const int* in_sizes, int n_in,
                              void* d_out, int out_size)
{
    (void)in_sizes; (void)n_in; (void)out_size;
    const int*   idx   = (const int*)  d_in[0];
    const float* cosb  = (const float*)d_in[1];
    const float* sinb  = (const float*)d_in[2];
    const float* wte   = (const float*)d_in[3];
    const float* vetab = (const float*)d_in[4];
    const float* wd    = (const float*)d_in[5];
    const float* wukv  = (const float*)d_in[6];
    const float* wuq   = (const float*)d_in[7];
    const float* vg    = (const float*)d_in[8];
    const float* ap    = (const float*)d_in[9];
    const float* fc    = (const float*)d_in[10];
    const float* pj    = (const float*)d_in[11];
    const float* rl    = (const float*)d_in[12];
    const float* xl    = (const float*)d_in[13];
    const float* lmh   = (const float*)d_in[14];
    float* out = (float*)d_out;

    float* px    = sym_addr<float>(g_x);
    float* px0   = sym_addr<float>(g_x0);
    float* pxn   = sym_addr<float>(g_xn);
    float* pdown = sym_addr<float>(g_down);
    float* pkv   = sym_addr<float>(g_kv);
    float* pqraw = sym_addr<float>(g_qraw);
    float* pq    = sym_addr<float>(g_q);
    float* pk    = sym_addr<float>(g_k);
    float* pv    = sym_addr<float>(g_v);

    bf *wdh = sym_addr<bf>(s_wd_h),   *wdl = sym_addr<bf>(s_wd_l);
    bf *ukh = sym_addr<bf>(s_wukv_h), *ukl = sym_addr<bf>(s_wukv_l);
    bf *uqh = sym_addr<bf>(s_wuq_h),  *uql = sym_addr<bf>(s_wuq_l);
    bf *aph = sym_addr<bf>(s_ap_h),   *apl = sym_addr<bf>(s_ap_l);
    bf *fch = sym_addr<bf>(s_fc_h),   *fcl = sym_addr<bf>(s_fc_l);
    bf *pjh = sym_addr<bf>(s_pj_h),   *pjl = sym_addr<bf>(s_pj_l);
    bf *lmh_h = sym_addr<bf>(s_lmh_h);
    bf *xnh = sym_addr<bf>(s_xn_h),   *xnl = sym_addr<bf>(s_xn_l);
    bf *dnh = sym_addr<bf>(s_dn_h),   *dnl = sym_addr<bf>(s_dn_l);
    bf *hhh = sym_addr<bf>(s_h_h),    *hhl = sym_addr<bf>(s_h_l);
    bf *yh  = sym_addr<bf>(s_y_h),    *yl  = sym_addr<bf>(s_y_l);

    // weight splits (once per call)
    split_w(wd,   wdh, wdl, (size_t)L_ * C_ * DOWN);
    split_w(wukv, ukh, ukl, (size_t)L_ * DC * KVW);
    split_w(wuq,  uqh, uql, (size_t)L_ * DC1 * C_);
    split_w(ap,   aph, apl, (size_t)L_ * C_ * C_);
    split_w(fc,   fch, fcl, (size_t)L_ * C_ * 4096);
    split_w(pj,   pjh, pjl, (size_t)L_ * 4096 * C_);
    {   // lm_head: fp16 hi only (2-pass path)
        int n4 = (int)((size_t)C_ * VSZ / 4);
        split16_kernel<<<(n4 + 1023) / 1024, 256>>>(lmh, (uint16_t*)lmh_h, n4);
    }

    embed_kernel<<<TKN, 256>>>(idx, wte, px, px0);

    for (int l = 0; l < L_; l++) {
        mixnorm_kernel<<<TKN, 256>>>(px, px0, rl, xl, l, pxn, xnh, xnl);

        // down = xn @ wd[l]  -> fp32 + split
        launch_g<64, 3, 0, false, true, true>({ xnh, xnl,
            wdh + (size_t)l * C_ * DOWN, wdl + (size_t)l * C_ * DOWN,
            pdown, dnh, dnl, TKN, DOWN, C_, C_, DOWN, DOWN });
        // kv = down[:, :256] @ wukv[l] -> fp32
        launch_g<64, 3, 0, false, false, true>({ dnh, dnl,
            ukh + (size_t)l * DC * KVW, ukl + (size_t)l * DC * KVW,
            pkv, nullptr, nullptr, TKN, KVW, DC, DOWN, KVW, KVW });
        // qraw = down[:, 256:512] @ wuq[l] -> fp32
        launch_g<64, 3, 0, false, false, true>({ dnh + DC, dnl + DC,
            uqh + (size_t)l * DC1 * C_, uql + (size_t)l * DC1 * C_,
            pqraw, nullptr, nullptr, TKN, C_, DC1, DOWN, C_, C_ });

        prep_kernel<<<TKN, 512>>>(pdown, pkv, pqraw, pxn, cosb, sinb,
                                  vg + (size_t)l * GC * H_,
                                  vetab + (size_t)l * VSZ * C_,
                                  idx, pq, pk, pv);

        attn_kernel<<<dim3(T_ / 64, B_ * H_), 256>>>(pq, pk, pv, yh, yl);

        // x += y @ attn_proj[l]
        launch_g<64, 3, 0, true, false, true>({ yh, yl,
            aph + (size_t)l * C_ * C_, apl + (size_t)l * C_ * C_,
            px, nullptr, nullptr, TKN, C_, C_, C_, C_, C_ });

        rmsnorm_kernel<<<TKN, 256>>>(px, pxn, xnh, xnl);

        // h = relu(xn @ fc[l])^2 -> split only
        launch_g<128, 3, 1, false, true, false>({ xnh, xnl,
            fch + (size_t)l * C_ * 4096, fcl + (size_t)l * C_ * 4096,
            nullptr, hhh, hhl, TKN, 4096, C_, C_, 4096, 4096 });
        // x += h @ proj[l]
        launch_g<64, 3, 0, true, false, true>({ hhh, hhl,
            pjh + (size_t)l * 4096 * C_, pjl + (size_t)l * 4096 * C_,
            px, nullptr, nullptr, TKN, C_, 4096, 4096, C_, C_ });
    }

    // final rmsnorm -> fp16 hi/lo (reuse xn split buffers as fp16 storage)
    rmsnorm16_kernel<<<TKN, 256>>>(px, (uint16_t*)xnh, (uint16_t*)xnl);
    // logits = softcap(xn @ lm_head)  — fp16 2-pass, B hi only
    launch_g<128, 2, 2, false, false, true>({ xnh, xnl, lmh_h, nullptr,
        out, nullptr, nullptr, TKN, VSZ, C_, C_, VSZ, VSZ });
}

// round 9
// speedup vs baseline: 3.6882x; 1.1279x over previous
#include <cuda_runtime.h>
#include <cuda_bf16.h>
#include <cuda_fp16.h>
#include <math.h>
#include <stdint.h>

// ---------------- problem constants ----------------
#define B_    2
#define T_    1024
#define C_    1024
#define H_    16
#define HD_   64
#define DC    256
#define DC1   256
#define DR    32
#define DN    32
#define DOWN  544
#define VSZ   32000
#define L_    4
#define GC    32
#define TKN   2048
#define KVW   1536
#define EPSF  1.1920929e-7f

// ---------------- fp32 scratch ----------------
__device__ float g_x   [TKN * C_];
__device__ float g_x0  [TKN * C_];
__device__ float g_xn  [TKN * C_];
__device__ float g_down[TKN * DOWN];
__device__ float g_kv  [TKN * KVW];
__device__ float g_qraw[TKN * C_];
__device__ float g_q   [B_ * H_ * T_ * HD_];
__device__ float g_k   [B_ * H_ * T_ * HD_];
__device__ float g_v   [B_ * H_ * T_ * HD_];

// ---------------- 16-bit hi/lo split buffers ----------------
__device__ __nv_bfloat16 s_wd_h  [L_ * C_ * DOWN],  s_wd_l  [L_ * C_ * DOWN];
__device__ __nv_bfloat16 s_wukv_h[L_ * DC * KVW],   s_wukv_l[L_ * DC * KVW];
__device__ __nv_bfloat16 s_wuq_h [L_ * DC1 * C_],   s_wuq_l [L_ * DC1 * C_];
__device__ __nv_bfloat16 s_ap_h  [L_ * C_ * C_],    s_ap_l  [L_ * C_ * C_];
__device__ __nv_bfloat16 s_fc_h  [L_ * C_ * 4096];  // fp16 bits (hi only)
__device__ __nv_bfloat16 s_pj_h  [L_ * 4096 * C_];  // fp16 bits (hi only)
__device__ __nv_bfloat16 s_lmh_h [C_ * VSZ];        // fp16 bits (hi only)
__device__ __nv_bfloat16 s_xn_h  [TKN * C_],        s_xn_l  [TKN * C_];   // bf16 (mixnorm) or fp16 (rmsnorm)
__device__ __nv_bfloat16 s_dn_h  [TKN * DOWN],      s_dn_l  [TKN * DOWN];
__device__ __nv_bfloat16 s_h_h   [TKN * 4096],      s_h_l   [TKN * 4096]; // fp16 bits
__device__ __nv_bfloat16 s_y_h   [TKN * C_],        s_y_l   [TKN * C_];

// ================= helpers =================
__device__ __forceinline__ uint32_t smem_u32(const void* p) {
    uint32_t a;
    asm("{ .reg .u64 t; cvta.to.shared.u64 t, %1; cvt.u32.u64 %0, t; }" : "=r"(a) : "l"(p));
    return a;
}
__device__ __forceinline__ void ldsm_x4(uint32_t r[4], uint32_t addr) {
    asm volatile("ldmatrix.sync.aligned.m8n8.x4.shared.b16 {%0,%1,%2,%3}, [%4];"
        : "=r"(r[0]), "=r"(r[1]), "=r"(r[2]), "=r"(r[3]) : "r"(addr));
}
__device__ __forceinline__ void ldsm_x2t(uint32_t r[2], uint32_t addr) {
    asm volatile("ldmatrix.sync.aligned.m8n8.x2.trans.shared.b16 {%0,%1}, [%2];"
        : "=r"(r[0]), "=r"(r[1]) : "r"(addr));
}
__device__ __forceinline__ void mma_bf16(float c[4], const uint32_t a[4], const uint32_t b[2]) {
    asm volatile("mma.sync.aligned.m16n8k16.row.col.f32.bf16.bf16.f32 "
        "{%0,%1,%2,%3}, {%4,%5,%6,%7}, {%8,%9}, {%0,%1,%2,%3};"
        : "+f"(c[0]), "+f"(c[1]), "+f"(c[2]), "+f"(c[3])
        : "r"(a[0]), "r"(a[1]), "r"(a[2]), "r"(a[3]), "r"(b[0]), "r"(b[1]));
}
__device__ __forceinline__ void mma_f16(float c[4], const uint32_t a[4], const uint32_t b[2]) {
    asm volatile("mma.sync.aligned.m16n8k16.row.col.f32.f16.f16.f32 "
        "{%0,%1,%2,%3}, {%4,%5,%6,%7}, {%8,%9}, {%0,%1,%2,%3};"
        : "+f"(c[0]), "+f"(c[1]), "+f"(c[2]), "+f"(c[3])
        : "r"(a[0]), "r"(a[1]), "r"(a[2]), "r"(a[3]), "r"(b[0]), "r"(b[1]));
}
__device__ __forceinline__ void cp16(uint32_t dst, const void* src) {
    asm volatile("cp.async.cg.shared.global [%0], [%1], 16;" :: "r"(dst), "l"(src));
}
__device__ __forceinline__ void cp16z(uint32_t dst, const void* src, uint32_t ssize) {
    asm volatile("cp.async.cg.shared.global [%0], [%1], 16, %2;" :: "r"(dst), "l"(src), "r"(ssize));
}
#define CP_COMMIT() asm volatile("cp.async.commit_group;" ::: "memory")
#define CP_WAIT1()  asm volatile("cp.async.wait_group 1;" ::: "memory")
__device__ __forceinline__ uint32_t pack_bf2(__nv_bfloat16 a, __nv_bfloat16 b) {
    union { __nv_bfloat16 h[2]; uint32_t u; } u;
    u.h[0] = a; u.h[1] = b;
    return u.u;
}
__device__ __forceinline__ uint32_t pack_h2(__half a, __half b) {
    union { __half h[2]; uint32_t u; } u;
    u.h[0] = a; u.h[1] = b;
    return u.u;
}

// smem per stage: A_hi[TM][40] | A_lo | B_hi[32][136] | (B_lo if PASSES==3)
// PASSES==3: bf16 3-pass (Ah*Bh + Al*Bh + Ah*Bl)
// PASSES==2: fp16 2-pass (Ah*Bh + Al*Bh), B hi only
// S16: WSPLIT output written as fp16 hi/lo (else bf16 hi/lo)
template<int TM, int PASSES, int EPI, bool ACC, bool WSPLIT, bool WF32, bool S16>
__global__ __launch_bounds__(256, 2) void gemm_16(
    const __nv_bfloat16* __restrict__ Ah, const __nv_bfloat16* __restrict__ Al,
    const __nv_bfloat16* __restrict__ Bh, const __nv_bfloat16* __restrict__ Bl,
    float* __restrict__ C, __nv_bfloat16* __restrict__ Ch, __nv_bfloat16* __restrict__ Cl,
    int M, int N, int K, int lda, int ldb, int ldc)
{
    constexpr int MT     = TM / 32;
    constexpr int A_SZ   = TM * 80;
    constexpr int B_OFF  = 2 * A_SZ;
    constexpr int STRIDE = B_OFF + (PASSES == 3 ? 17408 : 8704);

    extern __shared__ char dsm[];
    uint32_t sraw = smem_u32(dsm);
    uint32_t s0 = (sraw + 127u) & ~127u;

    int tid = threadIdx.x, wid = tid >> 5, lane = tid & 31;
    int row0 = blockIdx.x * TM, col0 = blockIdx.y * 128;
    int wm = (wid >> 2) * (TM / 2);
    int wn = (wid & 3) * 32;

    float c[MT][4][4];
    #pragma unroll
    for (int mt = 0; mt < MT; mt++)
        #pragma unroll
        for (int nt = 0; nt < 4; nt++)
            #pragma unroll
            for (int r = 0; r < 4; r++) c[mt][nt][r] = 0.f;

    int NC = K >> 5;

    auto issue_copy = [&](int i, int stg) {
        int k0 = i << 5;
        uint32_t sb = s0 + (uint32_t)stg * STRIDE;
        #pragma unroll
        for (int e = tid; e < TM * 4; e += 256) {
            int r = e >> 2, seg = e & 3;
            uint32_t d = sb + (uint32_t)(r * 80 + seg * 16);
            cp16(d,                  Ah + (size_t)(row0 + r) * lda + k0 + seg * 8);
            cp16(d + (uint32_t)A_SZ, Al + (size_t)(row0 + r) * lda + k0 + seg * 8);
        }
        #pragma unroll
        for (int e0 = 0; e0 < 2; e0++) {
            int e = tid + e0 * 256;
            int kk = e >> 4, seg = e & 15;
            int gc = col0 + seg * 8;
            uint32_t d = sb + (uint32_t)B_OFF + (uint32_t)(kk * 272 + seg * 16);
            int rem = N - gc;
            uint32_t sz = rem >= 8 ? 16u : (rem > 0 ? (uint32_t)(rem * 2) : 0u);
            cp16z(d, Bh + (size_t)(k0 + kk) * ldb + gc, sz);
            if constexpr (PASSES == 3)
                cp16z(d + 8704u, Bl + (size_t)(k0 + kk) * ldb + gc, sz);
        }
    };

    auto mma_chunk = [&](int stg) {
        uint32_t base = s0 + (uint32_t)stg * STRIDE;
        int arow = wm + ((lane >> 3) & 1) * 8 + (lane & 7);
        int krow = lane & 15;
        #pragma unroll
        for (int kk = 0; kk < 32; kk += 16) {
            int acol = kk + ((lane >> 4) & 1) * 8;
            if constexpr (PASSES == 3) {
                uint32_t af[MT][4], bh[4][2], bl[4][2];
                #pragma unroll
                for (int mt = 0; mt < MT; mt++)
                    ldsm_x4(af[mt], base + (uint32_t)((arow + mt * 16) * 80 + acol * 2));
                #pragma unroll
                for (int nt = 0; nt < 4; nt++) {
                    uint32_t bd = base + (uint32_t)B_OFF + (uint32_t)((kk + krow) * 272 + (wn + nt * 8) * 2);
                    ldsm_x2t(bh[nt], bd);
                    ldsm_x2t(bl[nt], bd + 8704u);
                }
                #pragma unroll
                for (int mt = 0; mt < MT; mt++)
                    #pragma unroll
                    for (int nt = 0; nt < 4; nt++)
                        mma_bf16(c[mt][nt], af[mt], bh[nt]);
                #pragma unroll
                for (int mt = 0; mt < MT; mt++)
                    #pragma unroll
                    for (int nt = 0; nt < 4; nt++)
                        mma_bf16(c[mt][nt], af[mt], bl[nt]);
                #pragma unroll
                for (int mt = 0; mt < MT; mt++)
                    ldsm_x4(af[mt], base + (uint32_t)A_SZ + (uint32_t)((arow + mt * 16) * 80 + acol * 2));
                #pragma unroll
                for (int mt = 0; mt < MT; mt++)
                    #pragma unroll
                    for (int nt = 0; nt < 4; nt++)
                        mma_bf16(c[mt][nt], af[mt], bh[nt]);
            } else {
                uint32_t af[MT][4], bh[4][2];
                #pragma unroll
                for (int mt = 0; mt < MT; mt++)
                    ldsm_x4(af[mt], base + (uint32_t)((arow + mt * 16) * 80 + acol * 2));
                #pragma unroll
                for (int nt = 0; nt < 4; nt++)
                    ldsm_x2t(bh[nt], base + (uint32_t)B_OFF + (uint32_t)((kk + krow) * 272 + (wn + nt * 8) * 2));
                #pragma unroll
                for (int mt = 0; mt < MT; mt++)
                    #pragma unroll
                    for (int nt = 0; nt < 4; nt++)
                        mma_f16(c[mt][nt], af[mt], bh[nt]);
                #pragma unroll
                for (int mt = 0; mt < MT; mt++)
                    ldsm_x4(af[mt], base + (uint32_t)A_SZ + (uint32_t)((arow + mt * 16) * 80 + acol * 2));
                #pragma unroll
                for (int mt = 0; mt < MT; mt++)
                    #pragma unroll
                    for (int nt = 0; nt < 4; nt++)
                        mma_f16(c[mt][nt], af[mt], bh[nt]);
            }
        }
    };

    issue_copy(0, 0); CP_COMMIT();
    issue_copy(1, 1); CP_COMMIT();
    for (int i = 0; i < NC; i++) {
        CP_WAIT1();
        __syncthreads();
        mma_chunk(i % 3);
        if (i + 2 < NC) issue_copy(i + 2, (i + 2) % 3);
        CP_COMMIT();
    }

    // ---- epilogue ----
    #pragma unroll
    for (int mt = 0; mt < MT; mt++) {
        #pragma unroll
        for (int nt = 0; nt < 4; nt++) {
            #pragma unroll
            for (int half = 0; half < 2; half++) {
                int grow = row0 + wm + mt * 16 + (lane >> 2) + half * 8;
                int gcol = col0 + wn + nt * 8 + (lane & 3) * 2;
                float v0 = c[mt][nt][half * 2 + 0];
                float v1 = c[mt][nt][half * 2 + 1];
                if (EPI == 1) {
                    float h0 = fmaxf(v0, 0.f); v0 = h0 * h0;
                    float h1 = fmaxf(v1, 0.f); v1 = h1 * h1;
                }
                if (EPI == 2) {
                    v0 = 15.0f * tanhf(v0 * (1.0f / 15.0f));
                    v1 = 15.0f * tanhf(v1 * (1.0f / 15.0f));
                }
                if (gcol + 1 < N) {
                    size_t p = (size_t)grow * ldc + gcol;
                    if (ACC) { v0 += C[p]; v1 += C[p + 1]; }
                    if (WF32) *(float2*)(C + p) = make_float2(v0, v1);
                    if (WSPLIT) {
                        if (S16) {
                            __half h0 = __float2half(v0);
                            __half h1 = __float2half(v1);
                            *(uint32_t*)(Ch + p) = pack_h2(h0, h1);
                            *(uint32_t*)(Cl + p) = pack_h2(
                                __float2half(v0 - __half2float(h0)),
                                __float2half(v1 - __half2float(h1)));
                        } else {
                            __nv_bfloat16 h0 = __float2bfloat16(v0);
                            __nv_bfloat16 h1 = __float2bfloat16(v1);
                            *(uint32_t*)(Ch + p) = pack_bf2(h0, h1);
                            *(uint32_t*)(Cl + p) = pack_bf2(
                                __float2bfloat16(v0 - __bfloat162float(h0)),
                                __float2bfloat16(v1 - __bfloat162float(h1)));
                        }
                    }
                } else if (gcol < N) {
                    size_t p = (size_t)grow * ldc + gcol;
                    if (ACC) v0 += C[p];
                    if (WF32) C[p] = v0;
                    if (WSPLIT) {
                        if (S16) {
                            __half h0 = __float2half(v0);
                            ((uint16_t*)Ch)[p] = __half_as_ushort(h0);
                            ((uint16_t*)Cl)[p] = __half_as_ushort(__float2half(v0 - __half2float(h0)));
                        } else {
                            __nv_bfloat16 h0 = __float2bfloat16(v0);
                            Ch[p] = h0;
                            Cl[p] = __float2bfloat16(v0 - __bfloat162float(h0));
                        }
                    }
                }
            }
        }
    }
}

// ---------------- weight splits (ILP=4) ----------------
__global__ __launch_bounds__(256) void split_kernel(
    const float* __restrict__ src, __nv_bfloat16* __restrict__ hi,
    __nv_bfloat16* __restrict__ lo, int n4)
{
    int base = blockIdx.x * 1024 + threadIdx.x;
    float4 v[4]; bool ok[4];
    #pragma unroll
    for (int j = 0; j < 4; j++) {
        int i = base + j * 256;
        ok[j] = i < n4;
        if (ok[j]) v[j] = ((const float4*)src)[i];
    }
    #pragma unroll
    for (int j = 0; j < 4; j++) {
        if (!ok[j]) continue;
        int i = base + j * 256;
        float f[4] = { v[j].x, v[j].y, v[j].z, v[j].w };
        union { __nv_bfloat16 h[4]; uint2 u; } ph, pl;
        #pragma unroll
        for (int jj = 0; jj < 4; jj++) {
            __nv_bfloat16 hv = __float2bfloat16(f[jj]);
            ph.h[jj] = hv;
            pl.h[jj] = __float2bfloat16(f[jj] - __bfloat162float(hv));
        }
        ((uint2*)hi)[i] = ph.u;
        ((uint2*)lo)[i] = pl.u;
    }
}

// fp16 hi-only split (fc / pj / lm_head weights)
__global__ __launch_bounds__(256) void split16_kernel(
    const float* __restrict__ src, uint16_t* __restrict__ hi, int n4)
{
    int base = blockIdx.x * 1024 + threadIdx.x;
    float4 v[4]; bool ok[4];
    #pragma unroll
    for (int j = 0; j < 4; j++) {
        int i = base + j * 256;
        ok[j] = i < n4;
        if (ok[j]) v[j] = ((const float4*)src)[i];
    }
    #pragma unroll
    for (int j = 0; j < 4; j++) {
        if (!ok[j]) continue;
        int i = base + j * 256;
        float f[4] = { v[j].x, v[j].y, v[j].z, v[j].w };
        union { uint16_t h[4]; uint2 u; } ph;
        #pragma unroll
        for (int jj = 0; jj < 4; jj++)
            ph.h[jj] = __half_as_ushort(__float2half(f[jj]));
        ((uint2*)hi)[i] = ph.u;
    }
}

// ---------------- block reduce ----------------
__device__ __forceinline__ float blockReduceSum(float v) {
    __shared__ float red[32];
    int lane = threadIdx.x & 31, w = threadIdx.x >> 5;
    #pragma unroll
    for (int o = 16; o; o >>= 1) v += __shfl_xor_sync(0xffffffffu, v, o);
    if (lane == 0) red[w] = v;
    __syncthreads();
    v = (threadIdx.x < (blockDim.x >> 5)) ? red[threadIdx.x] : 0.0f;
    if (w == 0) {
        #pragma unroll
        for (int o = 16; o; o >>= 1) v += __shfl_xor_sync(0xffffffffu, v, o);
        if (lane == 0) red[0] = v;
    }
    __syncthreads();
    return red[0];
}

// ---------------- embed + norms ----------------
__global__ __launch_bounds__(256) void embed_kernel(
    const int* __restrict__ idx, const float* __restrict__ wte,
    float* __restrict__ x, float* __restrict__ x0)
{
    int i = blockIdx.x;
    const float* row = wte + (size_t)idx[i] * C_;
    float v[4]; float ss = 0.f;
    #pragma unroll
    for (int j = 0; j < 4; j++) { v[j] = row[threadIdx.x + j * 256]; ss += v[j] * v[j]; }
    ss = blockReduceSum(ss);
    float sc = rsqrtf(ss / C_ + EPSF);
    #pragma unroll
    for (int j = 0; j < 4; j++) {
        float o = v[j] * sc;
        x [(size_t)i * C_ + threadIdx.x + j * 256] = o;
        x0[(size_t)i * C_ + threadIdx.x + j * 256] = o;
    }
}

// mix + norm -> fp32 xn + bf16 hi/lo (feeds wd, 3-pass path)
__global__ __launch_bounds__(256) void mixnorm_kernel(
    float* __restrict__ x, const float* __restrict__ x0,
    const float* __restrict__ rl, const float* __restrict__ xl, int l,
    float* __restrict__ xn, __nv_bfloat16* __restrict__ xnh, __nv_bfloat16* __restrict__ xnl)
{
    int i = blockIdx.x;
    float a = rl[l], bc = xl[l];
    float v[4]; float ss = 0.f;
    #pragma unroll
    for (int j = 0; j < 4; j++) {
        size_t p = (size_t)i * C_ + threadIdx.x + j * 256;
        v[j] = a * x[p] + bc * x0[p];
        ss += v[j] * v[j];
    }
    ss = blockReduceSum(ss);
    float sc = rsqrtf(ss / C_ + EPSF);
    #pragma unroll
    for (int j = 0; j < 4; j++) {
        size_t p = (size_t)i * C_ + threadIdx.x + j * 256;
        float o = v[j] * sc;
        x[p] = v[j];
        xn[p] = o;
        __nv_bfloat16 hv = __float2bfloat16(o);
        xnh[p] = hv;
        xnl[p] = __float2bfloat16(o - __bfloat162float(hv));
    }
}

// rmsnorm -> fp16 hi/lo (feeds fc / lm_head, 2-pass fp16 path)
__global__ __launch_bounds__(256) void rmsnorm16_kernel(
    const float* __restrict__ x, uint16_t* __restrict__ xnh, uint16_t* __restrict__ xnl)
{
    int i = blockIdx.x;
    float v[4]; float ss = 0.f;
    #pragma unroll
    for (int j = 0; j < 4; j++) {
        v[j] = x[(size_t)i * C_ + threadIdx.x + j * 256];
        ss += v[j] * v[j];
    }
    ss = blockReduceSum(ss);
    float sc = rsqrtf(ss / C_ + EPSF);
    #pragma unroll
    for (int j = 0; j < 4; j++) {
        size_t p = (size_t)i * C_ + threadIdx.x + j * 256;
        float o = v[j] * sc;
        __half hv = __float2half(o);
        xnh[p] = __half_as_ushort(hv);
        xnl[p] = __half_as_ushort(__float2half(o - __half2float(hv)));
    }
}

// ---------------- per-token q/k/v assembly ----------------
__global__ __launch_bounds__(512) void prep_kernel(
    const float* __restrict__ down, const float* __restrict__ kvb,
    const float* __restrict__ qraw, const float* __restrict__ xn,
    const float* __restrict__ cosb, const float* __restrict__ sinb,
    const float* __restrict__ vg, const float* __restrict__ vetab,
    const int* __restrict__ idx,
    float* __restrict__ Q, float* __restrict__ K, float* __restrict__ V)
{
    int i = blockIdx.x;
    int b = i / T_, t = i % T_;
    int w = threadIdx.x >> 5, lane = threadIdx.x & 31;
    __shared__ float cs[16], sn[16], kr[32];

    if (threadIdx.x < 16)       cs[threadIdx.x]      = cosb[(size_t)i * 16 + threadIdx.x];
    else if (threadIdx.x < 32)  sn[threadIdx.x - 16] = sinb[(size_t)i * 16 + threadIdx.x - 16];
    __syncthreads();

    float gv = xn[(size_t)i * C_ + lane] * vg[lane * H_ + w];
    #pragma unroll
    for (int o = 16; o; o >>= 1) gv += __shfl_xor_sync(0xffffffffu, gv, o);
    float gate = 2.0f / (1.0f + expf(-gv));

    if (w == 0) {
        int j = lane & 15;
        float x1 = down[(size_t)i * DOWN + 512 + j];
        float x2 = down[(size_t)i * DOWN + 528 + j];
        float cc = cs[j], ssn = sn[j];
        kr[lane] = (lane < 16) ? (x1 * cc + x2 * ssn) : (-x1 * ssn + x2 * cc);
    }
    __syncthreads();

    const float* kvrow = kvb  + (size_t)i * KVW + w * 96;
    const float* qrow  = qraw + (size_t)i * C_  + w * 64;
    const float* verow = vetab + (size_t)idx[i] * C_ + w * 64;

    float k0v = kvrow[lane];
    float k1v = kr[lane];
    float q0v = qrow[lane];
    float q1v;
    {
        int j = lane & 15;
        float a = qrow[32 + j], bb = qrow[48 + j];
        float cc = cs[j], ssn = sn[j];
        q1v = (lane < 16) ? (a * cc + bb * ssn) : (-a * ssn + bb * cc);
    }
    float v0 = kvrow[32 + lane] + gate * verow[lane];
    float v1 = kvrow[64 + lane] + gate * verow[32 + lane];

    float kss = k0v * k0v + k1v * k1v;
    float qss = q0v * q0v + q1v * q1v;
    #pragma unroll
    for (int o = 16; o; o >>= 1) {
        kss += __shfl_xor_sync(0xffffffffu, kss, o);
        qss += __shfl_xor_sync(0xffffffffu, qss, o);
    }
    float ksc = rsqrtf(kss * (1.0f / 64.0f) + EPSF);
    float qsc = rsqrtf(qss * (1.0f / 64.0f) + EPSF);

    size_t base = ((size_t)(b * H_ + w) * T_ + t) * 64;
    K[base + lane]      = k0v * ksc;
    K[base + 32 + lane] = k1v * ksc;
    Q[base + lane]      = q0v * qsc;
    Q[base + 32 + lane] = q1v * qsc;
    V[base + lane]      = v0;
    V[base + 32 + lane] = v1;
}

// ---------------- flash attention (fp32, causal) -> bf16 split output ----------------
__global__ __launch_bounds__(256) void attn_kernel(
    const float* __restrict__ Q, const float* __restrict__ Kt,
    const float* __restrict__ Vt,
    __nv_bfloat16* __restrict__ Yh, __nv_bfloat16* __restrict__ Yl)
{
    int qt0 = blockIdx.x * 64;
    int bh  = blockIdx.y;
    int b = bh >> 4, h = bh & 15;
    const float* Qb = Q  + (size_t)bh * T_ * 64;
    const float* Kb = Kt + (size_t)bh * T_ * 64;
    const float* Vb = Vt + (size_t)bh * T_ * 64;

    __shared__ float qs[64][65];
    __shared__ float ks[32][65];
    __shared__ float vs[32][68];
    __shared__ float ps[64][33];

    int tid = threadIdx.x;
    int tr = tid >> 4, tc = tid & 15;

    for (int e = tid; e < 64 * 64; e += 256) {
        int r = e >> 6, c = e & 63;
        qs[r][c] = Qb[(size_t)(qt0 + r) * 64 + c];
    }
    float m[4], l[4], o[4][4];
    #pragma unroll
    for (int mm = 0; mm < 4; mm++) {
        m[mm] = -1e30f; l[mm] = 0.f;
        #pragma unroll
        for (int nn = 0; nn < 4; nn++) o[mm][nn] = 0.f;
    }
    __syncthreads();

    for (int kt0 = 0; kt0 < qt0 + 64; kt0 += 32) {
        for (int e = tid; e < 32 * 64; e += 256) {
            int r = e >> 6, c = e & 63;
            ks[r][c] = Kb[(size_t)(kt0 + r) * 64 + c];
            vs[r][c] = Vb[(size_t)(kt0 + r) * 64 + c];
        }
        __syncthreads();

        float s[4][2];
        #pragma unroll
        for (int mm = 0; mm < 4; mm++) { s[mm][0] = 0.f; s[mm][1] = 0.f; }
        #pragma unroll
        for (int d = 0; d < 64; d++) {
            float a[4], bb[2];
            #pragma unroll
            for (int mm = 0; mm < 4; mm++) a[mm] = qs[tr * 4 + mm][d];
            #pragma unroll
            for (int nn = 0; nn < 2; nn++) bb[nn] = ks[tc * 2 + nn][d];
            #pragma unroll
            for (int mm = 0; mm < 4; mm++)
                #pragma unroll
                for (int nn = 0; nn < 2; nn++)
                    s[mm][nn] = fmaf(a[mm], bb[nn], s[mm][nn]);
        }
        bool edge = (kt0 + 32 > qt0);
        #pragma unroll
        for (int mm = 0; mm < 4; mm++)
            #pragma unroll
            for (int nn = 0; nn < 2; nn++) {
                s[mm][nn] *= 0.125f;
                if (edge) {
                    int qg = qt0 + tr * 4 + mm, kg = kt0 + tc * 2 + nn;
                    if (kg > qg) s[mm][nn] = -1e30f;
                }
            }
        #pragma unroll
        for (int mm = 0; mm < 4; mm++) {
            float rmax = fmaxf(s[mm][0], s[mm][1]);
            #pragma unroll
            for (int off = 1; off < 16; off <<= 1)
                rmax = fmaxf(rmax, __shfl_xor_sync(0xffffffffu, rmax, off));
            float mn = fmaxf(m[mm], rmax);
            float corr = expf(m[mm] - mn);
            float p0 = expf(s[mm][0] - mn);
            float p1 = expf(s[mm][1] - mn);
            float rs = p0 + p1;
            #pragma unroll
            for (int off = 1; off < 16; off <<= 1)
                rs += __shfl_xor_sync(0xffffffffu, rs, off);
            l[mm] = l[mm] * corr + rs;
            m[mm] = mn;
            ps[tr * 4 + mm][tc * 2 + 0] = p0;
            ps[tr * 4 + mm][tc * 2 + 1] = p1;
            #pragma unroll
            for (int nn = 0; nn < 4; nn++) o[mm][nn] *= corr;
        }
        __syncthreads();
        #pragma unroll
        for (int k = 0; k < 32; k++) {
            float pv[4], vv[4];
            #pragma unroll
            for (int mm = 0; mm < 4; mm++) pv[mm] = ps[tr * 4 + mm][k];
            #pragma unroll
            for (int nn = 0; nn < 4; nn++) vv[nn] = vs[k][tc * 4 + nn];
            #pragma unroll
            for (int mm = 0; mm < 4; mm++)
                #pragma unroll
                for (int nn = 0; nn < 4; nn++)
                    o[mm][nn] = fmaf(pv[mm], vv[nn], o[mm][nn]);
        }
        __syncthreads();
    }
    #pragma unroll
    for (int mm = 0; mm < 4; mm++) {
        int q = qt0 + tr * 4 + mm;
        float inv = 1.0f / l[mm];
        #pragma unroll
        for (int nn = 0; nn < 4; nn += 2) {
            size_t p = ((size_t)(b * T_ + q)) * C_ + h * 64 + tc * 4 + nn;
            float v0 = o[mm][nn] * inv, v1 = o[mm][nn + 1] * inv;
            __nv_bfloat16 h0 = __float2bfloat16(v0);
            __nv_bfloat16 h1 = __float2bfloat16(v1);
            *(uint32_t*)(Yh + p) = pack_bf2(h0, h1);
            *(uint32_t*)(Yl + p) = pack_bf2(
                __float2bfloat16(v0 - __bfloat162float(h0)),
                __float2bfloat16(v1 - __bfloat162float(h1)));
        }
    }
}

// ---------------- host side ----------------
template<typename Tp>
static Tp* sym_addr(const void* sym) {
    void* p = nullptr;
    cudaGetSymbolAddress(&p, sym);
    return (Tp*)p;
}
typedef __nv_bfloat16 bf;

struct GemmArgs {
    const bf *Ah, *Al, *Bh, *Bl;
    float* C; bf *Ch, *Cl;
    int M, N, K, lda, ldb, ldc;
};

template<int TM, int PASSES, int EPI, bool ACC, bool WSPLIT, bool WF32, bool S16>
static void launch_g(const GemmArgs& a) {
    constexpr int STRIDE = (2 * TM * 80) + (PASSES == 3 ? 17408 : 8704);
    constexpr int DSMEM  = 3 * STRIDE + 128;
    static bool done = false;
    if (!done) {
        cudaFuncSetAttribute(gemm_16<TM, PASSES, EPI, ACC, WSPLIT, WF32, S16>,
                             cudaFuncAttributeMaxDynamicSharedMemorySize, DSMEM);
        done = true;
    }
    dim3 grid(a.M / TM, (a.N + 127) / 128);
    gemm_16<TM, PASSES, EPI, ACC, WSPLIT, WF32, S16><<<grid, 256, DSMEM>>>(
        a.Ah, a.Al, a.Bh, a.Bl, a.C, a.Ch, a.Cl, a.M, a.N, a.K, a.lda, a.ldb, a.ldc);
}

static void split_w(const float* src, bf* hi, bf* lo, size_t n) {
    int n4 = (int)(n / 4);
    split_kernel<<<(n4 + 1023) / 1024, 256>>>(src, hi, lo, n4);
}
static void split_w16(const float* src, bf* hi, size_t n) {
    int n4 = (int)(n / 4);
    split16_kernel<<<(n4 + 1023) / 1024, 256>>>(src, (uint16_t*)hi, n4);
}

extern "C" void kernel_launch(void* const* d_in, const int* in_sizes, int n_in,
                              void* d_out, int out_size)
{
    (void)in_sizes; (void)n_in; (void)out_size;
    const int*   idx   = (const int*)  d_in[0];
    const float* cosb  = (const float*)d_in[1];
    const float* sinb  = (const float*)d_in[2];
    const float* wte   = (const float*)d_in[3];
    const float* vetab = (const float*)d_in[4];
    const float* wd    = (const float*)d_in[5];
    const float* wukv  = (const float*)d_in[6];
    const float* wuq   = (const float*)d_in[7];
    const float* vg    = (const float*)d_in[8];
    const float* ap    = (const float*)d_in[9];
    const float* fc    = (const float*)d_in[10];
    const float* pj    = (const float*)d_in[11];
    const float* rl    = (const float*)d_in[12];
    const float* xl    = (const float*)d_in[13];
    const float* lmh   = (const float*)d_in[14];
    float* out = (float*)d_out;

    float* px    = sym_addr<float>(g_x);
    float* px0   = sym_addr<float>(g_x0);
    float* pxn   = sym_addr<float>(g_xn);
    float* pdown = sym_addr<float>(g_down);
    float* pkv   = sym_addr<float>(g_kv);
    float* pqraw = sym_addr<float>(g_qraw);
    float* pq    = sym_addr<float>(g_q);
    float* pk    = sym_addr<float>(g_k);
    float* pv    = sym_addr<float>(g_v);

    bf *wdh = sym_addr<bf>(s_wd_h),   *wdl = sym_addr<bf>(s_wd_l);
    bf *ukh = sym_addr<bf>(s_wukv_h), *ukl = sym_addr<bf>(s_wukv_l);
    bf *uqh = sym_addr<bf>(s_wuq_h),  *uql = sym_addr<bf>(s_wuq_l);
    bf *aph = sym_addr<bf>(s_ap_h),   *apl = sym_addr<bf>(s_ap_l);
    bf *fch = sym_addr<bf>(s_fc_h);
    bf *pjh = sym_addr<bf>(s_pj_h);
    bf *lmh_h = sym_addr<bf>(s_lmh_h);
    bf *xnh = sym_addr<bf>(s_xn_h),   *xnl = sym_addr<bf>(s_xn_l);
    bf *dnh = sym_addr<bf>(s_dn_h),   *dnl = sym_addr<bf>(s_dn_l);
    bf *hhh = sym_addr<bf>(s_h_h),    *hhl = sym_addr<bf>(s_h_l);
    bf *yh  = sym_addr<bf>(s_y_h),    *yl  = sym_addr<bf>(s_y_l);

    // weight splits (once per call)
    split_w(wd,   wdh, wdl, (size_t)L_ * C_ * DOWN);
    split_w(wukv, ukh, ukl, (size_t)L_ * DC * KVW);
    split_w(wuq,  uqh, uql, (size_t)L_ * DC1 * C_);
    split_w(ap,   aph, apl, (size_t)L_ * C_ * C_);
    split_w16(fc,  fch,  (size_t)L_ * C_ * 4096);
    split_w16(pj,  pjh,  (size_t)L_ * 4096 * C_);
    split_w16(lmh, lmh_h, (size_t)C_ * VSZ);

    embed_kernel<<<TKN, 256>>>(idx, wte, px, px0);

    for (int l = 0; l < L_; l++) {
        mixnorm_kernel<<<TKN, 256>>>(px, px0, rl, xl, l, pxn, xnh, xnl);

        // down = xn @ wd[l]  -> fp32 + bf16 split (3-pass bf16)
        launch_g<64, 3, 0, false, true, true, false>({ xnh, xnl,
            wdh + (size_t)l * C_ * DOWN, wdl + (size_t)l * C_ * DOWN,
            pdown, dnh, dnl, TKN, DOWN, C_, C_, DOWN, DOWN });
        // kv = down[:, :256] @ wukv[l] -> fp32 (3-pass bf16)
        launch_g<64, 3, 0, false, false, true, false>({ dnh, dnl,
            ukh + (size_t)l * DC * KVW, ukl + (size_t)l * DC * KVW,
            pkv, nullptr, nullptr, TKN, KVW, DC, DOWN, KVW, KVW });
        // qraw = down[:, 256:512] @ wuq[l] -> fp32 (3-pass bf16)
        launch_g<64, 3, 0, false, false, true, false>({ dnh + DC, dnl + DC,
            uqh + (size_t)l * DC1 * C_, uql + (size_t)l * DC1 * C_,
            pqraw, nullptr, nullptr, TKN, C_, DC1, DOWN, C_, C_ });

        prep_kernel<<<TKN, 512>>>(pdown, pkv, pqraw, pxn, cosb, sinb,
                                  vg + (size_t)l * GC * H_,
                                  vetab + (size_t)l * VSZ * C_,
                                  idx, pq, pk, pv);

        attn_kernel<<<dim3(T_ / 64, B_ * H_), 256>>>(pq, pk, pv, yh, yl);

        // x += y @ attn_proj[l] (3-pass bf16)
        launch_g<64, 3, 0, true, false, true, false>({ yh, yl,
            aph + (size_t)l * C_ * C_, apl + (size_t)l * C_ * C_,
            px, nullptr, nullptr, TKN, C_, C_, C_, C_, C_ });

        // rmsnorm -> fp16 hi/lo (feeds fc 2-pass fp16)
        rmsnorm16_kernel<<<TKN, 256>>>(px, (uint16_t*)xnh, (uint16_t*)xnl);

        // h = relu(xn @ fc[l])^2 -> fp16 split (2-pass fp16)
        launch_g<128, 2, 1, false, true, false, true>({ xnh, xnl,
            fch + (size_t)l * C_ * 4096, nullptr,
            nullptr, hhh, hhl, TKN, 4096, C_, C_, 4096, 4096 });
        // x += h @ proj[l] (2-pass fp16)
        launch_g<64, 2, 0, true, false, true, false>({ hhh, hhl,
            pjh + (size_t)l * 4096 * C_, nullptr,
            px, nullptr, nullptr, TKN, C_, 4096, 4096, C_, C_ });
    }

    // final rmsnorm -> fp16 hi/lo
    rmsnorm16_kernel<<<TKN, 256>>>(px, (uint16_t*)xnh, (uint16_t*)xnl);
    // logits = softcap(xn @ lm_head) (2-pass fp16)
    launch_g<128, 2, 2, false, false, true, false>({ xnh, xnl, lmh_h, nullptr,
        out, nullptr, nullptr, TKN, VSZ, C_, C_, VSZ, VSZ });
}

// round 10
// speedup vs baseline: 3.8453x; 1.0426x over previous
#include <cuda_runtime.h>
#include <cuda_bf16.h>
#include <cuda_fp16.h>
#include <math.h>
#include <stdint.h>

// ---------------- problem constants ----------------
#define B_    2
#define T_    1024
#define C_    1024
#define H_    16
#define HD_   64
#define DC    256
#define DC1   256
#define DR    32
#define DN    32
#define DOWN  544
#define VSZ   32000
#define L_    4
#define GC    32
#define TKN   2048
#define KVW   1536
#define EPSF  1.1920929e-7f

// ---------------- fp32 scratch ----------------
__device__ float g_x   [TKN * C_];
__device__ float g_x0  [TKN * C_];
__device__ float g_xn  [TKN * C_];
__device__ float g_down[TKN * DOWN];
__device__ float g_kv  [TKN * KVW];
__device__ float g_qraw[TKN * C_];
__device__ float g_q   [B_ * H_ * T_ * HD_];
__device__ float g_k   [B_ * H_ * T_ * HD_];
__device__ float g_v   [B_ * H_ * T_ * HD_];

// ---------------- fp16 hi/lo split buffers (uint16_t = fp16 bits) ----------------
__device__ uint16_t s_wd_h  [L_ * C_ * DOWN];
__device__ uint16_t s_wukv_h[L_ * DC * KVW];
__device__ uint16_t s_wuq_h [L_ * DC1 * C_];
__device__ uint16_t s_ap_h  [L_ * C_ * C_];
__device__ uint16_t s_fc_h  [L_ * C_ * 4096];
__device__ uint16_t s_pj_h  [L_ * 4096 * C_];
__device__ uint16_t s_lmh_h [C_ * VSZ];
__device__ uint16_t s_xn_h  [TKN * C_],   s_xn_l [TKN * C_];
__device__ uint16_t s_dn_h  [TKN * DOWN], s_dn_l [TKN * DOWN];
__device__ uint16_t s_h_h   [TKN * 4096], s_h_l  [TKN * 4096];
__device__ uint16_t s_y_h   [TKN * C_],   s_y_l  [TKN * C_];

// ================= helpers =================
__device__ __forceinline__ uint32_t smem_u32(const void* p) {
    uint32_t a;
    asm("{ .reg .u64 t; cvta.to.shared.u64 t, %1; cvt.u32.u64 %0, t; }" : "=r"(a) : "l"(p));
    return a;
}
__device__ __forceinline__ void ldsm_x4(uint32_t r[4], uint32_t addr) {
    asm volatile("ldmatrix.sync.aligned.m8n8.x4.shared.b16 {%0,%1,%2,%3}, [%4];"
        : "=r"(r[0]), "=r"(r[1]), "=r"(r[2]), "=r"(r[3]) : "r"(addr));
}
__device__ __forceinline__ void ldsm_x2t(uint32_t r[2], uint32_t addr) {
    asm volatile("ldmatrix.sync.aligned.m8n8.x2.trans.shared.b16 {%0,%1}, [%2];"
        : "=r"(r[0]), "=r"(r[1]) : "r"(addr));
}
__device__ __forceinline__ void mma_f16(float c[4], const uint32_t a[4], const uint32_t b[2]) {
    asm volatile("mma.sync.aligned.m16n8k16.row.col.f32.f16.f16.f32 "
        "{%0,%1,%2,%3}, {%4,%5,%6,%7}, {%8,%9}, {%0,%1,%2,%3};"
        : "+f"(c[0]), "+f"(c[1]), "+f"(c[2]), "+f"(c[3])
        : "r"(a[0]), "r"(a[1]), "r"(a[2]), "r"(a[3]), "r"(b[0]), "r"(b[1]));
}
__device__ __forceinline__ void cp16(uint32_t dst, const void* src) {
    asm volatile("cp.async.cg.shared.global [%0], [%1], 16;" :: "r"(dst), "l"(src));
}
__device__ __forceinline__ void cp16z(uint32_t dst, const void* src, uint32_t ssize) {
    asm volatile("cp.async.cg.shared.global [%0], [%1], 16, %2;" :: "r"(dst), "l"(src), "r"(ssize));
}
#define CP_COMMIT() asm volatile("cp.async.commit_group;" ::: "memory")
#define CP_WAIT1()  asm volatile("cp.async.wait_group 1;" ::: "memory")
__device__ __forceinline__ uint32_t pack_h2(__half a, __half b) {
    union { __half h[2]; uint32_t u; } u;
    u.h[0] = a; u.h[1] = b;
    return u.u;
}

// ================= fp16 2-pass GEMM =================
// C[M,N] = A[M,K] @ B[K,N]; A fp16 hi/lo, B fp16 hi; D = Ah*Bh + Al*Bh (fp32 acc).
// smem per stage: A_hi[TM][40] | A_lo | B_hi[32][136]
// EPI: 0 none, 1 relu^2, 2 softcap.  WSPLIT -> fp16 hi/lo out. WF32 -> fp32 out.
template<int TM, int EPI, bool ACC, bool WSPLIT, bool WF32>
__global__ __launch_bounds__(256, 2) void gemm_16(
    const uint16_t* __restrict__ Ah, const uint16_t* __restrict__ Al,
    const uint16_t* __restrict__ Bh,
    float* __restrict__ C, uint16_t* __restrict__ Ch, uint16_t* __restrict__ Cl,
    int M, int N, int K, int lda, int ldb, int ldc)
{
    constexpr int MT     = TM / 32;
    constexpr int A_SZ   = TM * 80;
    constexpr int B_OFF  = 2 * A_SZ;
    constexpr int STRIDE = B_OFF + 8704;

    extern __shared__ char dsm[];
    uint32_t sraw = smem_u32(dsm);
    uint32_t s0 = (sraw + 127u) & ~127u;

    int tid = threadIdx.x, wid = tid >> 5, lane = tid & 31;
    int row0 = blockIdx.x * TM, col0 = blockIdx.y * 128;
    int wm = (wid >> 2) * (TM / 2);
    int wn = (wid & 3) * 32;

    float c[MT][4][4];
    #pragma unroll
    for (int mt = 0; mt < MT; mt++)
        #pragma unroll
        for (int nt = 0; nt < 4; nt++)
            #pragma unroll
            for (int r = 0; r < 4; r++) c[mt][nt][r] = 0.f;

    int NC = K >> 5;

    auto issue_copy = [&](int i, int stg) {
        int k0 = i << 5;
        uint32_t sb = s0 + (uint32_t)stg * STRIDE;
        #pragma unroll
        for (int e = tid; e < TM * 4; e += 256) {
            int r = e >> 2, seg = e & 3;
            uint32_t d = sb + (uint32_t)(r * 80 + seg * 16);
            cp16(d,                  Ah + (size_t)(row0 + r) * lda + k0 + seg * 8);
            cp16(d + (uint32_t)A_SZ, Al + (size_t)(row0 + r) * lda + k0 + seg * 8);
        }
        #pragma unroll
        for (int e0 = 0; e0 < 2; e0++) {
            int e = tid + e0 * 256;
            int kk = e >> 4, seg = e & 15;
            int gc = col0 + seg * 8;
            uint32_t d = sb + (uint32_t)B_OFF + (uint32_t)(kk * 272 + seg * 16);
            int rem = N - gc;
            uint32_t sz = rem >= 8 ? 16u : (rem > 0 ? (uint32_t)(rem * 2) : 0u);
            cp16z(d, Bh + (size_t)(k0 + kk) * ldb + gc, sz);
        }
    };

    auto mma_chunk = [&](int stg) {
        uint32_t base = s0 + (uint32_t)stg * STRIDE;
        int arow = wm + ((lane >> 3) & 1) * 8 + (lane & 7);
        int krow = lane & 15;
        #pragma unroll
        for (int kk = 0; kk < 32; kk += 16) {
            int acol = kk + ((lane >> 4) & 1) * 8;
            uint32_t af[MT][4], bh[4][2];
            #pragma unroll
            for (int mt = 0; mt < MT; mt++)
                ldsm_x4(af[mt], base + (uint32_t)((arow + mt * 16) * 80 + acol * 2));
            #pragma unroll
            for (int nt = 0; nt < 4; nt++)
                ldsm_x2t(bh[nt], base + (uint32_t)B_OFF + (uint32_t)((kk + krow) * 272 + (wn + nt * 8) * 2));
            #pragma unroll
            for (int mt = 0; mt < MT; mt++)
                #pragma unroll
                for (int nt = 0; nt < 4; nt++)
                    mma_f16(c[mt][nt], af[mt], bh[nt]);
            #pragma unroll
            for (int mt = 0; mt < MT; mt++)
                ldsm_x4(af[mt], base + (uint32_t)A_SZ + (uint32_t)((arow + mt * 16) * 80 + acol * 2));
            #pragma unroll
            for (int mt = 0; mt < MT; mt++)
                #pragma unroll
                for (int nt = 0; nt < 4; nt++)
                    mma_f16(c[mt][nt], af[mt], bh[nt]);
        }
    };

    issue_copy(0, 0); CP_COMMIT();
    issue_copy(1, 1); CP_COMMIT();
    for (int i = 0; i < NC; i++) {
        CP_WAIT1();
        __syncthreads();
        mma_chunk(i % 3);
        if (i + 2 < NC) issue_copy(i + 2, (i + 2) % 3);
        CP_COMMIT();
    }

    // ---- epilogue ----
    #pragma unroll
    for (int mt = 0; mt < MT; mt++) {
        #pragma unroll
        for (int nt = 0; nt < 4; nt++) {
            #pragma unroll
            for (int half = 0; half < 2; half++) {
                int grow = row0 + wm + mt * 16 + (lane >> 2) + half * 8;
                int gcol = col0 + wn + nt * 8 + (lane & 3) * 2;
                float v0 = c[mt][nt][half * 2 + 0];
                float v1 = c[mt][nt][half * 2 + 1];
                if (EPI == 1) {
                    float h0 = fmaxf(v0, 0.f); v0 = h0 * h0;
                    float h1 = fmaxf(v1, 0.f); v1 = h1 * h1;
                }
                if (EPI == 2) {
                    v0 = 15.0f * tanhf(v0 * (1.0f / 15.0f));
                    v1 = 15.0f * tanhf(v1 * (1.0f / 15.0f));
                }
                if (gcol + 1 < N) {
                    size_t p = (size_t)grow * ldc + gcol;
                    if (ACC) { v0 += C[p]; v1 += C[p + 1]; }
                    if (WF32) *(float2*)(C + p) = make_float2(v0, v1);
                    if (WSPLIT) {
                        __half h0 = __float2half(v0);
                        __half h1 = __float2half(v1);
                        *(uint32_t*)(Ch + p) = pack_h2(h0, h1);
                        *(uint32_t*)(Cl + p) = pack_h2(
                            __float2half(v0 - __half2float(h0)),
                            __float2half(v1 - __half2float(h1)));
                    }
                } else if (gcol < N) {
                    size_t p = (size_t)grow * ldc + gcol;
                    if (ACC) v0 += C[p];
                    if (WF32) C[p] = v0;
                    if (WSPLIT) {
                        __half h0 = __float2half(v0);
                        Ch[p] = __half_as_ushort(h0);
                        Cl[p] = __half_as_ushort(__float2half(v0 - __half2float(h0)));
                    }
                }
            }
        }
    }
}

// ---------------- fp16 hi-only weight split (ILP=8) ----------------
__global__ __launch_bounds__(256) void split16_kernel(
    const float* __restrict__ src, uint16_t* __restrict__ hi, int n4)
{
    int base = blockIdx.x * 2048 + threadIdx.x;
    #pragma unroll
    for (int j = 0; j < 8; j++) {
        int i = base + j * 256;
        if (i >= n4) break;
        float4 v = ((const float4*)src)[i];
        float f[4] = { v.x, v.y, v.z, v.w };
        union { uint16_t h[4]; uint2 u; } ph;
        #pragma unroll
        for (int jj = 0; jj < 4; jj++)
            ph.h[jj] = __half_as_ushort(__float2half(f[jj]));
        ((uint2*)hi)[i] = ph.u;
    }
}

// ---------------- block reduce ----------------
__device__ __forceinline__ float blockReduceSum(float v) {
    __shared__ float red[32];
    int lane = threadIdx.x & 31, w = threadIdx.x >> 5;
    #pragma unroll
    for (int o = 16; o; o >>= 1) v += __shfl_xor_sync(0xffffffffu, v, o);
    if (lane == 0) red[w] = v;
    __syncthreads();
    v = (threadIdx.x < (blockDim.x >> 5)) ? red[threadIdx.x] : 0.0f;
    if (w == 0) {
        #pragma unroll
        for (int o = 16; o; o >>= 1) v += __shfl_xor_sync(0xffffffffu, v, o);
        if (lane == 0) red[0] = v;
    }
    __syncthreads();
    return red[0];
}

// ---------------- embed + norms ----------------
__global__ __launch_bounds__(256) void embed_kernel(
    const int* __restrict__ idx, const float* __restrict__ wte,
    float* __restrict__ x, float* __restrict__ x0)
{
    int i = blockIdx.x;
    const float* row = wte + (size_t)idx[i] * C_;
    float v[4]; float ss = 0.f;
    #pragma unroll
    for (int j = 0; j < 4; j++) { v[j] = row[threadIdx.x + j * 256]; ss += v[j] * v[j]; }
    ss = blockReduceSum(ss);
    float sc = rsqrtf(ss / C_ + EPSF);
    #pragma unroll
    for (int j = 0; j < 4; j++) {
        float o = v[j] * sc;
        x [(size_t)i * C_ + threadIdx.x + j * 256] = o;
        x0[(size_t)i * C_ + threadIdx.x + j * 256] = o;
    }
}

// mix + norm -> fp32 xn + fp16 hi/lo
__global__ __launch_bounds__(256) void mixnorm_kernel(
    float* __restrict__ x, const float* __restrict__ x0,
    const float* __restrict__ rl, const float* __restrict__ xl, int l,
    float* __restrict__ xn, uint16_t* __restrict__ xnh, uint16_t* __restrict__ xnl)
{
    int i = blockIdx.x;
    float a = rl[l], bc = xl[l];
    float v[4]; float ss = 0.f;
    #pragma unroll
    for (int j = 0; j < 4; j++) {
        size_t p = (size_t)i * C_ + threadIdx.x + j * 256;
        v[j] = a * x[p] + bc * x0[p];
        ss += v[j] * v[j];
    }
    ss = blockReduceSum(ss);
    float sc = rsqrtf(ss / C_ + EPSF);
    #pragma unroll
    for (int j = 0; j < 4; j++) {
        size_t p = (size_t)i * C_ + threadIdx.x + j * 256;
        float o = v[j] * sc;
        x[p] = v[j];
        xn[p] = o;
        __half hv = __float2half(o);
        xnh[p] = __half_as_ushort(hv);
        xnl[p] = __half_as_ushort(__float2half(o - __half2float(hv)));
    }
}

// rmsnorm -> fp16 hi/lo
__global__ __launch_bounds__(256) void rmsnorm16_kernel(
    const float* __restrict__ x, uint16_t* __restrict__ xnh, uint16_t* __restrict__ xnl)
{
    int i = blockIdx.x;
    float v[4]; float ss = 0.f;
    #pragma unroll
    for (int j = 0; j < 4; j++) {
        v[j] = x[(size_t)i * C_ + threadIdx.x + j * 256];
        ss += v[j] * v[j];
    }
    ss = blockReduceSum(ss);
    float sc = rsqrtf(ss / C_ + EPSF);
    #pragma unroll
    for (int j = 0; j < 4; j++) {
        size_t p = (size_t)i * C_ + threadIdx.x + j * 256;
        float o = v[j] * sc;
        __half hv = __float2half(o);
        xnh[p] = __half_as_ushort(hv);
        xnl[p] = __half_as_ushort(__float2half(o - __half2float(hv)));
    }
}

// ---------------- per-token q/k/v assembly ----------------
__global__ __launch_bounds__(512) void prep_kernel(
    const float* __restrict__ down, const float* __restrict__ kvb,
    const float* __restrict__ qraw, const float* __restrict__ xn,
    const float* __restrict__ cosb, const float* __restrict__ sinb,
    const float* __restrict__ vg, const float* __restrict__ vetab,
    const int* __restrict__ idx,
    float* __restrict__ Q, float* __restrict__ K, float* __restrict__ V)
{
    int i = blockIdx.x;
    int b = i / T_, t = i % T_;
    int w = threadIdx.x >> 5, lane = threadIdx.x & 31;
    __shared__ float cs[16], sn[16], kr[32];

    if (threadIdx.x < 16)       cs[threadIdx.x]      = cosb[(size_t)i * 16 + threadIdx.x];
    else if (threadIdx.x < 32)  sn[threadIdx.x - 16] = sinb[(size_t)i * 16 + threadIdx.x - 16];
    __syncthreads();

    float gv = xn[(size_t)i * C_ + lane] * vg[lane * H_ + w];
    #pragma unroll
    for (int o = 16; o; o >>= 1) gv += __shfl_xor_sync(0xffffffffu, gv, o);
    float gate = 2.0f / (1.0f + expf(-gv));

    if (w == 0) {
        int j = lane & 15;
        float x1 = down[(size_t)i * DOWN + 512 + j];
        float x2 = down[(size_t)i * DOWN + 528 + j];
        float cc = cs[j], ssn = sn[j];
        kr[lane] = (lane < 16) ? (x1 * cc + x2 * ssn) : (-x1 * ssn + x2 * cc);
    }
    __syncthreads();

    const float* kvrow = kvb  + (size_t)i * KVW + w * 96;
    const float* qrow  = qraw + (size_t)i * C_  + w * 64;
    const float* verow = vetab + (size_t)idx[i] * C_ + w * 64;

    float k0v = kvrow[lane];
    float k1v = kr[lane];
    float q0v = qrow[lane];
    float q1v;
    {
        int j = lane & 15;
        float a = qrow[32 + j], bb = qrow[48 + j];
        float cc = cs[j], ssn = sn[j];
        q1v = (lane < 16) ? (a * cc + bb * ssn) : (-a * ssn + bb * cc);
    }
    float v0 = kvrow[32 + lane] + gate * verow[lane];
    float v1 = kvrow[64 + lane] + gate * verow[32 + lane];

    float kss = k0v * k0v + k1v * k1v;
    float qss = q0v * q0v + q1v * q1v;
    #pragma unroll
    for (int o = 16; o; o >>= 1) {
        kss += __shfl_xor_sync(0xffffffffu, kss, o);
        qss += __shfl_xor_sync(0xffffffffu, qss, o);
    }
    float ksc = rsqrtf(kss * (1.0f / 64.0f) + EPSF);
    float qsc = rsqrtf(qss * (1.0f / 64.0f) + EPSF);

    size_t base = ((size_t)(b * H_ + w) * T_ + t) * 64;
    K[base + lane]      = k0v * ksc;
    K[base + 32 + lane] = k1v * ksc;
    Q[base + lane]      = q0v * qsc;
    Q[base + 32 + lane] = q1v * qsc;
    V[base + lane]      = v0;
    V[base + 32 + lane] = v1;
}

// ---------------- flash attention (fp32, causal) -> fp16 split output ----------------
__global__ __launch_bounds__(256) void attn_kernel(
    const float* __restrict__ Q, const float* __restrict__ Kt,
    const float* __restrict__ Vt,
    uint16_t* __restrict__ Yh, uint16_t* __restrict__ Yl)
{
    int qt0 = blockIdx.x * 64;
    int bh  = blockIdx.y;
    int b = bh >> 4, h = bh & 15;
    const float* Qb = Q  + (size_t)bh * T_ * 64;
    const float* Kb = Kt + (size_t)bh * T_ * 64;
    const float* Vb = Vt + (size_t)bh * T_ * 64;

    __shared__ float qs[64][65];
    __shared__ float ks[32][65];
    __shared__ float vs[32][68];
    __shared__ float ps[64][33];

    int tid = threadIdx.x;
    int tr = tid >> 4, tc = tid & 15;

    for (int e = tid; e < 64 * 64; e += 256) {
        int r = e >> 6, c = e & 63;
        qs[r][c] = Qb[(size_t)(qt0 + r) * 64 + c];
    }
    float m[4], l[4], o[4][4];
    #pragma unroll
    for (int mm = 0; mm < 4; mm++) {
        m[mm] = -1e30f; l[mm] = 0.f;
        #pragma unroll
        for (int nn = 0; nn < 4; nn++) o[mm][nn] = 0.f;
    }
    __syncthreads();

    for (int kt0 = 0; kt0 < qt0 + 64; kt0 += 32) {
        for (int e = tid; e < 32 * 64; e += 256) {
            int r = e >> 6, c = e & 63;
            ks[r][c] = Kb[(size_t)(kt0 + r) * 64 + c];
            vs[r][c] = Vb[(size_t)(kt0 + r) * 64 + c];
        }
        __syncthreads();

        float s[4][2];
        #pragma unroll
        for (int mm = 0; mm < 4; mm++) { s[mm][0] = 0.f; s[mm][1] = 0.f; }
        #pragma unroll
        for (int d = 0; d < 64; d++) {
            float a[4], bb[2];
            #pragma unroll
            for (int mm = 0; mm < 4; mm++) a[mm] = qs[tr * 4 + mm][d];
            #pragma unroll
            for (int nn = 0; nn < 2; nn++) bb[nn] = ks[tc * 2 + nn][d];
            #pragma unroll
            for (int mm = 0; mm < 4; mm++)
                #pragma unroll
                for (int nn = 0; nn < 2; nn++)
                    s[mm][nn] = fmaf(a[mm], bb[nn], s[mm][nn]);
        }
        bool edge = (kt0 + 32 > qt0);
        #pragma unroll
        for (int mm = 0; mm < 4; mm++)
            #pragma unroll
            for (int nn = 0; nn < 2; nn++) {
                s[mm][nn] *= 0.125f;
                if (edge) {
                    int qg = qt0 + tr * 4 + mm, kg = kt0 + tc * 2 + nn;
                    if (kg > qg) s[mm][nn] = -1e30f;
                }
            }
        #pragma unroll
        for (int mm = 0; mm < 4; mm++) {
            float rmax = fmaxf(s[mm][0], s[mm][1]);
            #pragma unroll
            for (int off = 1; off < 16; off <<= 1)
                rmax = fmaxf(rmax, __shfl_xor_sync(0xffffffffu, rmax, off));
            float mn = fmaxf(m[mm], rmax);
            float corr = expf(m[mm] - mn);
            float p0 = expf(s[mm][0] - mn);
            float p1 = expf(s[mm][1] - mn);
            float rs = p0 + p1;
            #pragma unroll
            for (int off = 1; off < 16; off <<= 1)
                rs += __shfl_xor_sync(0xffffffffu, rs, off);
            l[mm] = l[mm] * corr + rs;
            m[mm] = mn;
            ps[tr * 4 + mm][tc * 2 + 0] = p0;
            ps[tr * 4 + mm][tc * 2 + 1] = p1;
            #pragma unroll
            for (int nn = 0; nn < 4; nn++) o[mm][nn] *= corr;
        }
        __syncthreads();
        #pragma unroll
        for (int k = 0; k < 32; k++) {
            float pv[4], vv[4];
            #pragma unroll
            for (int mm = 0; mm < 4; mm++) pv[mm] = ps[tr * 4 + mm][k];
            #pragma unroll
            for (int nn = 0; nn < 4; nn++) vv[nn] = vs[k][tc * 4 + nn];
            #pragma unroll
            for (int mm = 0; mm < 4; mm++)
                #pragma unroll
                for (int nn = 0; nn < 4; nn++)
                    o[mm][nn] = fmaf(pv[mm], vv[nn], o[mm][nn]);
        }
        __syncthreads();
    }
    #pragma unroll
    for (int mm = 0; mm < 4; mm++) {
        int q = qt0 + tr * 4 + mm;
        float inv = 1.0f / l[mm];
        #pragma unroll
        for (int nn = 0; nn < 4; nn += 2) {
            size_t p = ((size_t)(b * T_ + q)) * C_ + h * 64 + tc * 4 + nn;
            float v0 = o[mm][nn] * inv, v1 = o[mm][nn + 1] * inv;
            __half h0 = __float2half(v0);
            __half h1 = __float2half(v1);
            *(uint32_t*)(Yh + p) = pack_h2(h0, h1);
            *(uint32_t*)(Yl + p) = pack_h2(
                __float2half(v0 - __half2float(h0)),
                __float2half(v1 - __half2float(h1)));
        }
    }
}

// ---------------- host side ----------------
template<typename Tp>
static Tp* sym_addr(const void* sym) {
    void* p = nullptr;
    cudaGetSymbolAddress(&p, sym);
    return (Tp*)p;
}

struct GemmArgs {
    const uint16_t *Ah, *Al, *Bh;
    float* C; uint16_t *Ch, *Cl;
    int M, N, K, lda, ldb, ldc;
};

template<int TM, int EPI, bool ACC, bool WSPLIT, bool WF32>
static void launch_g(const GemmArgs& a) {
    constexpr int STRIDE = (2 * TM * 80) + 8704;
    constexpr int DSMEM  = 3 * STRIDE + 128;
    static bool done = false;
    if (!done) {
        cudaFuncSetAttribute(gemm_16<TM, EPI, ACC, WSPLIT, WF32>,
                             cudaFuncAttributeMaxDynamicSharedMemorySize, DSMEM);
        done = true;
    }
    dim3 grid(a.M / TM, (a.N + 127) / 128);
    gemm_16<TM, EPI, ACC, WSPLIT, WF32><<<grid, 256, DSMEM>>>(
        a.Ah, a.Al, a.Bh, a.C, a.Ch, a.Cl, a.M, a.N, a.K, a.lda, a.ldb, a.ldc);
}

static void split_w16(const float* src, uint16_t* hi, size_t n) {
    int n4 = (int)(n / 4);
    split16_kernel<<<(n4 + 2047) / 2048, 256>>>(src, hi, n4);
}

extern "C" void kernel_launch(void* const* d_in, const int* in_sizes, int n_in,
                              void* d_out, int out_size)
{
    (void)in_sizes; (void)n_in; (void)out_size;
    const int*   idx   = (const int*)  d_in[0];
    const float* cosb  = (const float*)d_in[1];
    const float* sinb  = (const float*)d_in[2];
    const float* wte   = (const float*)d_in[3];
    const float* vetab = (const float*)d_in[4];
    const float* wd    = (const float*)d_in[5];
    const float* wukv  = (const float*)d_in[6];
    const float* wuq   = (const float*)d_in[7];
    const float* vg    = (const float*)d_in[8];
    const float* ap    = (const float*)d_in[9];
    const float* fc    = (const float*)d_in[10];
    const float* pj    = (const float*)d_in[11];
    const float* rl    = (const float*)d_in[12];
    const float* xl    = (const float*)d_in[13];
    const float* lmh   = (const float*)d_in[14];
    float* out = (float*)d_out;

    float* px    = sym_addr<float>(g_x);
    float* px0   = sym_addr<float>(g_x0);
    float* pxn   = sym_addr<float>(g_xn);
    float* pdown = sym_addr<float>(g_down);
    float* pkv   = sym_addr<float>(g_kv);
    float* pqraw = sym_addr<float>(g_qraw);
    float* pq    = sym_addr<float>(g_q);
    float* pk    = sym_addr<float>(g_k);
    float* pv    = sym_addr<float>(g_v);

    uint16_t *wdh = sym_addr<uint16_t>(s_wd_h);
    uint16_t *ukh = sym_addr<uint16_t>(s_wukv_h);
    uint16_t *uqh = sym_addr<uint16_t>(s_wuq_h);
    uint16_t *aph = sym_addr<uint16_t>(s_ap_h);
    uint16_t *fch = sym_addr<uint16_t>(s_fc_h);
    uint16_t *pjh = sym_addr<uint16_t>(s_pj_h);
    uint16_t *lmhh = sym_addr<uint16_t>(s_lmh_h);
    uint16_t *xnh = sym_addr<uint16_t>(s_xn_h), *xnl = sym_addr<uint16_t>(s_xn_l);
    uint16_t *dnh = sym_addr<uint16_t>(s_dn_h), *dnl = sym_addr<uint16_t>(s_dn_l);
    uint16_t *hhh = sym_addr<uint16_t>(s_h_h),  *hhl = sym_addr<uint16_t>(s_h_l);
    uint16_t *yh  = sym_addr<uint16_t>(s_y_h),  *yl  = sym_addr<uint16_t>(s_y_l);

    // weight splits (fp16 hi only, once per call)
    split_w16(wd,   wdh,  (size_t)L_ * C_ * DOWN);
    split_w16(wukv, ukh,  (size_t)L_ * DC * KVW);
    split_w16(wuq,  uqh,  (size_t)L_ * DC1 * C_);
    split_w16(ap,   aph,  (size_t)L_ * C_ * C_);
    split_w16(fc,   fch,  (size_t)L_ * C_ * 4096);
    split_w16(pj,   pjh,  (size_t)L_ * 4096 * C_);
    split_w16(lmh,  lmhh, (size_t)C_ * VSZ);

    embed_kernel<<<TKN, 256>>>(idx, wte, px, px0);

    for (int l = 0; l < L_; l++) {
        mixnorm_kernel<<<TKN, 256>>>(px, px0, rl, xl, l, pxn, xnh, xnl);

        // down = xn @ wd[l]  -> fp32 + fp16 split
        launch_g<64, 0, false, true, true>({ xnh, xnl,
            wdh + (size_t)l * C_ * DOWN,
            pdown, dnh, dnl, TKN, DOWN, C_, C_, DOWN, DOWN });
        // kv = down[:, :256] @ wukv[l] -> fp32
        launch_g<64, 0, false, false, true>({ dnh, dnl,
            ukh + (size_t)l * DC * KVW,
            pkv, nullptr, nullptr, TKN, KVW, DC, DOWN, KVW, KVW });
        // qraw = down[:, 256:512] @ wuq[l] -> fp32
        launch_g<64, 0, false, false, true>({ dnh + DC, dnl + DC,
            uqh + (size_t)l * DC1 * C_,
            pqraw, nullptr, nullptr, TKN, C_, DC1, DOWN, C_, C_ });

        prep_kernel<<<TKN, 512>>>(pdown, pkv, pqraw, pxn, cosb, sinb,
                                  vg + (size_t)l * GC * H_,
                                  vetab + (size_t)l * VSZ * C_,
                                  idx, pq, pk, pv);

        attn_kernel<<<dim3(T_ / 64, B_ * H_), 256>>>(pq, pk, pv, yh, yl);

        // x += y @ attn_proj[l]
        launch_g<64, 0, true, false, true>({ yh, yl,
            aph + (size_t)l * C_ * C_,
            px, nullptr, nullptr, TKN, C_, C_, C_, C_, C_ });

        rmsnorm16_kernel<<<TKN, 256>>>(px, xnh, xnl);

        // h = relu(xn @ fc[l])^2 -> fp16 split
        launch_g<128, 1, false, true, false>({ xnh, xnl,
            fch + (size_t)l * C_ * 4096,
            nullptr, hhh, hhl, TKN, 4096, C_, C_, 4096, 4096 });
        // x += h @ proj[l]
        launch_g<64, 0, true, false, true>({ hhh, hhl,
            pjh + (size_t)l * 4096 * C_,
            px, nullptr, nullptr, TKN, C_, 4096, 4096, C_, C_ });
    }

    rmsnorm16_kernel<<<TKN, 256>>>(px, xnh, xnl);
    // logits = softcap(xn @ lm_head)
    launch_g<128, 2, false, false, true>({ xnh, xnl, lmhh,
        out, nullptr, nullptr, TKN, VSZ, C_, C_, VSZ, VSZ });
}

// round 12
// speedup vs baseline: 5.0060x; 1.3018x over previous
#include <cuda_runtime.h>
#include <cuda_bf16.h>
#include <cuda_fp16.h>
#include <math.h>
#include <stdint.h>

// ---------------- problem constants ----------------
#define B_    2
#define T_    1024
#define C_    1024
#define H_    16
#define HD_   64
#define DC    256
#define DC1   256
#define DR    32
#define DN    32
#define DOWN  544
#define VSZ   32000
#define L_    4
#define GC    32
#define TKN   2048
#define KVW   1536
#define EPSF  1.1920929e-7f

// ---------------- fp32 scratch ----------------
__device__ float g_x   [TKN * C_];
__device__ float g_x0  [TKN * C_];
__device__ float g_xn  [TKN * C_];
__device__ float g_down[TKN * DOWN];
__device__ float g_kv  [TKN * KVW];
__device__ float g_qraw[TKN * C_];

// ---------------- fp16 attention tensors [bh][T][64] ----------------
__device__ uint16_t g_qh[B_ * H_ * T_ * HD_], g_ql[B_ * H_ * T_ * HD_];
__device__ uint16_t g_kh[B_ * H_ * T_ * HD_];
__device__ uint16_t g_vh[B_ * H_ * T_ * HD_];

// ---------------- fp16 hi/lo split buffers (uint16_t = fp16 bits) ----------------
__device__ uint16_t s_wd_h  [L_ * C_ * DOWN];
__device__ uint16_t s_wukv_h[L_ * DC * KVW];
__device__ uint16_t s_wuq_h [L_ * DC1 * C_];
__device__ uint16_t s_ap_h  [L_ * C_ * C_];
__device__ uint16_t s_fc_h  [L_ * C_ * 4096];
__device__ uint16_t s_pj_h  [L_ * 4096 * C_];
__device__ uint16_t s_lmh_h [C_ * VSZ];
__device__ uint16_t s_xn_h  [TKN * C_],   s_xn_l [TKN * C_];
__device__ uint16_t s_dn_h  [TKN * DOWN], s_dn_l [TKN * DOWN];
__device__ uint16_t s_h_h   [TKN * 4096], s_h_l  [TKN * 4096];
__device__ uint16_t s_y_h   [TKN * C_],   s_y_l  [TKN * C_];

// ================= helpers =================
__device__ __forceinline__ uint32_t smem_u32(const void* p) {
    uint32_t a;
    asm("{ .reg .u64 t; cvta.to.shared.u64 t, %1; cvt.u32.u64 %0, t; }" : "=r"(a) : "l"(p));
    return a;
}
__device__ __forceinline__ void ldsm_x4(uint32_t r[4], uint32_t addr) {
    asm volatile("ldmatrix.sync.aligned.m8n8.x4.shared.b16 {%0,%1,%2,%3}, [%4];"
        : "=r"(r[0]), "=r"(r[1]), "=r"(r[2]), "=r"(r[3]) : "r"(addr));
}
__device__ __forceinline__ void ldsm_x2(uint32_t r[2], uint32_t addr) {
    asm volatile("ldmatrix.sync.aligned.m8n8.x2.shared.b16 {%0,%1}, [%2];"
        : "=r"(r[0]), "=r"(r[1]) : "r"(addr));
}
__device__ __forceinline__ void ldsm_x2t(uint32_t r[2], uint32_t addr) {
    asm volatile("ldmatrix.sync.aligned.m8n8.x2.trans.shared.b16 {%0,%1}, [%2];"
        : "=r"(r[0]), "=r"(r[1]) : "r"(addr));
}
__device__ __forceinline__ void mma_f16(float c[4], const uint32_t a[4], const uint32_t b[2]) {
    asm volatile("mma.sync.aligned.m16n8k16.row.col.f32.f16.f16.f32 "
        "{%0,%1,%2,%3}, {%4,%5,%6,%7}, {%8,%9}, {%0,%1,%2,%3};"
        : "+f"(c[0]), "+f"(c[1]), "+f"(c[2]), "+f"(c[3])
        : "r"(a[0]), "r"(a[1]), "r"(a[2]), "r"(a[3]), "r"(b[0]), "r"(b[1]));
}
__device__ __forceinline__ void cp16(uint32_t dst, const void* src) {
    asm volatile("cp.async.cg.shared.global [%0], [%1], 16;" :: "r"(dst), "l"(src));
}
__device__ __forceinline__ void cp16z(uint32_t dst, const void* src, uint32_t ssize) {
    asm volatile("cp.async.cg.shared.global [%0], [%1], 16, %2;" :: "r"(dst), "l"(src), "r"(ssize));
}
#define CP_COMMIT() asm volatile("cp.async.commit_group;" ::: "memory")
#define CP_WAIT1()  asm volatile("cp.async.wait_group 1;" ::: "memory")
__device__ __forceinline__ uint32_t pack_h2(__half a, __half b) {
    union { __half h[2]; uint32_t u; } u;
    u.h[0] = a; u.h[1] = b;
    return u.u;
}

// ================= fp16 2-pass GEMM =================
template<int TM, int EPI, bool ACC, bool WSPLIT, bool WF32>
__global__ __launch_bounds__(256, 2) void gemm_16(
    const uint16_t* __restrict__ Ah, const uint16_t* __restrict__ Al,
    const uint16_t* __restrict__ Bh,
    float* __restrict__ C, uint16_t* __restrict__ Ch, uint16_t* __restrict__ Cl,
    int M, int N, int K, int lda, int ldb, int ldc)
{
    constexpr int MT     = TM / 32;
    constexpr int A_SZ   = TM * 80;
    constexpr int B_OFF  = 2 * A_SZ;
    constexpr int STRIDE = B_OFF + 8704;

    extern __shared__ char dsm[];
    uint32_t sraw = smem_u32(dsm);
    uint32_t s0 = (sraw + 127u) & ~127u;

    int tid = threadIdx.x, wid = tid >> 5, lane = tid & 31;
    int row0 = blockIdx.x * TM, col0 = blockIdx.y * 128;
    int wm = (wid >> 2) * (TM / 2);
    int wn = (wid & 3) * 32;

    float c[MT][4][4];
    #pragma unroll
    for (int mt = 0; mt < MT; mt++)
        #pragma unroll
        for (int nt = 0; nt < 4; nt++)
            #pragma unroll
            for (int r = 0; r < 4; r++) c[mt][nt][r] = 0.f;

    int NC = K >> 5;

    auto issue_copy = [&](int i, int stg) {
        int k0 = i << 5;
        uint32_t sb = s0 + (uint32_t)stg * STRIDE;
        #pragma unroll
        for (int e = tid; e < TM * 4; e += 256) {
            int r = e >> 2, seg = e & 3;
            uint32_t d = sb + (uint32_t)(r * 80 + seg * 16);
            cp16(d,                  Ah + (size_t)(row0 + r) * lda + k0 + seg * 8);
            cp16(d + (uint32_t)A_SZ, Al + (size_t)(row0 + r) * lda + k0 + seg * 8);
        }
        #pragma unroll
        for (int e0 = 0; e0 < 2; e0++) {
            int e = tid + e0 * 256;
            int kk = e >> 4, seg = e & 15;
            int gc = col0 + seg * 8;
            uint32_t d = sb + (uint32_t)B_OFF + (uint32_t)(kk * 272 + seg * 16);
            int rem = N - gc;
            uint32_t sz = rem >= 8 ? 16u : (rem > 0 ? (uint32_t)(rem * 2) : 0u);
            cp16z(d, Bh + (size_t)(k0 + kk) * ldb + gc, sz);
        }
    };

    auto mma_chunk = [&](int stg) {
        uint32_t base = s0 + (uint32_t)stg * STRIDE;
        int arow = wm + ((lane >> 3) & 1) * 8 + (lane & 7);
        int krow = lane & 15;
        #pragma unroll
        for (int kk = 0; kk < 32; kk += 16) {
            int acol = kk + ((lane >> 4) & 1) * 8;
            uint32_t af[MT][4], bh[4][2];
            #pragma unroll
            for (int mt = 0; mt < MT; mt++)
                ldsm_x4(af[mt], base + (uint32_t)((arow + mt * 16) * 80 + acol * 2));
            #pragma unroll
            for (int nt = 0; nt < 4; nt++)
                ldsm_x2t(bh[nt], base + (uint32_t)B_OFF + (uint32_t)((kk + krow) * 272 + (wn + nt * 8) * 2));
            #pragma unroll
            for (int mt = 0; mt < MT; mt++)
                #pragma unroll
                for (int nt = 0; nt < 4; nt++)
                    mma_f16(c[mt][nt], af[mt], bh[nt]);
            #pragma unroll
            for (int mt = 0; mt < MT; mt++)
                ldsm_x4(af[mt], base + (uint32_t)A_SZ + (uint32_t)((arow + mt * 16) * 80 + acol * 2));
            #pragma unroll
            for (int mt = 0; mt < MT; mt++)
                #pragma unroll
                for (int nt = 0; nt < 4; nt++)
                    mma_f16(c[mt][nt], af[mt], bh[nt]);
        }
    };

    issue_copy(0, 0); CP_COMMIT();
    issue_copy(1, 1); CP_COMMIT();
    for (int i = 0; i < NC; i++) {
        CP_WAIT1();
        __syncthreads();
        mma_chunk(i % 3);
        if (i + 2 < NC) issue_copy(i + 2, (i + 2) % 3);
        CP_COMMIT();
    }

    #pragma unroll
    for (int mt = 0; mt < MT; mt++) {
        #pragma unroll
        for (int nt = 0; nt < 4; nt++) {
            #pragma unroll
            for (int half = 0; half < 2; half++) {
                int grow = row0 + wm + mt * 16 + (lane >> 2) + half * 8;
                int gcol = col0 + wn + nt * 8 + (lane & 3) * 2;
                float v0 = c[mt][nt][half * 2 + 0];
                float v1 = c[mt][nt][half * 2 + 1];
                if (EPI == 1) {
                    float h0 = fmaxf(v0, 0.f); v0 = h0 * h0;
                    float h1 = fmaxf(v1, 0.f); v1 = h1 * h1;
                }
                if (EPI == 2) {
                    v0 = 15.0f * tanhf(v0 * (1.0f / 15.0f));
                    v1 = 15.0f * tanhf(v1 * (1.0f / 15.0f));
                }
                if (gcol + 1 < N) {
                    size_t p = (size_t)grow * ldc + gcol;
                    if (ACC) { v0 += C[p]; v1 += C[p + 1]; }
                    if (WF32) *(float2*)(C + p) = make_float2(v0, v1);
                    if (WSPLIT) {
                        __half h0 = __float2half(v0);
                        __half h1 = __float2half(v1);
                        *(uint32_t*)(Ch + p) = pack_h2(h0, h1);
                        *(uint32_t*)(Cl + p) = pack_h2(
                            __float2half(v0 - __half2float(h0)),
                            __float2half(v1 - __half2float(h1)));
                    }
                } else if (gcol < N) {
                    size_t p = (size_t)grow * ldc + gcol;
                    if (ACC) v0 += C[p];
                    if (WF32) C[p] = v0;
                    if (WSPLIT) {
                        __half h0 = __float2half(v0);
                        Ch[p] = __half_as_ushort(h0);
                        Cl[p] = __half_as_ushort(__float2half(v0 - __half2float(h0)));
                    }
                }
            }
        }
    }
}

// ---------------- fp16 hi-only weight split ----------------
__global__ __launch_bounds__(256) void split16_kernel(
    const float* __restrict__ src, uint16_t* __restrict__ hi, int n4)
{
    int base = blockIdx.x * 1024 + threadIdx.x;
    float4 v[4]; bool ok[4];
    #pragma unroll
    for (int j = 0; j < 4; j++) {
        int i = base + j * 256;
        ok[j] = i < n4;
        if (ok[j]) v[j] = ((const float4*)src)[i];
    }
    #pragma unroll
    for (int j = 0; j < 4; j++) {
        if (!ok[j]) continue;
        int i = base + j * 256;
        float f[4] = { v[j].x, v[j].y, v[j].z, v[j].w };
        union { uint16_t h[4]; uint2 u; } ph;
        #pragma unroll
        for (int jj = 0; jj < 4; jj++)
            ph.h[jj] = __half_as_ushort(__float2half(f[jj]));
        ((uint2*)hi)[i] = ph.u;
    }
}

// ---------------- block reduce ----------------
__device__ __forceinline__ float blockReduceSum(float v) {
    __shared__ float red[32];
    int lane = threadIdx.x & 31, w = threadIdx.x >> 5;
    #pragma unroll
    for (int o = 16; o; o >>= 1) v += __shfl_xor_sync(0xffffffffu, v, o);
    if (lane == 0) red[w] = v;
    __syncthreads();
    v = (threadIdx.x < (blockDim.x >> 5)) ? red[threadIdx.x] : 0.0f;
    if (w == 0) {
        #pragma unroll
        for (int o = 16; o; o >>= 1) v += __shfl_xor_sync(0xffffffffu, v, o);
        if (lane == 0) red[0] = v;
    }
    __syncthreads();
    return red[0];
}

// ---------------- embed + norms ----------------
__global__ __launch_bounds__(256) void embed_kernel(
    const int* __restrict__ idx, const float* __restrict__ wte,
    float* __restrict__ x, float* __restrict__ x0)
{
    int i = blockIdx.x;
    const float* row = wte + (size_t)idx[i] * C_;
    float v[4]; float ss = 0.f;
    #pragma unroll
    for (int j = 0; j < 4; j++) { v[j] = row[threadIdx.x + j * 256]; ss += v[j] * v[j]; }
    ss = blockReduceSum(ss);
    float sc = rsqrtf(ss / C_ + EPSF);
    #pragma unroll
    for (int j = 0; j < 4; j++) {
        float o = v[j] * sc;
        x [(size_t)i * C_ + threadIdx.x + j * 256] = o;
        x0[(size_t)i * C_ + threadIdx.x + j * 256] = o;
    }
}

__global__ __launch_bounds__(256) void mixnorm_kernel(
    float* __restrict__ x, const float* __restrict__ x0,
    const float* __restrict__ rl, const float* __restrict__ xl, int l,
    float* __restrict__ xn, uint16_t* __restrict__ xnh, uint16_t* __restrict__ xnl)
{
    int i = blockIdx.x;
    float a = rl[l], bc = xl[l];
    float v[4]; float ss = 0.f;
    #pragma unroll
    for (int j = 0; j < 4; j++) {
        size_t p = (size_t)i * C_ + threadIdx.x + j * 256;
        v[j] = a * x[p] + bc * x0[p];
        ss += v[j] * v[j];
    }
    ss = blockReduceSum(ss);
    float sc = rsqrtf(ss / C_ + EPSF);
    #pragma unroll
    for (int j = 0; j < 4; j++) {
        size_t p = (size_t)i * C_ + threadIdx.x + j * 256;
        float o = v[j] * sc;
        x[p] = v[j];
        xn[p] = o;
        __half hv = __float2half(o);
        xnh[p] = __half_as_ushort(hv);
        xnl[p] = __half_as_ushort(__float2half(o - __half2float(hv)));
    }
}

__global__ __launch_bounds__(256) void rmsnorm16_kernel(
    const float* __restrict__ x, uint16_t* __restrict__ xnh, uint16_t* __restrict__ xnl)
{
    int i = blockIdx.x;
    float v[4]; float ss = 0.f;
    #pragma unroll
    for (int j = 0; j < 4; j++) {
        v[j] = x[(size_t)i * C_ + threadIdx.x + j * 256];
        ss += v[j] * v[j];
    }
    ss = blockReduceSum(ss);
    float sc = rsqrtf(ss / C_ + EPSF);
    #pragma unroll
    for (int j = 0; j < 4; j++) {
        size_t p = (size_t)i * C_ + threadIdx.x + j * 256;
        float o = v[j] * sc;
        __half hv = __float2half(o);
        xnh[p] = __half_as_ushort(hv);
        xnl[p] = __half_as_ushort(__float2half(o - __half2float(hv)));
    }
}

// ---------------- per-token q/k/v assembly -> fp16 ----------------
__global__ __launch_bounds__(512) void prep_kernel(
    const float* __restrict__ down, const float* __restrict__ kvb,
    const float* __restrict__ qraw, const float* __restrict__ xn,
    const float* __restrict__ cosb, const float* __restrict__ sinb,
    const float* __restrict__ vg, const float* __restrict__ vetab,
    const int* __restrict__ idx,
    uint16_t* __restrict__ Qh, uint16_t* __restrict__ Ql,
    uint16_t* __restrict__ Kh, uint16_t* __restrict__ Vh)
{
    int i = blockIdx.x;
    int b = i / T_, t = i % T_;
    int w = threadIdx.x >> 5, lane = threadIdx.x & 31;
    __shared__ float cs[16], sn[16], kr[32];

    if (threadIdx.x < 16)       cs[threadIdx.x]      = cosb[(size_t)i * 16 + threadIdx.x];
    else if (threadIdx.x < 32)  sn[threadIdx.x - 16] = sinb[(size_t)i * 16 + threadIdx.x - 16];
    __syncthreads();

    float gv = xn[(size_t)i * C_ + lane] * vg[lane * H_ + w];
    #pragma unroll
    for (int o = 16; o; o >>= 1) gv += __shfl_xor_sync(0xffffffffu, gv, o);
    float gate = 2.0f / (1.0f + expf(-gv));

    if (w == 0) {
        int j = lane & 15;
        float x1 = down[(size_t)i * DOWN + 512 + j];
        float x2 = down[(size_t)i * DOWN + 528 + j];
        float cc = cs[j], ssn = sn[j];
        kr[lane] = (lane < 16) ? (x1 * cc + x2 * ssn) : (-x1 * ssn + x2 * cc);
    }
    __syncthreads();

    const float* kvrow = kvb  + (size_t)i * KVW + w * 96;
    const float* qrow  = qraw + (size_t)i * C_  + w * 64;
    const float* verow = vetab + (size_t)idx[i] * C_ + w * 64;

    float k0v = kvrow[lane];
    float k1v = kr[lane];
    float q0v = qrow[lane];
    float q1v;
    {
        int j = lane & 15;
        float a = qrow[32 + j], bb = qrow[48 + j];
        float cc = cs[j], ssn = sn[j];
        q1v = (lane < 16) ? (a * cc + bb * ssn) : (-a * ssn + bb * cc);
    }
    float v0 = kvrow[32 + lane] + gate * verow[lane];
    float v1 = kvrow[64 + lane] + gate * verow[32 + lane];

    float kss = k0v * k0v + k1v * k1v;
    float qss = q0v * q0v + q1v * q1v;
    #pragma unroll
    for (int o = 16; o; o >>= 1) {
        kss += __shfl_xor_sync(0xffffffffu, kss, o);
        qss += __shfl_xor_sync(0xffffffffu, qss, o);
    }
    float ksc = rsqrtf(kss * (1.0f / 64.0f) + EPSF);
    float qsc = rsqrtf(qss * (1.0f / 64.0f) + EPSF);

    size_t base = ((size_t)(b * H_ + w) * T_ + t) * 64;
    float qv0 = q0v * qsc, qv1 = q1v * qsc;
    __half qh0 = __float2half(qv0), qh1 = __float2half(qv1);
    Qh[base + lane]      = __half_as_ushort(qh0);
    Qh[base + 32 + lane] = __half_as_ushort(qh1);
    Ql[base + lane]      = __half_as_ushort(__float2half(qv0 - __half2float(qh0)));
    Ql[base + 32 + lane] = __half_as_ushort(__float2half(qv1 - __half2float(qh1)));
    Kh[base + lane]      = __half_as_ushort(__float2half(k0v * ksc));
    Kh[base + 32 + lane] = __half_as_ushort(__float2half(k1v * ksc));
    Vh[base + lane]      = __half_as_ushort(__float2half(v0));
    Vh[base + 32 + lane] = __half_as_ushort(__float2half(v1));
}

// ---------------- tensor-core flash attention (causal) ----------------
// 128 threads = 4 warps; warp w owns q rows [w*16, w*16+16). KV blocks of 64.
// S = (Qh+Ql)*Kh^T (2-pass), P split hi/lo in regs, O = (Ph+Pl)*Vh (2-pass).
#define ASTR 72   // smem row stride in halfs (144B, ldsm conflict-free)
__global__ __launch_bounds__(128) void attn_tc_kernel(
    const uint16_t* __restrict__ Qh, const uint16_t* __restrict__ Ql,
    const uint16_t* __restrict__ Kh, const uint16_t* __restrict__ Vh,
    uint16_t* __restrict__ Yh, uint16_t* __restrict__ Yl)
{
    __shared__ uint16_t sqh[64 * ASTR], sql[64 * ASTR];
    __shared__ uint16_t skh[64 * ASTR], svh[64 * ASTR];

    int qt0 = blockIdx.x * 64;
    int bh  = blockIdx.y;
    int b = bh >> 4, h = bh & 15;
    size_t gbase = (size_t)bh * T_ * 64;
    int tid = threadIdx.x, wid = tid >> 5, lane = tid & 31;
    int wm = wid * 16;

    for (int e = tid; e < 1024; e += 128) {
        int r = e >> 4, c4 = (e & 15) << 2;
        *(uint2*)&sqh[r * ASTR + c4] = *(const uint2*)&Qh[gbase + (size_t)(qt0 + r) * 64 + c4];
        *(uint2*)&sql[r * ASTR + c4] = *(const uint2*)&Ql[gbase + (size_t)(qt0 + r) * 64 + c4];
    }
    __syncthreads();

    uint32_t sqh_b = smem_u32(sqh), sql_b = smem_u32(sql);
    uint32_t skh_b = smem_u32(skh), svh_b = smem_u32(svh);

    // hoist Q fragments (reused across all KV blocks)
    uint32_t qfh[4][4], qfl[4][4];
    {
        int arow = wm + (lane & 15);
        #pragma unroll
        for (int k = 0; k < 4; k++) {
            int acol = k * 16 + ((lane >> 4) & 1) * 8;
            uint32_t off = (uint32_t)((arow * ASTR + acol) * 2);
            ldsm_x4(qfh[k], sqh_b + off);
            ldsm_x4(qfl[k], sql_b + off);
        }
    }

    float m0 = -1e30f, m1 = -1e30f, l0 = 0.f, l1 = 0.f;
    float o[8][4];
    #pragma unroll
    for (int nt = 0; nt < 8; nt++)
        #pragma unroll
        for (int j = 0; j < 4; j++) o[nt][j] = 0.f;

    int r0g = qt0 + wm + (lane >> 2);
    int niter = qt0 / 64 + 1;

    for (int it = 0; it < niter; it++) {
        int kv0 = it * 64;
        __syncthreads();
        for (int e = tid; e < 1024; e += 128) {
            int r = e >> 4, c4 = (e & 15) << 2;
            *(uint2*)&skh[r * ASTR + c4] = *(const uint2*)&Kh[gbase + (size_t)(kv0 + r) * 64 + c4];
            *(uint2*)&svh[r * ASTR + c4] = *(const uint2*)&Vh[gbase + (size_t)(kv0 + r) * 64 + c4];
        }
        __syncthreads();

        // ---- S = Q @ K^T ----
        float s[8][4];
        #pragma unroll
        for (int nt = 0; nt < 8; nt++)
            #pragma unroll
            for (int j = 0; j < 4; j++) s[nt][j] = 0.f;
        #pragma unroll
        for (int k = 0; k < 4; k++) {
            #pragma unroll
            for (int nt = 0; nt < 8; nt++) {
                uint32_t bf[2];
                ldsm_x2(bf, skh_b + (uint32_t)(((nt * 8 + (lane & 7)) * ASTR
                            + k * 16 + ((lane >> 3) & 1) * 8) * 2));
                mma_f16(s[nt], qfh[k], bf);
                mma_f16(s[nt], qfl[k], bf);
            }
        }

        // ---- scale + causal mask ----
        bool edge = (kv0 == qt0);
        #pragma unroll
        for (int nt = 0; nt < 8; nt++) {
            #pragma unroll
            for (int j = 0; j < 4; j++) s[nt][j] *= 0.125f;
            if (edge) {
                int c0 = kv0 + nt * 8 + 2 * (lane & 3);
                if (c0     > r0g)     s[nt][0] = -1e30f;
                if (c0 + 1 > r0g)     s[nt][1] = -1e30f;
                if (c0     > r0g + 8) s[nt][2] = -1e30f;
                if (c0 + 1 > r0g + 8) s[nt][3] = -1e30f;
            }
        }

        // ---- online softmax (rows g, g+8) ----
        float rm0 = -1e30f, rm1 = -1e30f;
        #pragma unroll
        for (int nt = 0; nt < 8; nt++) {
            rm0 = fmaxf(rm0, fmaxf(s[nt][0], s[nt][1]));
            rm1 = fmaxf(rm1, fmaxf(s[nt][2], s[nt][3]));
        }
        rm0 = fmaxf(rm0, __shfl_xor_sync(0xffffffffu, rm0, 1));
        rm0 = fmaxf(rm0, __shfl_xor_sync(0xffffffffu, rm0, 2));
        rm1 = fmaxf(rm1, __shfl_xor_sync(0xffffffffu, rm1, 1));
        rm1 = fmaxf(rm1, __shfl_xor_sync(0xffffffffu, rm1, 2));
        float mn0 = fmaxf(m0, rm0), mn1 = fmaxf(m1, rm1);
        float corr0 = __expf(m0 - mn0), corr1 = __expf(m1 - mn1);
        m0 = mn0; m1 = mn1;
        float sum0 = 0.f, sum1 = 0.f;
        #pragma unroll
        for (int nt = 0; nt < 8; nt++) {
            s[nt][0] = __expf(s[nt][0] - mn0);
            s[nt][1] = __expf(s[nt][1] - mn0);
            s[nt][2] = __expf(s[nt][2] - mn1);
            s[nt][3] = __expf(s[nt][3] - mn1);
            sum0 += s[nt][0] + s[nt][1];
            sum1 += s[nt][2] + s[nt][3];
        }
        sum0 += __shfl_xor_sync(0xffffffffu, sum0, 1);
        sum0 += __shfl_xor_sync(0xffffffffu, sum0, 2);
        sum1 += __shfl_xor_sync(0xffffffffu, sum1, 1);
        sum1 += __shfl_xor_sync(0xffffffffu, sum1, 2);
        l0 = l0 * corr0 + sum0;
        l1 = l1 * corr1 + sum1;
        #pragma unroll
        for (int nt = 0; nt < 8; nt++) {
            o[nt][0] *= corr0; o[nt][1] *= corr0;
            o[nt][2] *= corr1; o[nt][3] *= corr1;
        }

        // ---- O += P @ V (P hi/lo from regs) ----
        #pragma unroll
        for (int k = 0; k < 4; k++) {
            uint32_t ph[4], pl[4];
            {
                float a0 = s[2*k][0],   a1 = s[2*k][1],   a2 = s[2*k][2],   a3 = s[2*k][3];
                float b0 = s[2*k+1][0], b1 = s[2*k+1][1], b2 = s[2*k+1][2], b3 = s[2*k+1][3];
                __half ha0 = __float2half(a0), ha1 = __float2half(a1);
                __half ha2 = __float2half(a2), ha3 = __float2half(a3);
                __half hb0 = __float2half(b0), hb1 = __float2half(b1);
                __half hb2 = __float2half(b2), hb3 = __float2half(b3);
                ph[0] = pack_h2(ha0, ha1); ph[1] = pack_h2(ha2, ha3);
                ph[2] = pack_h2(hb0, hb1); ph[3] = pack_h2(hb2, hb3);
                pl[0] = pack_h2(__float2half(a0 - __half2float(ha0)), __float2half(a1 - __half2float(ha1)));
                pl[1] = pack_h2(__float2half(a2 - __half2float(ha2)), __float2half(a3 - __half2float(ha3)));
                pl[2] = pack_h2(__float2half(b0 - __half2float(hb0)), __float2half(b1 - __half2float(hb1)));
                pl[3] = pack_h2(__float2half(b2 - __half2float(hb2)), __float2half(b3 - __half2float(hb3)));
            }
            #pragma unroll
            for (int nt = 0; nt < 8; nt++) {
                uint32_t bf[2];
                ldsm_x2t(bf, svh_b + (uint32_t)(((k * 16 + (lane & 15)) * ASTR + nt * 8) * 2));
                mma_f16(o[nt], ph, bf);
                mma_f16(o[nt], pl, bf);
            }
        }
    }

    // ---- epilogue: y fp16 hi/lo ----
    float inv0 = 1.0f / l0, inv1 = 1.0f / l1;
    #pragma unroll
    for (int nt = 0; nt < 8; nt++) {
        int col = h * 64 + nt * 8 + 2 * (lane & 3);
        size_t p0 = ((size_t)(b * T_ + r0g)) * C_ + col;
        size_t p1 = ((size_t)(b * T_ + r0g + 8)) * C_ + col;
        float v0 = o[nt][0] * inv0, v1 = o[nt][1] * inv0;
        float v2 = o[nt][2] * inv1, v3 = o[nt][3] * inv1;
        __half h0 = __float2half(v0), h1 = __float2half(v1);
        __half h2 = __float2half(v2), h3 = __float2half(v3);
        *(uint32_t*)(Yh + p0) = pack_h2(h0, h1);
        *(uint32_t*)(Yl + p0) = pack_h2(
            __float2half(v0 - __half2float(h0)), __float2half(v1 - __half2float(h1)));
        *(uint32_t*)(Yh + p1) = pack_h2(h2, h3);
        *(uint32_t*)(Yl + p1) = pack_h2(
            __float2half(v2 - __half2float(h2)), __float2half(v3 - __half2float(h3)));
    }
}

// ---------------- host side ----------------
template<typename Tp>
static Tp* sym_addr(const void* sym) {
    void* p = nullptr;
    cudaGetSymbolAddress(&p, sym);
    return (Tp*)p;
}

struct GemmArgs {
    const uint16_t *Ah, *Al, *Bh;
    float* C; uint16_t *Ch, *Cl;
    int M, N, K, lda, ldb, ldc;
};

template<int TM, int EPI, bool ACC, bool WSPLIT, bool WF32>
static void launch_g(const GemmArgs& a) {
    constexpr int STRIDE = (2 * TM * 80) + 8704;
    constexpr int DSMEM  = 3 * STRIDE + 128;
    static bool done = false;
    if (!done) {
        cudaFuncSetAttribute(gemm_16<TM, EPI, ACC, WSPLIT, WF32>,
                             cudaFuncAttributeMaxDynamicSharedMemorySize, DSMEM);
        done = true;
    }
    dim3 grid(a.M / TM, (a.N + 127) / 128);
    gemm_16<TM, EPI, ACC, WSPLIT, WF32><<<grid, 256, DSMEM>>>(
        a.Ah, a.Al, a.Bh, a.C, a.Ch, a.Cl, a.M, a.N, a.K, a.lda, a.ldb, a.ldc);
}

static void split_w16(const float* src, uint16_t* hi, size_t n) {
    int n4 = (int)(n / 4);
    split16_kernel<<<(n4 + 1023) / 1024, 256>>>(src, hi, n4);
}

extern "C" void kernel_launch(void* const* d_in, const int* in_sizes, int n_in,
                              void* d_out, int out_size)
{
    (void)in_sizes; (void)n_in; (void)out_size;
    const int*   idx   = (const int*)  d_in[0];
    const float* cosb  = (const float*)d_in[1];
    const float* sinb  = (const float*)d_in[2];
    const float* wte   = (const float*)d_in[3];
    const float* vetab = (const float*)d_in[4];
    const float* wd    = (const float*)d_in[5];
    const float* wukv  = (const float*)d_in[6];
    const float* wuq   = (const float*)d_in[7];
    const float* vg    = (const float*)d_in[8];
    const float* ap    = (const float*)d_in[9];
    const float* fc    = (const float*)d_in[10];
    const float* pj    = (const float*)d_in[11];
    const float* rl    = (const float*)d_in[12];
    const float* xl    = (const float*)d_in[13];
    const float* lmh   = (const float*)d_in[14];
    float* out = (float*)d_out;

    float* px    = sym_addr<float>(g_x);
    float* px0   = sym_addr<float>(g_x0);
    float* pxn   = sym_addr<float>(g_xn);
    float* pdown = sym_addr<float>(g_down);
    float* pkv   = sym_addr<float>(g_kv);
    float* pqraw = sym_addr<float>(g_qraw);

    uint16_t *pqh = sym_addr<uint16_t>(g_qh), *pql = sym_addr<uint16_t>(g_ql);
    uint16_t *pkh = sym_addr<uint16_t>(g_kh), *pvh = sym_addr<uint16_t>(g_vh);

    uint16_t *wdh = sym_addr<uint16_t>(s_wd_h);
    uint16_t *ukh = sym_addr<uint16_t>(s_wukv_h);
    uint16_t *uqh = sym_addr<uint16_t>(s_wuq_h);
    uint16_t *aph = sym_addr<uint16_t>(s_ap_h);
    uint16_t *fch = sym_addr<uint16_t>(s_fc_h);
    uint16_t *pjh = sym_addr<uint16_t>(s_pj_h);
    uint16_t *lmhh = sym_addr<uint16_t>(s_lmh_h);
    uint16_t *xnh = sym_addr<uint16_t>(s_xn_h), *xnl = sym_addr<uint16_t>(s_xn_l);
    uint16_t *dnh = sym_addr<uint16_t>(s_dn_h), *dnl = sym_addr<uint16_t>(s_dn_l);
    uint16_t *hhh = sym_addr<uint16_t>(s_h_h),  *hhl = sym_addr<uint16_t>(s_h_l);
    uint16_t *yh  = sym_addr<uint16_t>(s_y_h),  *yl  = sym_addr<uint16_t>(s_y_l);

    split_w16(wd,   wdh,  (size_t)L_ * C_ * DOWN);
    split_w16(wukv, ukh,  (size_t)L_ * DC * KVW);
    split_w16(wuq,  uqh,  (size_t)L_ * DC1 * C_);
    split_w16(ap,   aph,  (size_t)L_ * C_ * C_);
    split_w16(fc,   fch,  (size_t)L_ * C_ * 4096);
    split_w16(pj,   pjh,  (size_t)L_ * 4096 * C_);
    split_w16(lmh,  lmhh, (size_t)C_ * VSZ);

    embed_kernel<<<TKN, 256>>>(idx, wte, px, px0);

    for (int l = 0; l < L_; l++) {
        mixnorm_kernel<<<TKN, 256>>>(px, px0, rl, xl, l, pxn, xnh, xnl);

        launch_g<64, 0, false, true, true>({ xnh, xnl,
            wdh + (size_t)l * C_ * DOWN,
            pdown, dnh, dnl, TKN, DOWN, C_, C_, DOWN, DOWN });
        launch_g<64, 0, false, false, true>({ dnh, dnl,
            ukh + (size_t)l * DC * KVW,
            pkv, nullptr, nullptr, TKN, KVW, DC, DOWN, KVW, KVW });
        launch_g<64, 0, false, false, true>({ dnh + DC, dnl + DC,
            uqh + (size_t)l * DC1 * C_,
            pqraw, nullptr, nullptr, TKN, C_, DC1, DOWN, C_, C_ });

        prep_kernel<<<TKN, 512>>>(pdown, pkv, pqraw, pxn, cosb, sinb,
                                  vg + (size_t)l * GC * H_,
                                  vetab + (size_t)l * VSZ * C_,
                                  idx, pqh, pql, pkh, pvh);

        attn_tc_kernel<<<dim3(T_ / 64, B_ * H_), 128>>>(pqh, pql, pkh, pvh, yh, yl);

        launch_g<64, 0, true, false, true>({ yh, yl,
            aph + (size_t)l * C_ * C_,
            px, nullptr, nullptr, TKN, C_, C_, C_, C_, C_ });

        rmsnorm16_kernel<<<TKN, 256>>>(px, xnh, xnl);

        launch_g<128, 1, false, true, false>({ xnh, xnl,
            fch + (size_t)l * C_ * 4096,
            nullptr, hhh, hhl, TKN, 4096, C_, C_, 4096, 4096 });
        launch_g<64, 0, true, false, true>({ hhh, hhl,
            pjh + (size_t)l * 4096 * C_,
            px, nullptr, nullptr, TKN, C_, 4096, 4096, C_, C_ });
    }

    rmsnorm16_kernel<<<TKN, 256>>>(px, xnh, xnl);
    launch_g<128, 2, false, false, true>({ xnh, xnl, lmhh,
        out, nullptr, nullptr, TKN, VSZ, C_, C_, VSZ, VSZ });
}

// round 13
// speedup vs baseline: 7.0063x; 1.3996x over previous
#include <cuda_runtime.h>
#include <cuda_bf16.h>
#include <cuda_fp16.h>
#include <math.h>
#include <stdint.h>

// ---------------- problem constants ----------------
#define B_    2
#define T_    1024
#define C_    1024
#define H_    16
#define HD_   64
#define DC    256
#define DC1   256
#define DR    32
#define DN    32
#define DOWN  544
#define VSZ   32000
#define L_    4
#define GC    32
#define TKN   2048
#define KVW   1536
#define EPSF  1.1920929e-7f

// ---------------- fp32 scratch ----------------
__device__ float g_x   [TKN * C_];
__device__ float g_x0  [TKN * C_];
__device__ float g_xn  [TKN * C_];
__device__ float g_down[TKN * DOWN];
__device__ float g_kv  [TKN * KVW];
__device__ float g_qraw[TKN * C_];

// ---------------- fp16 attention tensors [bh][T][64] ----------------
__device__ uint16_t g_qh[B_ * H_ * T_ * HD_], g_ql[B_ * H_ * T_ * HD_];
__device__ uint16_t g_kh[B_ * H_ * T_ * HD_];
__device__ uint16_t g_vh[B_ * H_ * T_ * HD_];

// ---------------- fp16 buffers (uint16_t = fp16 bits) ----------------
__device__ uint16_t s_wd_h  [L_ * C_ * DOWN];
__device__ uint16_t s_wukv_h[L_ * DC * KVW];
__device__ uint16_t s_wuq_h [L_ * DC1 * C_];
__device__ uint16_t s_ap_h  [L_ * C_ * C_];
__device__ uint16_t s_fc_h  [L_ * C_ * 4096];
__device__ uint16_t s_pj_h  [L_ * 4096 * C_];
__device__ uint16_t s_lmh_h [C_ * VSZ];
__device__ uint16_t s_xn_h  [TKN * C_];
__device__ uint16_t s_dn_h  [TKN * DOWN];
__device__ uint16_t s_h_h   [TKN * 4096];
__device__ uint16_t s_y_h   [TKN * C_];

// ================= helpers =================
__device__ __forceinline__ uint32_t smem_u32(const void* p) {
    uint32_t a;
    asm("{ .reg .u64 t; cvta.to.shared.u64 t, %1; cvt.u32.u64 %0, t; }" : "=r"(a) : "l"(p));
    return a;
}
__device__ __forceinline__ void ldsm_x4(uint32_t r[4], uint32_t addr) {
    asm volatile("ldmatrix.sync.aligned.m8n8.x4.shared.b16 {%0,%1,%2,%3}, [%4];"
        : "=r"(r[0]), "=r"(r[1]), "=r"(r[2]), "=r"(r[3]) : "r"(addr));
}
__device__ __forceinline__ void ldsm_x2(uint32_t r[2], uint32_t addr) {
    asm volatile("ldmatrix.sync.aligned.m8n8.x2.shared.b16 {%0,%1}, [%2];"
        : "=r"(r[0]), "=r"(r[1]) : "r"(addr));
}
__device__ __forceinline__ void ldsm_x2t(uint32_t r[2], uint32_t addr) {
    asm volatile("ldmatrix.sync.aligned.m8n8.x2.trans.shared.b16 {%0,%1}, [%2];"
        : "=r"(r[0]), "=r"(r[1]) : "r"(addr));
}
__device__ __forceinline__ void mma_f16(float c[4], const uint32_t a[4], const uint32_t b[2]) {
    asm volatile("mma.sync.aligned.m16n8k16.row.col.f32.f16.f16.f32 "
        "{%0,%1,%2,%3}, {%4,%5,%6,%7}, {%8,%9}, {%0,%1,%2,%3};"
        : "+f"(c[0]), "+f"(c[1]), "+f"(c[2]), "+f"(c[3])
        : "r"(a[0]), "r"(a[1]), "r"(a[2]), "r"(a[3]), "r"(b[0]), "r"(b[1]));
}
__device__ __forceinline__ void cp16(uint32_t dst, const void* src) {
    asm volatile("cp.async.cg.shared.global [%0], [%1], 16;" :: "r"(dst), "l"(src));
}
__device__ __forceinline__ void cp16z(uint32_t dst, const void* src, uint32_t ssize) {
    asm volatile("cp.async.cg.shared.global [%0], [%1], 16, %2;" :: "r"(dst), "l"(src), "r"(ssize));
}
#define CP_COMMIT() asm volatile("cp.async.commit_group;" ::: "memory")
#define CP_WAIT1()  asm volatile("cp.async.wait_group 1;" ::: "memory")
__device__ __forceinline__ uint32_t pack_h2(__half a, __half b) {
    union { __half h[2]; uint32_t u; } u;
    u.h[0] = a; u.h[1] = b;
    return u.u;
}

// ================= fp16 single-pass GEMM =================
// C[M,N] = fp16(A)[M,K] @ fp16(B)[K,N], fp32 accumulate.
// smem per stage: A[TM][40] | B[32][136]
template<int TM, int EPI, bool ACC, bool WSPLIT, bool WF32>
__global__ __launch_bounds__(256, 2) void gemm_16(
    const uint16_t* __restrict__ Ah, const uint16_t* __restrict__ Bh,
    float* __restrict__ C, uint16_t* __restrict__ Ch,
    int M, int N, int K, int lda, int ldb, int ldc)
{
    constexpr int MT     = TM / 32;
    constexpr int A_SZ   = TM * 80;
    constexpr int STRIDE = A_SZ + 8704;

    extern __shared__ char dsm[];
    uint32_t sraw = smem_u32(dsm);
    uint32_t s0 = (sraw + 127u) & ~127u;

    int tid = threadIdx.x, wid = tid >> 5, lane = tid & 31;
    int row0 = blockIdx.x * TM, col0 = blockIdx.y * 128;
    int wm = (wid >> 2) * (TM / 2);
    int wn = (wid & 3) * 32;

    float c[MT][4][4];
    #pragma unroll
    for (int mt = 0; mt < MT; mt++)
        #pragma unroll
        for (int nt = 0; nt < 4; nt++)
            #pragma unroll
            for (int r = 0; r < 4; r++) c[mt][nt][r] = 0.f;

    int NC = K >> 5;

    auto issue_copy = [&](int i, int stg) {
        int k0 = i << 5;
        uint32_t sb = s0 + (uint32_t)stg * STRIDE;
        #pragma unroll
        for (int e = tid; e < TM * 4; e += 256) {
            int r = e >> 2, seg = e & 3;
            cp16(sb + (uint32_t)(r * 80 + seg * 16),
                 Ah + (size_t)(row0 + r) * lda + k0 + seg * 8);
        }
        #pragma unroll
        for (int e0 = 0; e0 < 2; e0++) {
            int e = tid + e0 * 256;
            int kk = e >> 4, seg = e & 15;
            int gc = col0 + seg * 8;
            uint32_t d = sb + (uint32_t)A_SZ + (uint32_t)(kk * 272 + seg * 16);
            int rem = N - gc;
            uint32_t sz = rem >= 8 ? 16u : (rem > 0 ? (uint32_t)(rem * 2) : 0u);
            cp16z(d, Bh + (size_t)(k0 + kk) * ldb + gc, sz);
        }
    };

    auto mma_chunk = [&](int stg) {
        uint32_t base = s0 + (uint32_t)stg * STRIDE;
        int arow = wm + ((lane >> 3) & 1) * 8 + (lane & 7);
        int krow = lane & 15;
        #pragma unroll
        for (int kk = 0; kk < 32; kk += 16) {
            int acol = kk + ((lane >> 4) & 1) * 8;
            uint32_t af[MT][4], bh[4][2];
            #pragma unroll
            for (int mt = 0; mt < MT; mt++)
                ldsm_x4(af[mt], base + (uint32_t)((arow + mt * 16) * 80 + acol * 2));
            #pragma unroll
            for (int nt = 0; nt < 4; nt++)
                ldsm_x2t(bh[nt], base + (uint32_t)A_SZ + (uint32_t)((kk + krow) * 272 + (wn + nt * 8) * 2));
            #pragma unroll
            for (int mt = 0; mt < MT; mt++)
                #pragma unroll
                for (int nt = 0; nt < 4; nt++)
                    mma_f16(c[mt][nt], af[mt], bh[nt]);
        }
    };

    issue_copy(0, 0); CP_COMMIT();
    issue_copy(1, 1); CP_COMMIT();
    for (int i = 0; i < NC; i++) {
        CP_WAIT1();
        __syncthreads();
        mma_chunk(i % 3);
        if (i + 2 < NC) issue_copy(i + 2, (i + 2) % 3);
        CP_COMMIT();
    }

    // ---- epilogue ----
    #pragma unroll
    for (int mt = 0; mt < MT; mt++) {
        #pragma unroll
        for (int nt = 0; nt < 4; nt++) {
            #pragma unroll
            for (int half = 0; half < 2; half++) {
                int grow = row0 + wm + mt * 16 + (lane >> 2) + half * 8;
                int gcol = col0 + wn + nt * 8 + (lane & 3) * 2;
                float v0 = c[mt][nt][half * 2 + 0];
                float v1 = c[mt][nt][half * 2 + 1];
                if (EPI == 1) {
                    float h0 = fmaxf(v0, 0.f); v0 = h0 * h0;
                    float h1 = fmaxf(v1, 0.f); v1 = h1 * h1;
                }
                if (EPI == 2) {
                    v0 = 15.0f * tanhf(v0 * (1.0f / 15.0f));
                    v1 = 15.0f * tanhf(v1 * (1.0f / 15.0f));
                }
                if (gcol + 1 < N) {
                    size_t p = (size_t)grow * ldc + gcol;
                    if (ACC) { v0 += C[p]; v1 += C[p + 1]; }
                    if (WF32) *(float2*)(C + p) = make_float2(v0, v1);
                    if (WSPLIT)
                        *(uint32_t*)(Ch + p) = pack_h2(__float2half(v0), __float2half(v1));
                } else if (gcol < N) {
                    size_t p = (size_t)grow * ldc + gcol;
                    if (ACC) v0 += C[p];
                    if (WF32) C[p] = v0;
                    if (WSPLIT) Ch[p] = __half_as_ushort(__float2half(v0));
                }
            }
        }
    }
}

// ---------------- fp16 hi-only weight split ----------------
__global__ __launch_bounds__(256) void split16_kernel(
    const float* __restrict__ src, uint16_t* __restrict__ hi, int n4)
{
    int base = blockIdx.x * 1024 + threadIdx.x;
    float4 v[4]; bool ok[4];
    #pragma unroll
    for (int j = 0; j < 4; j++) {
        int i = base + j * 256;
        ok[j] = i < n4;
        if (ok[j]) v[j] = ((const float4*)src)[i];
    }
    #pragma unroll
    for (int j = 0; j < 4; j++) {
        if (!ok[j]) continue;
        int i = base + j * 256;
        float f[4] = { v[j].x, v[j].y, v[j].z, v[j].w };
        union { uint16_t h[4]; uint2 u; } ph;
        #pragma unroll
        for (int jj = 0; jj < 4; jj++)
            ph.h[jj] = __half_as_ushort(__float2half(f[jj]));
        ((uint2*)hi)[i] = ph.u;
    }
}

// ---------------- block reduce ----------------
__device__ __forceinline__ float blockReduceSum(float v) {
    __shared__ float red[32];
    int lane = threadIdx.x & 31, w = threadIdx.x >> 5;
    #pragma unroll
    for (int o = 16; o; o >>= 1) v += __shfl_xor_sync(0xffffffffu, v, o);
    if (lane == 0) red[w] = v;
    __syncthreads();
    v = (threadIdx.x < (blockDim.x >> 5)) ? red[threadIdx.x] : 0.0f;
    if (w == 0) {
        #pragma unroll
        for (int o = 16; o; o >>= 1) v += __shfl_xor_sync(0xffffffffu, v, o);
        if (lane == 0) red[0] = v;
    }
    __syncthreads();
    return red[0];
}

// ---------------- embed + norms ----------------
__global__ __launch_bounds__(256) void embed_kernel(
    const int* __restrict__ idx, const float* __restrict__ wte,
    float* __restrict__ x, float* __restrict__ x0)
{
    int i = blockIdx.x;
    const float* row = wte + (size_t)idx[i] * C_;
    float v[4]; float ss = 0.f;
    #pragma unroll
    for (int j = 0; j < 4; j++) { v[j] = row[threadIdx.x + j * 256]; ss += v[j] * v[j]; }
    ss = blockReduceSum(ss);
    float sc = rsqrtf(ss / C_ + EPSF);
    #pragma unroll
    for (int j = 0; j < 4; j++) {
        float o = v[j] * sc;
        x [(size_t)i * C_ + threadIdx.x + j * 256] = o;
        x0[(size_t)i * C_ + threadIdx.x + j * 256] = o;
    }
}

// mix + norm -> fp32 xn + fp16 hi
__global__ __launch_bounds__(256) void mixnorm_kernel(
    float* __restrict__ x, const float* __restrict__ x0,
    const float* __restrict__ rl, const float* __restrict__ xl, int l,
    float* __restrict__ xn, uint16_t* __restrict__ xnh)
{
    int i = blockIdx.x;
    float a = rl[l], bc = xl[l];
    float v[4]; float ss = 0.f;
    #pragma unroll
    for (int j = 0; j < 4; j++) {
        size_t p = (size_t)i * C_ + threadIdx.x + j * 256;
        v[j] = a * x[p] + bc * x0[p];
        ss += v[j] * v[j];
    }
    ss = blockReduceSum(ss);
    float sc = rsqrtf(ss / C_ + EPSF);
    #pragma unroll
    for (int j = 0; j < 4; j++) {
        size_t p = (size_t)i * C_ + threadIdx.x + j * 256;
        float o = v[j] * sc;
        x[p] = v[j];
        xn[p] = o;
        xnh[p] = __half_as_ushort(__float2half(o));
    }
}

// rmsnorm -> fp16 hi
__global__ __launch_bounds__(256) void rmsnorm16_kernel(
    const float* __restrict__ x, uint16_t* __restrict__ xnh)
{
    int i = blockIdx.x;
    float v[4]; float ss = 0.f;
    #pragma unroll
    for (int j = 0; j < 4; j++) {
        v[j] = x[(size_t)i * C_ + threadIdx.x + j * 256];
        ss += v[j] * v[j];
    }
    ss = blockReduceSum(ss);
    float sc = rsqrtf(ss / C_ + EPSF);
    #pragma unroll
    for (int j = 0; j < 4; j++) {
        size_t p = (size_t)i * C_ + threadIdx.x + j * 256;
        xnh[p] = __half_as_ushort(__float2half(v[j] * sc));
    }
}

// ---------------- per-token q/k/v assembly -> fp16 ----------------
__global__ __launch_bounds__(512) void prep_kernel(
    const float* __restrict__ down, const float* __restrict__ kvb,
    const float* __restrict__ qraw, const float* __restrict__ xn,
    const float* __restrict__ cosb, const float* __restrict__ sinb,
    const float* __restrict__ vg, const float* __restrict__ vetab,
    const int* __restrict__ idx,
    uint16_t* __restrict__ Qh, uint16_t* __restrict__ Ql,
    uint16_t* __restrict__ Kh, uint16_t* __restrict__ Vh)
{
    int i = blockIdx.x;
    int b = i / T_, t = i % T_;
    int w = threadIdx.x >> 5, lane = threadIdx.x & 31;
    __shared__ float cs[16], sn[16], kr[32];

    if (threadIdx.x < 16)       cs[threadIdx.x]      = cosb[(size_t)i * 16 + threadIdx.x];
    else if (threadIdx.x < 32)  sn[threadIdx.x - 16] = sinb[(size_t)i * 16 + threadIdx.x - 16];
    __syncthreads();

    float gv = xn[(size_t)i * C_ + lane] * vg[lane * H_ + w];
    #pragma unroll
    for (int o = 16; o; o >>= 1) gv += __shfl_xor_sync(0xffffffffu, gv, o);
    float gate = 2.0f / (1.0f + expf(-gv));

    if (w == 0) {
        int j = lane & 15;
        float x1 = down[(size_t)i * DOWN + 512 + j];
        float x2 = down[(size_t)i * DOWN + 528 + j];
        float cc = cs[j], ssn = sn[j];
        kr[lane] = (lane < 16) ? (x1 * cc + x2 * ssn) : (-x1 * ssn + x2 * cc);
    }
    __syncthreads();

    const float* kvrow = kvb  + (size_t)i * KVW + w * 96;
    const float* qrow  = qraw + (size_t)i * C_  + w * 64;
    const float* verow = vetab + (size_t)idx[i] * C_ + w * 64;

    float k0v = kvrow[lane];
    float k1v = kr[lane];
    float q0v = qrow[lane];
    float q1v;
    {
        int j = lane & 15;
        float a = qrow[32 + j], bb = qrow[48 + j];
        float cc = cs[j], ssn = sn[j];
        q1v = (lane < 16) ? (a * cc + bb * ssn) : (-a * ssn + bb * cc);
    }
    float v0 = kvrow[32 + lane] + gate * verow[lane];
    float v1 = kvrow[64 + lane] + gate * verow[32 + lane];

    float kss = k0v * k0v + k1v * k1v;
    float qss = q0v * q0v + q1v * q1v;
    #pragma unroll
    for (int o = 16; o; o >>= 1) {
        kss += __shfl_xor_sync(0xffffffffu, kss, o);
        qss += __shfl_xor_sync(0xffffffffu, qss, o);
    }
    float ksc = rsqrtf(kss * (1.0f / 64.0f) + EPSF);
    float qsc = rsqrtf(qss * (1.0f / 64.0f) + EPSF);

    size_t base = ((size_t)(b * H_ + w) * T_ + t) * 64;
    float qv0 = q0v * qsc, qv1 = q1v * qsc;
    __half qh0 = __float2half(qv0), qh1 = __float2half(qv1);
    Qh[base + lane]      = __half_as_ushort(qh0);
    Qh[base + 32 + lane] = __half_as_ushort(qh1);
    Ql[base + lane]      = __half_as_ushort(__float2half(qv0 - __half2float(qh0)));
    Ql[base + 32 + lane] = __half_as_ushort(__float2half(qv1 - __half2float(qh1)));
    Kh[base + lane]      = __half_as_ushort(__float2half(k0v * ksc));
    Kh[base + 32 + lane] = __half_as_ushort(__float2half(k1v * ksc));
    Vh[base + lane]      = __half_as_ushort(__float2half(v0));
    Vh[base + 32 + lane] = __half_as_ushort(__float2half(v1));
}

// ---------------- tensor-core flash attention (causal) ----------------
#define ASTR 72
__global__ __launch_bounds__(128) void attn_tc_kernel(
    const uint16_t* __restrict__ Qh, const uint16_t* __restrict__ Ql,
    const uint16_t* __restrict__ Kh, const uint16_t* __restrict__ Vh,
    uint16_t* __restrict__ Yh)
{
    __shared__ uint16_t sqh[64 * ASTR], sql[64 * ASTR];
    __shared__ uint16_t skh[64 * ASTR], svh[64 * ASTR];

    int qt0 = blockIdx.x * 64;
    int bh  = blockIdx.y;
    int b = bh >> 4, h = bh & 15;
    size_t gbase = (size_t)bh * T_ * 64;
    int tid = threadIdx.x, wid = tid >> 5, lane = tid & 31;
    int wm = wid * 16;

    for (int e = tid; e < 1024; e += 128) {
        int r = e >> 4, c4 = (e & 15) << 2;
        *(uint2*)&sqh[r * ASTR + c4] = *(const uint2*)&Qh[gbase + (size_t)(qt0 + r) * 64 + c4];
        *(uint2*)&sql[r * ASTR + c4] = *(const uint2*)&Ql[gbase + (size_t)(qt0 + r) * 64 + c4];
    }
    __syncthreads();

    uint32_t sqh_b = smem_u32(sqh), sql_b = smem_u32(sql);
    uint32_t skh_b = smem_u32(skh), svh_b = smem_u32(svh);

    uint32_t qfh[4][4], qfl[4][4];
    {
        int arow = wm + (lane & 15);
        #pragma unroll
        for (int k = 0; k < 4; k++) {
            int acol = k * 16 + ((lane >> 4) & 1) * 8;
            uint32_t off = (uint32_t)((arow * ASTR + acol) * 2);
            ldsm_x4(qfh[k], sqh_b + off);
            ldsm_x4(qfl[k], sql_b + off);
        }
    }

    float m0 = -1e30f, m1 = -1e30f, l0 = 0.f, l1 = 0.f;
    float o[8][4];
    #pragma unroll
    for (int nt = 0; nt < 8; nt++)
        #pragma unroll
        for (int j = 0; j < 4; j++) o[nt][j] = 0.f;

    int r0g = qt0 + wm + (lane >> 2);
    int niter = qt0 / 64 + 1;

    for (int it = 0; it < niter; it++) {
        int kv0 = it * 64;
        __syncthreads();
        for (int e = tid; e < 1024; e += 128) {
            int r = e >> 4, c4 = (e & 15) << 2;
            *(uint2*)&skh[r * ASTR + c4] = *(const uint2*)&Kh[gbase + (size_t)(kv0 + r) * 64 + c4];
            *(uint2*)&svh[r * ASTR + c4] = *(const uint2*)&Vh[gbase + (size_t)(kv0 + r) * 64 + c4];
        }
        __syncthreads();

        float s[8][4];
        #pragma unroll
        for (int nt = 0; nt < 8; nt++)
            #pragma unroll
            for (int j = 0; j < 4; j++) s[nt][j] = 0.f;
        #pragma unroll
        for (int k = 0; k < 4; k++) {
            #pragma unroll
            for (int nt = 0; nt < 8; nt++) {
                uint32_t bf[2];
                ldsm_x2(bf, skh_b + (uint32_t)(((nt * 8 + (lane & 7)) * ASTR
                            + k * 16 + ((lane >> 3) & 1) * 8) * 2));
                mma_f16(s[nt], qfh[k], bf);
                mma_f16(s[nt], qfl[k], bf);
            }
        }

        bool edge = (kv0 == qt0);
        #pragma unroll
        for (int nt = 0; nt < 8; nt++) {
            #pragma unroll
            for (int j = 0; j < 4; j++) s[nt][j] *= 0.125f;
            if (edge) {
                int c0 = kv0 + nt * 8 + 2 * (lane & 3);
                if (c0     > r0g)     s[nt][0] = -1e30f;
                if (c0 + 1 > r0g)     s[nt][1] = -1e30f;
                if (c0     > r0g + 8) s[nt][2] = -1e30f;
                if (c0 + 1 > r0g + 8) s[nt][3] = -1e30f;
            }
        }

        float rm0 = -1e30f, rm1 = -1e30f;
        #pragma unroll
        for (int nt = 0; nt < 8; nt++) {
            rm0 = fmaxf(rm0, fmaxf(s[nt][0], s[nt][1]));
            rm1 = fmaxf(rm1, fmaxf(s[nt][2], s[nt][3]));
        }
        rm0 = fmaxf(rm0, __shfl_xor_sync(0xffffffffu, rm0, 1));
        rm0 = fmaxf(rm0, __shfl_xor_sync(0xffffffffu, rm0, 2));
        rm1 = fmaxf(rm1, __shfl_xor_sync(0xffffffffu, rm1, 1));
        rm1 = fmaxf(rm1, __shfl_xor_sync(0xffffffffu, rm1, 2));
        float mn0 = fmaxf(m0, rm0), mn1 = fmaxf(m1, rm1);
        float corr0 = __expf(m0 - mn0), corr1 = __expf(m1 - mn1);
        m0 = mn0; m1 = mn1;
        float sum0 = 0.f, sum1 = 0.f;
        #pragma unroll
        for (int nt = 0; nt < 8; nt++) {
            s[nt][0] = __expf(s[nt][0] - mn0);
            s[nt][1] = __expf(s[nt][1] - mn0);
            s[nt][2] = __expf(s[nt][2] - mn1);
            s[nt][3] = __expf(s[nt][3] - mn1);
            sum0 += s[nt][0] + s[nt][1];
            sum1 += s[nt][2] + s[nt][3];
        }
        sum0 += __shfl_xor_sync(0xffffffffu, sum0, 1);
        sum0 += __shfl_xor_sync(0xffffffffu, sum0, 2);
        sum1 += __shfl_xor_sync(0xffffffffu, sum1, 1);
        sum1 += __shfl_xor_sync(0xffffffffu, sum1, 2);
        l0 = l0 * corr0 + sum0;
        l1 = l1 * corr1 + sum1;
        #pragma unroll
        for (int nt = 0; nt < 8; nt++) {
            o[nt][0] *= corr0; o[nt][1] *= corr0;
            o[nt][2] *= corr1; o[nt][3] *= corr1;
        }

        #pragma unroll
        for (int k = 0; k < 4; k++) {
            uint32_t ph[4], pl[4];
            {
                float a0 = s[2*k][0],   a1 = s[2*k][1],   a2 = s[2*k][2],   a3 = s[2*k][3];
                float b0 = s[2*k+1][0], b1 = s[2*k+1][1], b2 = s[2*k+1][2], b3 = s[2*k+1][3];
                __half ha0 = __float2half(a0), ha1 = __float2half(a1);
                __half ha2 = __float2half(a2), ha3 = __float2half(a3);
                __half hb0 = __float2half(b0), hb1 = __float2half(b1);
                __half hb2 = __float2half(b2), hb3 = __float2half(b3);
                ph[0] = pack_h2(ha0, ha1); ph[1] = pack_h2(ha2, ha3);
                ph[2] = pack_h2(hb0, hb1); ph[3] = pack_h2(hb2, hb3);
                pl[0] = pack_h2(__float2half(a0 - __half2float(ha0)), __float2half(a1 - __half2float(ha1)));
                pl[1] = pack_h2(__float2half(a2 - __half2float(ha2)), __float2half(a3 - __half2float(ha3)));
                pl[2] = pack_h2(__float2half(b0 - __half2float(hb0)), __float2half(b1 - __half2float(hb1)));
                pl[3] = pack_h2(__float2half(b2 - __half2float(hb2)), __float2half(b3 - __half2float(hb3)));
            }
            #pragma unroll
            for (int nt = 0; nt < 8; nt++) {
                uint32_t bf[2];
                ldsm_x2t(bf, svh_b + (uint32_t)(((k * 16 + (lane & 15)) * ASTR + nt * 8) * 2));
                mma_f16(o[nt], ph, bf);
                mma_f16(o[nt], pl, bf);
            }
        }
    }

    float inv0 = 1.0f / l0, inv1 = 1.0f / l1;
    #pragma unroll
    for (int nt = 0; nt < 8; nt++) {
        int col = h * 64 + nt * 8 + 2 * (lane & 3);
        size_t p0 = ((size_t)(b * T_ + r0g)) * C_ + col;
        size_t p1 = ((size_t)(b * T_ + r0g + 8)) * C_ + col;
        *(uint32_t*)(Yh + p0) = pack_h2(__float2half(o[nt][0] * inv0), __float2half(o[nt][1] * inv0));
        *(uint32_t*)(Yh + p1) = pack_h2(__float2half(o[nt][2] * inv1), __float2half(o[nt][3] * inv1));
    }
}

// ---------------- host side ----------------
template<typename Tp>
static Tp* sym_addr(const void* sym) {
    void* p = nullptr;
    cudaGetSymbolAddress(&p, sym);
    return (Tp*)p;
}

struct GemmArgs {
    const uint16_t *Ah, *Bh;
    float* C; uint16_t *Ch;
    int M, N, K, lda, ldb, ldc;
};

template<int TM, int EPI, bool ACC, bool WSPLIT, bool WF32>
static void launch_g(const GemmArgs& a) {
    constexpr int STRIDE = (TM * 80) + 8704;
    constexpr int DSMEM  = 3 * STRIDE + 128;
    static bool done = false;
    if (!done) {
        cudaFuncSetAttribute(gemm_16<TM, EPI, ACC, WSPLIT, WF32>,
                             cudaFuncAttributeMaxDynamicSharedMemorySize, DSMEM);
        done = true;
    }
    dim3 grid(a.M / TM, (a.N + 127) / 128);
    gemm_16<TM, EPI, ACC, WSPLIT, WF32><<<grid, 256, DSMEM>>>(
        a.Ah, a.Bh, a.C, a.Ch, a.M, a.N, a.K, a.lda, a.ldb, a.ldc);
}

static void split_w16(const float* src, uint16_t* hi, size_t n) {
    int n4 = (int)(n / 4);
    split16_kernel<<<(n4 + 1023) / 1024, 256>>>(src, hi, n4);
}

extern "C" void kernel_launch(void* const* d_in, const int* in_sizes, int n_in,
                              void* d_out, int out_size)
{
    (void)in_sizes; (void)n_in; (void)out_size;
    const int*   idx   = (const int*)  d_in[0];
    const float* cosb  = (const float*)d_in[1];
    const float* sinb  = (const float*)d_in[2];
    const float* wte   = (const float*)d_in[3];
    const float* vetab = (const float*)d_in[4];
    const float* wd    = (const float*)d_in[5];
    const float* wukv  = (const float*)d_in[6];
    const float* wuq   = (const float*)d_in[7];
    const float* vg    = (const float*)d_in[8];
    const float* ap    = (const float*)d_in[9];
    const float* fc    = (const float*)d_in[10];
    const float* pj    = (const float*)d_in[11];
    const float* rl    = (const float*)d_in[12];
    const float* xl    = (const float*)d_in[13];
    const float* lmh   = (const float*)d_in[14];
    float* out = (float*)d_out;

    float* px    = sym_addr<float>(g_x);
    float* px0   = sym_addr<float>(g_x0);
    float* pxn   = sym_addr<float>(g_xn);
    float* pdown = sym_addr<float>(g_down);
    float* pkv   = sym_addr<float>(g_kv);
    float* pqraw = sym_addr<float>(g_qraw);

    uint16_t *pqh = sym_addr<uint16_t>(g_qh), *pql = sym_addr<uint16_t>(g_ql);
    uint16_t *pkh = sym_addr<uint16_t>(g_kh), *pvh = sym_addr<uint16_t>(g_vh);

    uint16_t *wdh = sym_addr<uint16_t>(s_wd_h);
    uint16_t *ukh = sym_addr<uint16_t>(s_wukv_h);
    uint16_t *uqh = sym_addr<uint16_t>(s_wuq_h);
    uint16_t *aph = sym_addr<uint16_t>(s_ap_h);
    uint16_t *fch = sym_addr<uint16_t>(s_fc_h);
    uint16_t *pjh = sym_addr<uint16_t>(s_pj_h);
    uint16_t *lmhh = sym_addr<uint16_t>(s_lmh_h);
    uint16_t *xnh = sym_addr<uint16_t>(s_xn_h);
    uint16_t *dnh = sym_addr<uint16_t>(s_dn_h);
    uint16_t *hhh = sym_addr<uint16_t>(s_h_h);
    uint16_t *yh  = sym_addr<uint16_t>(s_y_h);

    split_w16(wd,   wdh,  (size_t)L_ * C_ * DOWN);
    split_w16(wukv, ukh,  (size_t)L_ * DC * KVW);
    split_w16(wuq,  uqh,  (size_t)L_ * DC1 * C_);
    split_w16(ap,   aph,  (size_t)L_ * C_ * C_);
    split_w16(fc,   fch,  (size_t)L_ * C_ * 4096);
    split_w16(pj,   pjh,  (size_t)L_ * 4096 * C_);
    split_w16(lmh,  lmhh, (size_t)C_ * VSZ);

    embed_kernel<<<TKN, 256>>>(idx, wte, px, px0);

    for (int l = 0; l < L_; l++) {
        mixnorm_kernel<<<TKN, 256>>>(px, px0, rl, xl, l, pxn, xnh);

        // down = xn @ wd[l]  -> fp32 + fp16
        launch_g<64, 0, false, true, true>({ xnh,
            wdh + (size_t)l * C_ * DOWN,
            pdown, dnh, TKN, DOWN, C_, C_, DOWN, DOWN });
        // kv = down[:, :256] @ wukv[l] -> fp32
        launch_g<64, 0, false, false, true>({ dnh,
            ukh + (size_t)l * DC * KVW,
            pkv, nullptr, TKN, KVW, DC, DOWN, KVW, KVW });
        // qraw = down[:, 256:512] @ wuq[l] -> fp32
        launch_g<64, 0, false, false, true>({ dnh + DC,
            uqh + (size_t)l * DC1 * C_,
            pqraw, nullptr, TKN, C_, DC1, DOWN, C_, C_ });

        prep_kernel<<<TKN, 512>>>(pdown, pkv, pqraw, pxn, cosb, sinb,
                                  vg + (size_t)l * GC * H_,
                                  vetab + (size_t)l * VSZ * C_,
                                  idx, pqh, pql, pkh, pvh);

        attn_tc_kernel<<<dim3(T_ / 64, B_ * H_), 128>>>(pqh, pql, pkh, pvh, yh);

        // x += y @ attn_proj[l]
        launch_g<64, 0, true, false, true>({ yh,
            aph + (size_t)l * C_ * C_,
            px, nullptr, TKN, C_, C_, C_, C_, C_ });

        rmsnorm16_kernel<<<TKN, 256>>>(px, xnh);

        // h = relu(xn @ fc[l])^2 -> fp16
        launch_g<128, 1, false, true, false>({ xnh,
            fch + (size_t)l * C_ * 4096,
            nullptr, hhh, TKN, 4096, C_, C_, 4096, 4096 });
        // x += h @ proj[l]
        launch_g<64, 0, true, false, true>({ hhh,
            pjh + (size_t)l * 4096 * C_,
            px, nullptr, TKN, C_, 4096, 4096, C_, C_ });
    }

    rmsnorm16_kernel<<<TKN, 256>>>(px, xnh);
    // logits = softcap(xn @ lm_head)
    launch_g<128, 2, false, false, true>({ xnh, lmhh,
        out, nullptr, TKN, VSZ, C_, C_, VSZ, VSZ });
}

// round 15
// speedup vs baseline: 7.1461x; 1.0199x over previous
#include <cuda_runtime.h>
#include <cuda_bf16.h>
#include <cuda_fp16.h>
#include <math.h>
#include <stdint.h>

// ---------------- problem constants ----------------
#define B_    2
#define T_    1024
#define C_    1024
#define H_    16
#define HD_   64
#define DC    256
#define DC1   256
#define DR    32
#define DN    32
#define DOWN  544
#define VSZ   32000
#define L_    4
#define GC    32
#define TKN   2048
#define KVW   1536
#define EPSF  1.1920929e-7f

// ---------------- fp32 scratch ----------------
__device__ float g_x   [TKN * C_];
__device__ float g_x0  [TKN * C_];
__device__ float g_xn  [TKN * C_];
__device__ float g_down[TKN * DOWN];
__device__ float g_kv  [TKN * KVW];
__device__ float g_qraw[TKN * C_];

// ---------------- fp16 attention tensors [bh][T][64] ----------------
__device__ uint16_t g_qh[B_ * H_ * T_ * HD_], g_ql[B_ * H_ * T_ * HD_];
__device__ uint16_t g_kh[B_ * H_ * T_ * HD_];
__device__ uint16_t g_vh[B_ * H_ * T_ * HD_];

// ---------------- fp16 buffers (uint16_t = fp16 bits) ----------------
__device__ uint16_t s_wd_h  [L_ * C_ * DOWN];
__device__ uint16_t s_wukv_h[L_ * DC * KVW];
__device__ uint16_t s_wuq_h [L_ * DC1 * C_];
__device__ uint16_t s_ap_h  [L_ * C_ * C_];
__device__ uint16_t s_fc_h  [L_ * C_ * 4096];
__device__ uint16_t s_pj_h  [L_ * 4096 * C_];
__device__ uint16_t s_lmh_h [C_ * VSZ];
__device__ uint16_t s_xn_h  [TKN * C_];
__device__ uint16_t s_dn_h  [TKN * DOWN];
__device__ uint16_t s_h_h   [TKN * 4096];
__device__ uint16_t s_y_h   [TKN * C_];

// ================= helpers =================
__device__ __forceinline__ uint32_t smem_u32(const void* p) {
    uint32_t a;
    asm("{ .reg .u64 t; cvta.to.shared.u64 t, %1; cvt.u32.u64 %0, t; }" : "=r"(a) : "l"(p));
    return a;
}
__device__ __forceinline__ void ldsm_x4(uint32_t r[4], uint32_t addr) {
    asm volatile("ldmatrix.sync.aligned.m8n8.x4.shared.b16 {%0,%1,%2,%3}, [%4];"
        : "=r"(r[0]), "=r"(r[1]), "=r"(r[2]), "=r"(r[3]) : "r"(addr));
}
__device__ __forceinline__ void ldsm_x2(uint32_t r[2], uint32_t addr) {
    asm volatile("ldmatrix.sync.aligned.m8n8.x2.shared.b16 {%0,%1}, [%2];"
        : "=r"(r[0]), "=r"(r[1]) : "r"(addr));
}
__device__ __forceinline__ void ldsm_x2t(uint32_t r[2], uint32_t addr) {
    asm volatile("ldmatrix.sync.aligned.m8n8.x2.trans.shared.b16 {%0,%1}, [%2];"
        : "=r"(r[0]), "=r"(r[1]) : "r"(addr));
}
__device__ __forceinline__ void mma_f16(float c[4], const uint32_t a[4], const uint32_t b[2]) {
    asm volatile("mma.sync.aligned.m16n8k16.row.col.f32.f16.f16.f32 "
        "{%0,%1,%2,%3}, {%4,%5,%6,%7}, {%8,%9}, {%0,%1,%2,%3};"
        : "+f"(c[0]), "+f"(c[1]), "+f"(c[2]), "+f"(c[3])
        : "r"(a[0]), "r"(a[1]), "r"(a[2]), "r"(a[3]), "r"(b[0]), "r"(b[1]));
}
__device__ __forceinline__ void cp16(uint32_t dst, const void* src) {
    asm volatile("cp.async.cg.shared.global [%0], [%1], 16;" :: "r"(dst), "l"(src));
}
__device__ __forceinline__ void cp16z(uint32_t dst, const void* src, uint32_t ssize) {
    asm volatile("cp.async.cg.shared.global [%0], [%1], 16, %2;" :: "r"(dst), "l"(src), "r"(ssize));
}
#define CP_COMMIT() asm volatile("cp.async.commit_group;" ::: "memory")
#define CP_WAIT1()  asm volatile("cp.async.wait_group 1;" ::: "memory")
__device__ __forceinline__ uint32_t pack_h2(__half a, __half b) {
    union { __half h[2]; uint32_t u; } u;
    u.h[0] = a; u.h[1] = b;
    return u.u;
}

// ================= fp16 single-pass GEMM =================
// C[M,N] = fp16(A)[M,K] @ fp16(B)[K,N], fp32 accumulate.
// smem per stage: A[TM][40] | B[32][136]
template<int TM, int EPI, bool ACC, bool WSPLIT, bool WF32>
__global__ __launch_bounds__(256, 2) void gemm_16(
    const uint16_t* __restrict__ Ah, const uint16_t* __restrict__ Bh,
    float* __restrict__ C, uint16_t* __restrict__ Ch,
    int M, int N, int K, int lda, int ldb, int ldc)
{
    constexpr int MT     = TM / 32;
    constexpr int A_SZ   = TM * 80;
    constexpr int STRIDE = A_SZ + 8704;

    extern __shared__ char dsm[];
    uint32_t sraw = smem_u32(dsm);
    uint32_t s0 = (sraw + 127u) & ~127u;

    int tid = threadIdx.x, wid = tid >> 5, lane = tid & 31;
    int row0 = blockIdx.x * TM, col0 = blockIdx.y * 128;
    int wm = (wid >> 2) * (TM / 2);
    int wn = (wid & 3) * 32;

    float c[MT][4][4];
    #pragma unroll
    for (int mt = 0; mt < MT; mt++)
        #pragma unroll
        for (int nt = 0; nt < 4; nt++)
            #pragma unroll
            for (int r = 0; r < 4; r++) c[mt][nt][r] = 0.f;

    int NC = K >> 5;

    auto issue_copy = [&](int i, int stg) {
        int k0 = i << 5;
        uint32_t sb = s0 + (uint32_t)stg * STRIDE;
        #pragma unroll
        for (int e = tid; e < TM * 4; e += 256) {
            int r = e >> 2, seg = e & 3;
            cp16(sb + (uint32_t)(r * 80 + seg * 16),
                 Ah + (size_t)(row0 + r) * lda + k0 + seg * 8);
        }
        #pragma unroll
        for (int e0 = 0; e0 < 2; e0++) {
            int e = tid + e0 * 256;
            int kk = e >> 4, seg = e & 15;
            int gc = col0 + seg * 8;
            uint32_t d = sb + (uint32_t)A_SZ + (uint32_t)(kk * 272 + seg * 16);
            int rem = N - gc;
            uint32_t sz = rem >= 8 ? 16u : (rem > 0 ? (uint32_t)(rem * 2) : 0u);
            cp16z(d, Bh + (size_t)(k0 + kk) * ldb + gc, sz);
        }
    };

    auto mma_chunk = [&](int stg) {
        uint32_t base = s0 + (uint32_t)stg * STRIDE;
        int arow = wm + ((lane >> 3) & 1) * 8 + (lane & 7);
        int krow = lane & 15;
        #pragma unroll
        for (int kk = 0; kk < 32; kk += 16) {
            int acol = kk + ((lane >> 4) & 1) * 8;
            uint32_t af[MT][4], bh[4][2];
            #pragma unroll
            for (int mt = 0; mt < MT; mt++)
                ldsm_x4(af[mt], base + (uint32_t)((arow + mt * 16) * 80 + acol * 2));
            #pragma unroll
            for (int nt = 0; nt < 4; nt++)
                ldsm_x2t(bh[nt], base + (uint32_t)A_SZ + (uint32_t)((kk + krow) * 272 + (wn + nt * 8) * 2));
            #pragma unroll
            for (int mt = 0; mt < MT; mt++)
                #pragma unroll
                for (int nt = 0; nt < 4; nt++)
                    mma_f16(c[mt][nt], af[mt], bh[nt]);
        }
    };

    issue_copy(0, 0); CP_COMMIT();
    issue_copy(1, 1); CP_COMMIT();
    for (int i = 0; i < NC; i++) {
        CP_WAIT1();
        __syncthreads();
        mma_chunk(i % 3);
        if (i + 2 < NC) issue_copy(i + 2, (i + 2) % 3);
        CP_COMMIT();
    }

    // ---- epilogue ----
    #pragma unroll
    for (int mt = 0; mt < MT; mt++) {
        #pragma unroll
        for (int nt = 0; nt < 4; nt++) {
            #pragma unroll
            for (int half = 0; half < 2; half++) {
                int grow = row0 + wm + mt * 16 + (lane >> 2) + half * 8;
                int gcol = col0 + wn + nt * 8 + (lane & 3) * 2;
                float v0 = c[mt][nt][half * 2 + 0];
                float v1 = c[mt][nt][half * 2 + 1];
                if (EPI == 1) {
                    float h0 = fmaxf(v0, 0.f); v0 = h0 * h0;
                    float h1 = fmaxf(v1, 0.f); v1 = h1 * h1;
                }
                if (EPI == 2) {
                    v0 = 15.0f * tanhf(v0 * (1.0f / 15.0f));
                    v1 = 15.0f * tanhf(v1 * (1.0f / 15.0f));
                }
                if (gcol + 1 < N) {
                    size_t p = (size_t)grow * ldc + gcol;
                    if (ACC) { v0 += C[p]; v1 += C[p + 1]; }
                    if (WF32) *(float2*)(C + p) = make_float2(v0, v1);
                    if (WSPLIT)
                        *(uint32_t*)(Ch + p) = pack_h2(__float2half(v0), __float2half(v1));
                } else if (gcol < N) {
                    size_t p = (size_t)grow * ldc + gcol;
                    if (ACC) v0 += C[p];
                    if (WF32) C[p] = v0;
                    if (WSPLIT) Ch[p] = __half_as_ushort(__float2half(v0));
                }
            }
        }
    }
}

// ---------------- fp16 weight split (uint4 stores) ----------------
__global__ __launch_bounds__(256) void split16_kernel(
    const float* __restrict__ src, uint16_t* __restrict__ hi, int n8)
{
    int base = blockIdx.x * 1024 + threadIdx.x;
    #pragma unroll
    for (int j = 0; j < 4; j++) {
        int i = base + j * 256;
        if (i >= n8) continue;
        float4 a = ((const float4*)src)[2 * i];
        float4 b = ((const float4*)src)[2 * i + 1];
        union { uint16_t h[8]; uint4 u; } ph;
        ph.h[0] = __half_as_ushort(__float2half(a.x));
        ph.h[1] = __half_as_ushort(__float2half(a.y));
        ph.h[2] = __half_as_ushort(__float2half(a.z));
        ph.h[3] = __half_as_ushort(__float2half(a.w));
        ph.h[4] = __half_as_ushort(__float2half(b.x));
        ph.h[5] = __half_as_ushort(__float2half(b.y));
        ph.h[6] = __half_as_ushort(__float2half(b.z));
        ph.h[7] = __half_as_ushort(__float2half(b.w));
        ((uint4*)hi)[i] = ph.u;
    }
}

// ---------------- block reduce ----------------
__device__ __forceinline__ float blockReduceSum(float v) {
    __shared__ float red[32];
    int lane = threadIdx.x & 31, w = threadIdx.x >> 5;
    #pragma unroll
    for (int o = 16; o; o >>= 1) v += __shfl_xor_sync(0xffffffffu, v, o);
    if (lane == 0) red[w] = v;
    __syncthreads();
    v = (threadIdx.x < (blockDim.x >> 5)) ? red[threadIdx.x] : 0.0f;
    if (w == 0) {
        #pragma unroll
        for (int o = 16; o; o >>= 1) v += __shfl_xor_sync(0xffffffffu, v, o);
        if (lane == 0) red[0] = v;
    }
    __syncthreads();
    return red[0];
}

// ---------------- embed + norms ----------------
__global__ __launch_bounds__(256) void embed_kernel(
    const int* __restrict__ idx, const float* __restrict__ wte,
    float* __restrict__ x, float* __restrict__ x0)
{
    int i = blockIdx.x;
    const float* row = wte + (size_t)idx[i] * C_;
    float v[4]; float ss = 0.f;
    #pragma unroll
    for (int j = 0; j < 4; j++) { v[j] = row[threadIdx.x + j * 256]; ss += v[j] * v[j]; }
    ss = blockReduceSum(ss);
    float sc = rsqrtf(ss / C_ + EPSF);
    #pragma unroll
    for (int j = 0; j < 4; j++) {
        float o = v[j] * sc;
        x [(size_t)i * C_ + threadIdx.x + j * 256] = o;
        x0[(size_t)i * C_ + threadIdx.x + j * 256] = o;
    }
}

__global__ __launch_bounds__(256) void mixnorm_kernel(
    float* __restrict__ x, const float* __restrict__ x0,
    const float* __restrict__ rl, const float* __restrict__ xl, int l,
    float* __restrict__ xn, uint16_t* __restrict__ xnh)
{
    int i = blockIdx.x;
    float a = rl[l], bc = xl[l];
    float v[4]; float ss = 0.f;
    #pragma unroll
    for (int j = 0; j < 4; j++) {
        size_t p = (size_t)i * C_ + threadIdx.x + j * 256;
        v[j] = a * x[p] + bc * x0[p];
        ss += v[j] * v[j];
    }
    ss = blockReduceSum(ss);
    float sc = rsqrtf(ss / C_ + EPSF);
    #pragma unroll
    for (int j = 0; j < 4; j++) {
        size_t p = (size_t)i * C_ + threadIdx.x + j * 256;
        float o = v[j] * sc;
        x[p] = v[j];
        xn[p] = o;
        xnh[p] = __half_as_ushort(__float2half(o));
    }
}

__global__ __launch_bounds__(256) void rmsnorm16_kernel(
    const float* __restrict__ x, uint16_t* __restrict__ xnh)
{
    int i = blockIdx.x;
    float v[4]; float ss = 0.f;
    #pragma unroll
    for (int j = 0; j < 4; j++) {
        v[j] = x[(size_t)i * C_ + threadIdx.x + j * 256];
        ss += v[j] * v[j];
    }
    ss = blockReduceSum(ss);
    float sc = rsqrtf(ss / C_ + EPSF);
    #pragma unroll
    for (int j = 0; j < 4; j++) {
        size_t p = (size_t)i * C_ + threadIdx.x + j * 256;
        xnh[p] = __half_as_ushort(__float2half(v[j] * sc));
    }
}

// ---------------- per-token q/k/v assembly -> fp16 ----------------
__global__ __launch_bounds__(512) void prep_kernel(
    const float* __restrict__ down, const float* __restrict__ kvb,
    const float* __restrict__ qraw, const float* __restrict__ xn,
    const float* __restrict__ cosb, const float* __restrict__ sinb,
    const float* __restrict__ vg, const float* __restrict__ vetab,
    const int* __restrict__ idx,
    uint16_t* __restrict__ Qh, uint16_t* __restrict__ Ql,
    uint16_t* __restrict__ Kh, uint16_t* __restrict__ Vh)
{
    int i = blockIdx.x;
    int b = i / T_, t = i % T_;
    int w = threadIdx.x >> 5, lane = threadIdx.x & 31;
    __shared__ float cs[16], sn[16], kr[32];

    if (threadIdx.x < 16)       cs[threadIdx.x]      = cosb[(size_t)i * 16 + threadIdx.x];
    else if (threadIdx.x < 32)  sn[threadIdx.x - 16] = sinb[(size_t)i * 16 + threadIdx.x - 16];
    __syncthreads();

    float gv = xn[(size_t)i * C_ + lane] * vg[lane * H_ + w];
    #pragma unroll
    for (int o = 16; o; o >>= 1) gv += __shfl_xor_sync(0xffffffffu, gv, o);
    float gate = 2.0f / (1.0f + expf(-gv));

    if (w == 0) {
        int j = lane & 15;
        float x1 = down[(size_t)i * DOWN + 512 + j];
        float x2 = down[(size_t)i * DOWN + 528 + j];
        float cc = cs[j], ssn = sn[j];
        kr[lane] = (lane < 16) ? (x1 * cc + x2 * ssn) : (-x1 * ssn + x2 * cc);
    }
    __syncthreads();

    const float* kvrow = kvb  + (size_t)i * KVW + w * 96;
    const float* qrow  = qraw + (size_t)i * C_  + w * 64;
    const float* verow = vetab + (size_t)idx[i] * C_ + w * 64;

    float k0v = kvrow[lane];
    float k1v = kr[lane];
    float q0v = qrow[lane];
    float q1v;
    {
        int j = lane & 15;
        float a = qrow[32 + j], bb = qrow[48 + j];
        float cc = cs[j], ssn = sn[j];
        q1v = (lane < 16) ? (a * cc + bb * ssn) : (-a * ssn + bb * cc);
    }
    float v0 = kvrow[32 + lane] + gate * verow[lane];
    float v1 = kvrow[64 + lane] + gate * verow[32 + lane];

    float kss = k0v * k0v + k1v * k1v;
    float qss = q0v * q0v + q1v * q1v;
    #pragma unroll
    for (int o = 16; o; o >>= 1) {
        kss += __shfl_xor_sync(0xffffffffu, kss, o);
        qss += __shfl_xor_sync(0xffffffffu, qss, o);
    }
    float ksc = rsqrtf(kss * (1.0f / 64.0f) + EPSF);
    float qsc = rsqrtf(qss * (1.0f / 64.0f) + EPSF);

    size_t base = ((size_t)(b * H_ + w) * T_ + t) * 64;
    float qv0 = q0v * qsc, qv1 = q1v * qsc;
    __half qh0 = __float2half(qv0), qh1 = __float2half(qv1);
    Qh[base + lane]      = __half_as_ushort(qh0);
    Qh[base + 32 + lane] = __half_as_ushort(qh1);
    Ql[base + lane]      = __half_as_ushort(__float2half(qv0 - __half2float(qh0)));
    Ql[base + 32 + lane] = __half_as_ushort(__float2half(qv1 - __half2float(qh1)));
    Kh[base + lane]      = __half_as_ushort(__float2half(k0v * ksc));
    Kh[base + 32 + lane] = __half_as_ushort(__float2half(k1v * ksc));
    Vh[base + lane]      = __half_as_ushort(__float2half(v0));
    Vh[base + 32 + lane] = __half_as_ushort(__float2half(v1));
}

// ---------------- tensor-core flash attention (causal) ----------------
#define ASTR 72
__global__ __launch_bounds__(128) void attn_tc_kernel(
    const uint16_t* __restrict__ Qh, const uint16_t* __restrict__ Ql,
    const uint16_t* __restrict__ Kh, const uint16_t* __restrict__ Vh,
    uint16_t* __restrict__ Yh)
{
    __shared__ uint16_t sqh[64 * ASTR], sql[64 * ASTR];
    __shared__ uint16_t skh[64 * ASTR], svh[64 * ASTR];

    int qt0 = blockIdx.x * 64;
    int bh  = blockIdx.y;
    int b = bh >> 4, h = bh & 15;
    size_t gbase = (size_t)bh * T_ * 64;
    int tid = threadIdx.x, wid = tid >> 5, lane = tid & 31;
    int wm = wid * 16;

    for (int e = tid; e < 1024; e += 128) {
        int r = e >> 4, c4 = (e & 15) << 2;
        *(uint2*)&sqh[r * ASTR + c4] = *(const uint2*)&Qh[gbase + (size_t)(qt0 + r) * 64 + c4];
        *(uint2*)&sql[r * ASTR + c4] = *(const uint2*)&Ql[gbase + (size_t)(qt0 + r) * 64 + c4];
    }
    __syncthreads();

    uint32_t sqh_b = smem_u32(sqh), sql_b = smem_u32(sql);
    uint32_t skh_b = smem_u32(skh), svh_b = smem_u32(svh);

    uint32_t qfh[4][4], qfl[4][4];
    {
        int arow = wm + (lane & 15);
        #pragma unroll
        for (int k = 0; k < 4; k++) {
            int acol = k * 16 + ((lane >> 4) & 1) * 8;
            uint32_t off = (uint32_t)((arow * ASTR + acol) * 2);
            ldsm_x4(qfh[k], sqh_b + off);
            ldsm_x4(qfl[k], sql_b + off);
        }
    }

    float m0 = -1e30f, m1 = -1e30f, l0 = 0.f, l1 = 0.f;
    float o[8][4];
    #pragma unroll
    for (int nt = 0; nt < 8; nt++)
        #pragma unroll
        for (int j = 0; j < 4; j++) o[nt][j] = 0.f;

    int r0g = qt0 + wm + (lane >> 2);
    int niter = qt0 / 64 + 1;

    for (int it = 0; it < niter; it++) {
        int kv0 = it * 64;
        __syncthreads();
        for (int e = tid; e < 1024; e += 128) {
            int r = e >> 4, c4 = (e & 15) << 2;
            *(uint2*)&skh[r * ASTR + c4] = *(const uint2*)&Kh[gbase + (size_t)(kv0 + r) * 64 + c4];
            *(uint2*)&svh[r * ASTR + c4] = *(const uint2*)&Vh[gbase + (size_t)(kv0 + r) * 64 + c4];
        }
        __syncthreads();

        float s[8][4];
        #pragma unroll
        for (int nt = 0; nt < 8; nt++)
            #pragma unroll
            for (int j = 0; j < 4; j++) s[nt][j] = 0.f;
        #pragma unroll
        for (int k = 0; k < 4; k++) {
            #pragma unroll
            for (int nt = 0; nt < 8; nt++) {
                uint32_t bf[2];
                ldsm_x2(bf, skh_b + (uint32_t)(((nt * 8 + (lane & 7)) * ASTR
                            + k * 16 + ((lane >> 3) & 1) * 8) * 2));
                mma_f16(s[nt], qfh[k], bf);
                mma_f16(s[nt], qfl[k], bf);
            }
        }

        bool edge = (kv0 == qt0);
        #pragma unroll
        for (int nt = 0; nt < 8; nt++) {
            #pragma unroll
            for (int j = 0; j < 4; j++) s[nt][j] *= 0.125f;
            if (edge) {
                int c0 = kv0 + nt * 8 + 2 * (lane & 3);
                if (c0     > r0g)     s[nt][0] = -1e30f;
                if (c0 + 1 > r0g)     s[nt][1] = -1e30f;
                if (c0     > r0g + 8) s[nt][2] = -1e30f;
                if (c0 + 1 > r0g + 8) s[nt][3] = -1e30f;
            }
        }

        float rm0 = -1e30f, rm1 = -1e30f;
        #pragma unroll
        for (int nt = 0; nt < 8; nt++) {
            rm0 = fmaxf(rm0, fmaxf(s[nt][0], s[nt][1]));
            rm1 = fmaxf(rm1, fmaxf(s[nt][2], s[nt][3]));
        }
        rm0 = fmaxf(rm0, __shfl_xor_sync(0xffffffffu, rm0, 1));
        rm0 = fmaxf(rm0, __shfl_xor_sync(0xffffffffu, rm0, 2));
        rm1 = fmaxf(rm1, __shfl_xor_sync(0xffffffffu, rm1, 1));
        rm1 = fmaxf(rm1, __shfl_xor_sync(0xffffffffu, rm1, 2));
        float mn0 = fmaxf(m0, rm0), mn1 = fmaxf(m1, rm1);
        float corr0 = __expf(m0 - mn0), corr1 = __expf(m1 - mn1);
        m0 = mn0; m1 = mn1;
        float sum0 = 0.f, sum1 = 0.f;
        #pragma unroll
        for (int nt = 0; nt < 8; nt++) {
            s[nt][0] = __expf(s[nt][0] - mn0);
            s[nt][1] = __expf(s[nt][1] - mn0);
            s[nt][2] = __expf(s[nt][2] - mn1);
            s[nt][3] = __expf(s[nt][3] - mn1);
            sum0 += s[nt][0] + s[nt][1];
            sum1 += s[nt][2] + s[nt][3];
        }
        sum0 += __shfl_xor_sync(0xffffffffu, sum0, 1);
        sum0 += __shfl_xor_sync(0xffffffffu, sum0, 2);
        sum1 += __shfl_xor_sync(0xffffffffu, sum1, 1);
        sum1 += __shfl_xor_sync(0xffffffffu, sum1, 2);
        l0 = l0 * corr0 + sum0;
        l1 = l1 * corr1 + sum1;
        #pragma unroll
        for (int nt = 0; nt < 8; nt++) {
            o[nt][0] *= corr0; o[nt][1] *= corr0;
            o[nt][2] *= corr1; o[nt][3] *= corr1;
        }

        #pragma unroll
        for (int k = 0; k < 4; k++) {
            uint32_t ph[4], pl[4];
            {
                float a0 = s[2*k][0],   a1 = s[2*k][1],   a2 = s[2*k][2],   a3 = s[2*k][3];
                float b0 = s[2*k+1][0], b1 = s[2*k+1][1], b2 = s[2*k+1][2], b3 = s[2*k+1][3];
                __half ha0 = __float2half(a0), ha1 = __float2half(a1);
                __half ha2 = __float2half(a2), ha3 = __float2half(a3);
                __half hb0 = __float2half(b0), hb1 = __float2half(b1);
                __half hb2 = __float2half(b2), hb3 = __float2half(b3);
                ph[0] = pack_h2(ha0, ha1); ph[1] = pack_h2(ha2, ha3);
                ph[2] = pack_h2(hb0, hb1); ph[3] = pack_h2(hb2, hb3);
                pl[0] = pack_h2(__float2half(a0 - __half2float(ha0)), __float2half(a1 - __half2float(ha1)));
                pl[1] = pack_h2(__float2half(a2 - __half2float(ha2)), __float2half(a3 - __half2float(ha3)));
                pl[2] = pack_h2(__float2half(b0 - __half2float(hb0)), __float2half(b1 - __half2float(hb1)));
                pl[3] = pack_h2(__float2half(b2 - __half2float(hb2)), __float2half(b3 - __half2float(hb3)));
            }
            #pragma unroll
            for (int nt = 0; nt < 8; nt++) {
                uint32_t bf[2];
                ldsm_x2t(bf, svh_b + (uint32_t)(((k * 16 + (lane & 15)) * ASTR + nt * 8) * 2));
                mma_f16(o[nt], ph, bf);
                mma_f16(o[nt], pl, bf);
            }
        }
    }

    float inv0 = 1.0f / l0, inv1 = 1.0f / l1;
    #pragma unroll
    for (int nt = 0; nt < 8; nt++) {
        int col = h * 64 + nt * 8 + 2 * (lane & 3);
        size_t p0 = ((size_t)(b * T_ + r0g)) * C_ + col;
        size_t p1 = ((size_t)(b * T_ + r0g + 8)) * C_ + col;
        *(uint32_t*)(Yh + p0) = pack_h2(__float2half(o[nt][0] * inv0), __float2half(o[nt][1] * inv0));
        *(uint32_t*)(Yh + p1) = pack_h2(__float2half(o[nt][2] * inv1), __float2half(o[nt][3] * inv1));
    }
}

// ---------------- host side ----------------
template<typename Tp>
static Tp* sym_addr(const void* sym) {
    void* p = nullptr;
    cudaGetSymbolAddress(&p, sym);
    return (Tp*)p;
}

struct GemmArgs {
    const uint16_t *Ah, *Bh;
    float* C; uint16_t *Ch;
    int M, N, K, lda, ldb, ldc;
};

template<int TM, int EPI, bool ACC, bool WSPLIT, bool WF32>
static void launch_g(const GemmArgs& a, cudaStream_t st = 0) {
    constexpr int STRIDE = (TM * 80) + 8704;
    constexpr int DSMEM  = 3 * STRIDE + 128;
    static bool done = false;
    if (!done) {
        cudaFuncSetAttribute(gemm_16<TM, EPI, ACC, WSPLIT, WF32>,
                             cudaFuncAttributeMaxDynamicSharedMemorySize, DSMEM);
        done = true;
    }
    dim3 grid(a.M / TM, (a.N + 127) / 128);
    gemm_16<TM, EPI, ACC, WSPLIT, WF32><<<grid, 256, DSMEM, st>>>(
        a.Ah, a.Bh, a.C, a.Ch, a.M, a.N, a.K, a.lda, a.ldb, a.ldc);
}

static void split_w16(const float* src, uint16_t* hi, size_t n, cudaStream_t st) {
    int n8 = (int)(n / 8);
    split16_kernel<<<(n8 + 1023) / 1024, 256, 0, st>>>(src, hi, n8);
}

extern "C" void kernel_launch(void* const* d_in, const int* in_sizes, int n_in,
                              void* d_out, int out_size)
{
    (void)in_sizes; (void)n_in; (void)out_size;
    const int*   idx   = (const int*)  d_in[0];
    const float* cosb  = (const float*)d_in[1];
    const float* sinb  = (const float*)d_in[2];
    const float* wte   = (const float*)d_in[3];
    const float* vetab = (const float*)d_in[4];
    const float* wd    = (const float*)d_in[5];
    const float* wukv  = (const float*)d_in[6];
    const float* wuq   = (const float*)d_in[7];
    const float* vg    = (const float*)d_in[8];
    const float* ap    = (const float*)d_in[9];
    const float* fc    = (const float*)d_in[10];
    const float* pj    = (const float*)d_in[11];
    const float* rl    = (const float*)d_in[12];
    const float* xl    = (const float*)d_in[13];
    const float* lmh   = (const float*)d_in[14];
    float* out = (float*)d_out;

    // streams/events created once (first call is the un-captured correctness run)
    static cudaStream_t s1 = nullptr, s2 = nullptr;
    static cudaEvent_t ev_fork = nullptr, ev_small = nullptr,
                       ev_fc = nullptr, ev_pj = nullptr, ev_lmh = nullptr,
                       ev_wd = nullptr, ev_q = nullptr;
    if (!s1) {
        cudaStreamCreateWithFlags(&s1, cudaStreamNonBlocking);
        cudaStreamCreateWithFlags(&s2, cudaStreamNonBlocking);
        cudaEventCreateWithFlags(&ev_fork,  cudaEventDisableTiming);
        cudaEventCreateWithFlags(&ev_small, cudaEventDisableTiming);
        cudaEventCreateWithFlags(&ev_fc,    cudaEventDisableTiming);
        cudaEventCreateWithFlags(&ev_pj,    cudaEventDisableTiming);
        cudaEventCreateWithFlags(&ev_lmh,   cudaEventDisableTiming);
        cudaEventCreateWithFlags(&ev_wd,    cudaEventDisableTiming);
        cudaEventCreateWithFlags(&ev_q,     cudaEventDisableTiming);
    }

    float* px    = sym_addr<float>(g_x);
    float* px0   = sym_addr<float>(g_x0);
    float* pxn   = sym_addr<float>(g_xn);
    float* pdown = sym_addr<float>(g_down);
    float* pkv   = sym_addr<float>(g_kv);
    float* pqraw = sym_addr<float>(g_qraw);

    uint16_t *pqh = sym_addr<uint16_t>(g_qh), *pql = sym_addr<uint16_t>(g_ql);
    uint16_t *pkh = sym_addr<uint16_t>(g_kh), *pvh = sym_addr<uint16_t>(g_vh);

    uint16_t *wdh = sym_addr<uint16_t>(s_wd_h);
    uint16_t *ukh = sym_addr<uint16_t>(s_wukv_h);
    uint16_t *uqh = sym_addr<uint16_t>(s_wuq_h);
    uint16_t *aph = sym_addr<uint16_t>(s_ap_h);
    uint16_t *fch = sym_addr<uint16_t>(s_fc_h);
    uint16_t *pjh = sym_addr<uint16_t>(s_pj_h);
    uint16_t *lmhh = sym_addr<uint16_t>(s_lmh_h);
    uint16_t *xnh = sym_addr<uint16_t>(s_xn_h);
    uint16_t *dnh = sym_addr<uint16_t>(s_dn_h);
    uint16_t *hhh = sym_addr<uint16_t>(s_h_h);
    uint16_t *yh  = sym_addr<uint16_t>(s_y_h);

    // ---- fork side stream: weight splits overlap with compute ----
    cudaEventRecord(ev_fork, 0);
    cudaStreamWaitEvent(s1, ev_fork, 0);
    split_w16(wd,   wdh,  (size_t)L_ * C_ * DOWN, s1);
    split_w16(wukv, ukh,  (size_t)L_ * DC * KVW,  s1);
    split_w16(wuq,  uqh,  (size_t)L_ * DC1 * C_,  s1);
    split_w16(ap,   aph,  (size_t)L_ * C_ * C_,   s1);
    cudaEventRecord(ev_small, s1);
    split_w16(fc,   fch,  (size_t)L_ * C_ * 4096, s1);
    cudaEventRecord(ev_fc, s1);
    split_w16(pj,   pjh,  (size_t)L_ * 4096 * C_, s1);
    cudaEventRecord(ev_pj, s1);
    split_w16(lmh,  lmhh, (size_t)C_ * VSZ,       s1);
    cudaEventRecord(ev_lmh, s1);

    embed_kernel<<<TKN, 256>>>(idx, wte, px, px0);
    cudaStreamWaitEvent(0, ev_small, 0);

    for (int l = 0; l < L_; l++) {
        mixnorm_kernel<<<TKN, 256>>>(px, px0, rl, xl, l, pxn, xnh);

        // down = xn @ wd[l]  -> fp32 + fp16
        launch_g<64, 0, false, true, true>({ xnh,
            wdh + (size_t)l * C_ * DOWN,
            pdown, dnh, TKN, DOWN, C_, C_, DOWN, DOWN });
        cudaEventRecord(ev_wd, 0);

        // qraw on side stream s2, concurrent with kv on main
        cudaStreamWaitEvent(s2, ev_wd, 0);
        launch_g<64, 0, false, false, true>({ dnh + DC,
            uqh + (size_t)l * DC1 * C_,
            pqraw, nullptr, TKN, C_, DC1, DOWN, C_, C_ }, s2);
        cudaEventRecord(ev_q, s2);

        // kv = down[:, :256] @ wukv[l] -> fp32 (main)
        launch_g<64, 0, false, false, true>({ dnh,
            ukh + (size_t)l * DC * KVW,
            pkv, nullptr, TKN, KVW, DC, DOWN, KVW, KVW });

        cudaStreamWaitEvent(0, ev_q, 0);
        prep_kernel<<<TKN, 512>>>(pdown, pkv, pqraw, pxn, cosb, sinb,
                                  vg + (size_t)l * GC * H_,
                                  vetab + (size_t)l * VSZ * C_,
                                  idx, pqh, pql, pkh, pvh);

        attn_tc_kernel<<<dim3(T_ / 64, B_ * H_), 128>>>(pqh, pql, pkh, pvh, yh);

        // x += y @ attn_proj[l]
        launch_g<64, 0, true, false, true>({ yh,
            aph + (size_t)l * C_ * C_,
            px, nullptr, TKN, C_, C_, C_, C_, C_ });

        rmsnorm16_kernel<<<TKN, 256>>>(px, xnh);

        if (l == 0) cudaStreamWaitEvent(0, ev_fc, 0);
        // h = relu(xn @ fc[l])^2 -> fp16
        launch_g<128, 1, false, true, false>({ xnh,
            fch + (size_t)l * C_ * 4096,
            nullptr, hhh, TKN, 4096, C_, C_, 4096, 4096 });
        if (l == 0) cudaStreamWaitEvent(0, ev_pj, 0);
        // x += h @ proj[l]
        launch_g<64, 0, true, false, true>({ hhh,
            pjh + (size_t)l * 4096 * C_,
            px, nullptr, TKN, C_, 4096, 4096, C_, C_ });
    }

    rmsnorm16_kernel<<<TKN, 256>>>(px, xnh);
    cudaStreamWaitEvent(0, ev_lmh, 0);
    // logits = softcap(xn @ lm_head)
    launch_g<128, 2, false, false, true>({ xnh, lmhh,
        out, nullptr, TKN, VSZ, C_, C_, VSZ, VSZ });
}

// round 16
// speedup vs baseline: 7.7338x; 1.0822x over previous
#include <cuda_runtime.h>
#include <cuda_bf16.h>
#include <cuda_fp16.h>
#include <math.h>
#include <stdint.h>

// ---------------- problem constants ----------------
#define B_    2
#define T_    1024
#define C_    1024
#define H_    16
#define HD_   64
#define DC    256
#define DC1   256
#define DR    32
#define DN    32
#define DOWN  544
#define VSZ   32000
#define L_    4
#define GC    32
#define TKN   2048
#define KVW   1536
#define EPSF  1.1920929e-7f

// ---------------- fp32 scratch ----------------
__device__ float g_x   [TKN * C_];
__device__ float g_x0  [TKN * C_];
__device__ float g_xn  [TKN * C_];
__device__ float g_down[TKN * DOWN];
__device__ float g_kv  [TKN * KVW];
__device__ float g_qraw[TKN * C_];

// ---------------- fp16 attention tensors [bh][T][64] ----------------
__device__ uint16_t g_qh[B_ * H_ * T_ * HD_], g_ql[B_ * H_ * T_ * HD_];
__device__ uint16_t g_kh[B_ * H_ * T_ * HD_];
__device__ uint16_t g_vh[B_ * H_ * T_ * HD_];

// ---------------- fp16 buffers (uint16_t = fp16 bits) ----------------
__device__ uint16_t s_wd_h  [L_ * C_ * DOWN];
__device__ uint16_t s_wukv_h[L_ * DC * KVW];
__device__ uint16_t s_wuq_h [L_ * DC1 * C_];
__device__ uint16_t s_ap_h  [L_ * C_ * C_];
__device__ uint16_t s_fc_h  [L_ * C_ * 4096];
__device__ uint16_t s_pj_h  [L_ * 4096 * C_];
__device__ uint16_t s_lmh_h [C_ * VSZ];
__device__ uint16_t s_xn_h  [TKN * C_];
__device__ uint16_t s_dn_h  [TKN * DOWN];
__device__ uint16_t s_h_h   [TKN * 4096];
__device__ uint16_t s_y_h   [TKN * C_];

// ================= helpers =================
__device__ __forceinline__ uint32_t smem_u32(const void* p) {
    uint32_t a;
    asm("{ .reg .u64 t; cvta.to.shared.u64 t, %1; cvt.u32.u64 %0, t; }" : "=r"(a) : "l"(p));
    return a;
}
__device__ __forceinline__ void ldsm_x4(uint32_t r[4], uint32_t addr) {
    asm volatile("ldmatrix.sync.aligned.m8n8.x4.shared.b16 {%0,%1,%2,%3}, [%4];"
        : "=r"(r[0]), "=r"(r[1]), "=r"(r[2]), "=r"(r[3]) : "r"(addr));
}
__device__ __forceinline__ void ldsm_x2(uint32_t r[2], uint32_t addr) {
    asm volatile("ldmatrix.sync.aligned.m8n8.x2.shared.b16 {%0,%1}, [%2];"
        : "=r"(r[0]), "=r"(r[1]) : "r"(addr));
}
__device__ __forceinline__ void ldsm_x2t(uint32_t r[2], uint32_t addr) {
    asm volatile("ldmatrix.sync.aligned.m8n8.x2.trans.shared.b16 {%0,%1}, [%2];"
        : "=r"(r[0]), "=r"(r[1]) : "r"(addr));
}
__device__ __forceinline__ void ldsm_x4t(uint32_t r[4], uint32_t addr) {
    asm volatile("ldmatrix.sync.aligned.m8n8.x4.trans.shared.b16 {%0,%1,%2,%3}, [%4];"
        : "=r"(r[0]), "=r"(r[1]), "=r"(r[2]), "=r"(r[3]) : "r"(addr));
}
__device__ __forceinline__ void mma_f16(float c[4], const uint32_t a[4], const uint32_t b[2]) {
    asm volatile("mma.sync.aligned.m16n8k16.row.col.f32.f16.f16.f32 "
        "{%0,%1,%2,%3}, {%4,%5,%6,%7}, {%8,%9}, {%0,%1,%2,%3};"
        : "+f"(c[0]), "+f"(c[1]), "+f"(c[2]), "+f"(c[3])
        : "r"(a[0]), "r"(a[1]), "r"(a[2]), "r"(a[3]), "r"(b[0]), "r"(b[1]));
}
__device__ __forceinline__ void cp16(uint32_t dst, const void* src) {
    asm volatile("cp.async.cg.shared.global [%0], [%1], 16;" :: "r"(dst), "l"(src));
}
__device__ __forceinline__ void cp16z(uint32_t dst, const void* src, uint32_t ssize) {
    asm volatile("cp.async.cg.shared.global [%0], [%1], 16, %2;" :: "r"(dst), "l"(src), "r"(ssize));
}
#define CP_COMMIT() asm volatile("cp.async.commit_group;" ::: "memory")
#define CP_WAIT1()  asm volatile("cp.async.wait_group 1;" ::: "memory")
__device__ __forceinline__ uint32_t pack_h2(__half a, __half b) {
    union { __half h[2]; uint32_t u; } u;
    u.h[0] = a; u.h[1] = b;
    return u.u;
}

// ================= fp16 single-pass GEMM (K-chunk 64, x4t B loads) =================
// C[M,N] = fp16(A)[M,K] @ fp16(B)[K,N], fp32 accumulate.
// smem per stage: A[TM][72 halfs, 144B rows] | B[64][136 halfs, 272B rows]
template<int TM, int EPI, bool ACC, bool WSPLIT, bool WF32>
__global__ __launch_bounds__(256, 2) void gemm_16(
    const uint16_t* __restrict__ Ah, const uint16_t* __restrict__ Bh,
    float* __restrict__ C, uint16_t* __restrict__ Ch,
    int M, int N, int K, int lda, int ldb, int ldc)
{
    constexpr int MT     = TM / 32;
    constexpr int A_SZ   = TM * 144;
    constexpr int STRIDE = A_SZ + 17408;

    extern __shared__ char dsm[];
    uint32_t sraw = smem_u32(dsm);
    uint32_t s0 = (sraw + 127u) & ~127u;

    int tid = threadIdx.x, wid = tid >> 5, lane = tid & 31;
    int row0 = blockIdx.x * TM, col0 = blockIdx.y * 128;
    int wm = (wid >> 2) * (TM / 2);
    int wn = (wid & 3) * 32;

    float c[MT][4][4];
    #pragma unroll
    for (int mt = 0; mt < MT; mt++)
        #pragma unroll
        for (int nt = 0; nt < 4; nt++)
            #pragma unroll
            for (int r = 0; r < 4; r++) c[mt][nt][r] = 0.f;

    int NC = K >> 6;

    auto issue_copy = [&](int i, int stg) {
        int k0 = i << 6;
        uint32_t sb = s0 + (uint32_t)stg * STRIDE;
        #pragma unroll
        for (int e = tid; e < TM * 8; e += 256) {
            int r = e >> 3, seg = e & 7;
            cp16(sb + (uint32_t)(r * 144 + seg * 16),
                 Ah + (size_t)(row0 + r) * lda + k0 + seg * 8);
        }
        #pragma unroll
        for (int e0 = 0; e0 < 4; e0++) {
            int e = tid + e0 * 256;
            int kk = e >> 4, seg = e & 15;
            int gc = col0 + seg * 8;
            uint32_t d = sb + (uint32_t)A_SZ + (uint32_t)(kk * 272 + seg * 16);
            int rem = N - gc;
            uint32_t sz = rem >= 8 ? 16u : (rem > 0 ? (uint32_t)(rem * 2) : 0u);
            cp16z(d, Bh + (size_t)(k0 + kk) * ldb + gc, sz);
        }
    };

    auto mma_chunk = [&](int stg) {
        uint32_t base = s0 + (uint32_t)stg * STRIDE;
        int arow = wm + ((lane >> 3) & 1) * 8 + (lane & 7);
        int brow = (lane & 7) + ((lane >> 3) & 1) * 8;   // k-row within k16 (lanes 0-15)
        int bsel = ((lane >> 4) & 1) * 8;                // n sub-offset (lanes 16-31 -> +8)
        #pragma unroll
        for (int kk = 0; kk < 64; kk += 16) {
            int acol = kk + ((lane >> 4) & 1) * 8;
            uint32_t af[MT][4], bh[4][2];
            #pragma unroll
            for (int mt = 0; mt < MT; mt++)
                ldsm_x4(af[mt], base + (uint32_t)((arow + mt * 16) * 144 + acol * 2));
            #pragma unroll
            for (int nt2 = 0; nt2 < 2; nt2++) {
                uint32_t bb[4];
                ldsm_x4t(bb, base + (uint32_t)A_SZ
                    + (uint32_t)((kk + brow) * 272 + (wn + nt2 * 16 + bsel) * 2));
                bh[2 * nt2][0]     = bb[0]; bh[2 * nt2][1]     = bb[1];
                bh[2 * nt2 + 1][0] = bb[2]; bh[2 * nt2 + 1][1] = bb[3];
            }
            #pragma unroll
            for (int mt = 0; mt < MT; mt++)
                #pragma unroll
                for (int nt = 0; nt < 4; nt++)
                    mma_f16(c[mt][nt], af[mt], bh[nt]);
        }
    };

    issue_copy(0, 0); CP_COMMIT();
    issue_copy(1, 1); CP_COMMIT();
    for (int i = 0; i < NC; i++) {
        CP_WAIT1();
        __syncthreads();
        mma_chunk(i % 3);
        if (i + 2 < NC) issue_copy(i + 2, (i + 2) % 3);
        CP_COMMIT();
    }

    // ---- epilogue ----
    #pragma unroll
    for (int mt = 0; mt < MT; mt++) {
        #pragma unroll
        for (int nt = 0; nt < 4; nt++) {
            #pragma unroll
            for (int half = 0; half < 2; half++) {
                int grow = row0 + wm + mt * 16 + (lane >> 2) + half * 8;
                int gcol = col0 + wn + nt * 8 + (lane & 3) * 2;
                float v0 = c[mt][nt][half * 2 + 0];
                float v1 = c[mt][nt][half * 2 + 1];
                if (EPI == 1) {
                    float h0 = fmaxf(v0, 0.f); v0 = h0 * h0;
                    float h1 = fmaxf(v1, 0.f); v1 = h1 * h1;
                }
                if (EPI == 2) {
                    v0 = 15.0f * tanhf(v0 * (1.0f / 15.0f));
                    v1 = 15.0f * tanhf(v1 * (1.0f / 15.0f));
                }
                if (gcol + 1 < N) {
                    size_t p = (size_t)grow * ldc + gcol;
                    if (ACC) { v0 += C[p]; v1 += C[p + 1]; }
                    if (WF32) *(float2*)(C + p) = make_float2(v0, v1);
                    if (WSPLIT)
                        *(uint32_t*)(Ch + p) = pack_h2(__float2half(v0), __float2half(v1));
                } else if (gcol < N) {
                    size_t p = (size_t)grow * ldc + gcol;
                    if (ACC) v0 += C[p];
                    if (WF32) C[p] = v0;
                    if (WSPLIT) Ch[p] = __half_as_ushort(__float2half(v0));
                }
            }
        }
    }
}

// ---------------- fp16 weight split (uint4 stores) ----------------
__global__ __launch_bounds__(256) void split16_kernel(
    const float* __restrict__ src, uint16_t* __restrict__ hi, int n8)
{
    int base = blockIdx.x * 1024 + threadIdx.x;
    #pragma unroll
    for (int j = 0; j < 4; j++) {
        int i = base + j * 256;
        if (i >= n8) continue;
        float4 a = ((const float4*)src)[2 * i];
        float4 b = ((const float4*)src)[2 * i + 1];
        union { uint16_t h[8]; uint4 u; } ph;
        ph.h[0] = __half_as_ushort(__float2half(a.x));
        ph.h[1] = __half_as_ushort(__float2half(a.y));
        ph.h[2] = __half_as_ushort(__float2half(a.z));
        ph.h[3] = __half_as_ushort(__float2half(a.w));
        ph.h[4] = __half_as_ushort(__float2half(b.x));
        ph.h[5] = __half_as_ushort(__float2half(b.y));
        ph.h[6] = __half_as_ushort(__float2half(b.z));
        ph.h[7] = __half_as_ushort(__float2half(b.w));
        ((uint4*)hi)[i] = ph.u;
    }
}

// ---------------- block reduce ----------------
__device__ __forceinline__ float blockReduceSum(float v) {
    __shared__ float red[32];
    int lane = threadIdx.x & 31, w = threadIdx.x >> 5;
    #pragma unroll
    for (int o = 16; o; o >>= 1) v += __shfl_xor_sync(0xffffffffu, v, o);
    if (lane == 0) red[w] = v;
    __syncthreads();
    v = (threadIdx.x < (blockDim.x >> 5)) ? red[threadIdx.x] : 0.0f;
    if (w == 0) {
        #pragma unroll
        for (int o = 16; o; o >>= 1) v += __shfl_xor_sync(0xffffffffu, v, o);
        if (lane == 0) red[0] = v;
    }
    __syncthreads();
    return red[0];
}

// ---------------- embed + norms ----------------
__global__ __launch_bounds__(256) void embed_kernel(
    const int* __restrict__ idx, const float* __restrict__ wte,
    float* __restrict__ x, float* __restrict__ x0)
{
    int i = blockIdx.x;
    const float* row = wte + (size_t)idx[i] * C_;
    float v[4]; float ss = 0.f;
    #pragma unroll
    for (int j = 0; j < 4; j++) { v[j] = row[threadIdx.x + j * 256]; ss += v[j] * v[j]; }
    ss = blockReduceSum(ss);
    float sc = rsqrtf(ss / C_ + EPSF);
    #pragma unroll
    for (int j = 0; j < 4; j++) {
        float o = v[j] * sc;
        x [(size_t)i * C_ + threadIdx.x + j * 256] = o;
        x0[(size_t)i * C_ + threadIdx.x + j * 256] = o;
    }
}

__global__ __launch_bounds__(256) void mixnorm_kernel(
    float* __restrict__ x, const float* __restrict__ x0,
    const float* __restrict__ rl, const float* __restrict__ xl, int l,
    float* __restrict__ xn, uint16_t* __restrict__ xnh)
{
    int i = blockIdx.x;
    float a = rl[l], bc = xl[l];
    float v[4]; float ss = 0.f;
    #pragma unroll
    for (int j = 0; j < 4; j++) {
        size_t p = (size_t)i * C_ + threadIdx.x + j * 256;
        v[j] = a * x[p] + bc * x0[p];
        ss += v[j] * v[j];
    }
    ss = blockReduceSum(ss);
    float sc = rsqrtf(ss / C_ + EPSF);
    #pragma unroll
    for (int j = 0; j < 4; j++) {
        size_t p = (size_t)i * C_ + threadIdx.x + j * 256;
        float o = v[j] * sc;
        x[p] = v[j];
        xn[p] = o;
        xnh[p] = __half_as_ushort(__float2half(o));
    }
}

__global__ __launch_bounds__(256) void rmsnorm16_kernel(
    const float* __restrict__ x, uint16_t* __restrict__ xnh)
{
    int i = blockIdx.x;
    float v[4]; float ss = 0.f;
    #pragma unroll
    for (int j = 0; j < 4; j++) {
        v[j] = x[(size_t)i * C_ + threadIdx.x + j * 256];
        ss += v[j] * v[j];
    }
    ss = blockReduceSum(ss);
    float sc = rsqrtf(ss / C_ + EPSF);
    #pragma unroll
    for (int j = 0; j < 4; j++) {
        size_t p = (size_t)i * C_ + threadIdx.x + j * 256;
        xnh[p] = __half_as_ushort(__float2half(v[j] * sc));
    }
}

// ---------------- per-token q/k/v assembly -> fp16 ----------------
__global__ __launch_bounds__(512) void prep_kernel(
    const float* __restrict__ down, const float* __restrict__ kvb,
    const float* __restrict__ qraw, const float* __restrict__ xn,
    const float* __restrict__ cosb, const float* __restrict__ sinb,
    const float* __restrict__ vg, const float* __restrict__ vetab,
    const int* __restrict__ idx,
    uint16_t* __restrict__ Qh, uint16_t* __restrict__ Ql,
    uint16_t* __restrict__ Kh, uint16_t* __restrict__ Vh)
{
    int i = blockIdx.x;
    int b = i / T_, t = i % T_;
    int w = threadIdx.x >> 5, lane = threadIdx.x & 31;
    __shared__ float cs[16], sn[16], kr[32];

    if (threadIdx.x < 16)       cs[threadIdx.x]      = cosb[(size_t)i * 16 + threadIdx.x];
    else if (threadIdx.x < 32)  sn[threadIdx.x - 16] = sinb[(size_t)i * 16 + threadIdx.x - 16];
    __syncthreads();

    float gv = xn[(size_t)i * C_ + lane] * vg[lane * H_ + w];
    #pragma unroll
    for (int o = 16; o; o >>= 1) gv += __shfl_xor_sync(0xffffffffu, gv, o);
    float gate = 2.0f / (1.0f + expf(-gv));

    if (w == 0) {
        int j = lane & 15;
        float x1 = down[(size_t)i * DOWN + 512 + j];
        float x2 = down[(size_t)i * DOWN + 528 + j];
        float cc = cs[j], ssn = sn[j];
        kr[lane] = (lane < 16) ? (x1 * cc + x2 * ssn) : (-x1 * ssn + x2 * cc);
    }
    __syncthreads();

    const float* kvrow = kvb  + (size_t)i * KVW + w * 96;
    const float* qrow  = qraw + (size_t)i * C_  + w * 64;
    const float* verow = vetab + (size_t)idx[i] * C_ + w * 64;

    float k0v = kvrow[lane];
    float k1v = kr[lane];
    float q0v = qrow[lane];
    float q1v;
    {
        int j = lane & 15;
        float a = qrow[32 + j], bb = qrow[48 + j];
        float cc = cs[j], ssn = sn[j];
        q1v = (lane < 16) ? (a * cc + bb * ssn) : (-a * ssn + bb * cc);
    }
    float v0 = kvrow[32 + lane] + gate * verow[lane];
    float v1 = kvrow[64 + lane] + gate * verow[32 + lane];

    float kss = k0v * k0v + k1v * k1v;
    float qss = q0v * q0v + q1v * q1v;
    #pragma unroll
    for (int o = 16; o; o >>= 1) {
        kss += __shfl_xor_sync(0xffffffffu, kss, o);
        qss += __shfl_xor_sync(0xffffffffu, qss, o);
    }
    float ksc = rsqrtf(kss * (1.0f / 64.0f) + EPSF);
    float qsc = rsqrtf(qss * (1.0f / 64.0f) + EPSF);

    size_t base = ((size_t)(b * H_ + w) * T_ + t) * 64;
    float qv0 = q0v * qsc, qv1 = q1v * qsc;
    __half qh0 = __float2half(qv0), qh1 = __float2half(qv1);
    Qh[base + lane]      = __half_as_ushort(qh0);
    Qh[base + 32 + lane] = __half_as_ushort(qh1);
    Ql[base + lane]      = __half_as_ushort(__float2half(qv0 - __half2float(qh0)));
    Ql[base + 32 + lane] = __half_as_ushort(__float2half(qv1 - __half2float(qh1)));
    Kh[base + lane]      = __half_as_ushort(__float2half(k0v * ksc));
    Kh[base + 32 + lane] = __half_as_ushort(__float2half(k1v * ksc));
    Vh[base + lane]      = __half_as_ushort(__float2half(v0));
    Vh[base + 32 + lane] = __half_as_ushort(__float2half(v1));
}

// ---------------- tensor-core flash attention (causal) ----------------
#define ASTR 72
__global__ __launch_bounds__(128) void attn_tc_kernel(
    const uint16_t* __restrict__ Qh, const uint16_t* __restrict__ Ql,
    const uint16_t* __restrict__ Kh, const uint16_t* __restrict__ Vh,
    uint16_t* __restrict__ Yh)
{
    __shared__ uint16_t sqh[64 * ASTR], sql[64 * ASTR];
    __shared__ uint16_t skh[64 * ASTR], svh[64 * ASTR];

    int qt0 = blockIdx.x * 64;
    int bh  = blockIdx.y;
    int b = bh >> 4, h = bh & 15;
    size_t gbase = (size_t)bh * T_ * 64;
    int tid = threadIdx.x, wid = tid >> 5, lane = tid & 31;
    int wm = wid * 16;

    for (int e = tid; e < 1024; e += 128) {
        int r = e >> 4, c4 = (e & 15) << 2;
        *(uint2*)&sqh[r * ASTR + c4] = *(const uint2*)&Qh[gbase + (size_t)(qt0 + r) * 64 + c4];
        *(uint2*)&sql[r * ASTR + c4] = *(const uint2*)&Ql[gbase + (size_t)(qt0 + r) * 64 + c4];
    }
    __syncthreads();

    uint32_t sqh_b = smem_u32(sqh), sql_b = smem_u32(sql);
    uint32_t skh_b = smem_u32(skh), svh_b = smem_u32(svh);

    uint32_t qfh[4][4], qfl[4][4];
    {
        int arow = wm + (lane & 15);
        #pragma unroll
        for (int k = 0; k < 4; k++) {
            int acol = k * 16 + ((lane >> 4) & 1) * 8;
            uint32_t off = (uint32_t)((arow * ASTR + acol) * 2);
            ldsm_x4(qfh[k], sqh_b + off);
            ldsm_x4(qfl[k], sql_b + off);
        }
    }

    float m0 = -1e30f, m1 = -1e30f, l0 = 0.f, l1 = 0.f;
    float o[8][4];
    #pragma unroll
    for (int nt = 0; nt < 8; nt++)
        #pragma unroll
        for (int j = 0; j < 4; j++) o[nt][j] = 0.f;

    int r0g = qt0 + wm + (lane >> 2);
    int niter = qt0 / 64 + 1;

    for (int it = 0; it < niter; it++) {
        int kv0 = it * 64;
        __syncthreads();
        for (int e = tid; e < 1024; e += 128) {
            int r = e >> 4, c4 = (e & 15) << 2;
            *(uint2*)&skh[r * ASTR + c4] = *(const uint2*)&Kh[gbase + (size_t)(kv0 + r) * 64 + c4];
            *(uint2*)&svh[r * ASTR + c4] = *(const uint2*)&Vh[gbase + (size_t)(kv0 + r) * 64 + c4];
        }
        __syncthreads();

        float s[8][4];
        #pragma unroll
        for (int nt = 0; nt < 8; nt++)
            #pragma unroll
            for (int j = 0; j < 4; j++) s[nt][j] = 0.f;
        #pragma unroll
        for (int k = 0; k < 4; k++) {
            #pragma unroll
            for (int nt = 0; nt < 8; nt++) {
                uint32_t bf[2];
                ldsm_x2(bf, skh_b + (uint32_t)(((nt * 8 + (lane & 7)) * ASTR
                            + k * 16 + ((lane >> 3) & 1) * 8) * 2));
                mma_f16(s[nt], qfh[k], bf);
                mma_f16(s[nt], qfl[k], bf);
            }
        }

        bool edge = (kv0 == qt0);
        #pragma unroll
        for (int nt = 0; nt < 8; nt++) {
            #pragma unroll
            for (int j = 0; j < 4; j++) s[nt][j] *= 0.125f;
            if (edge) {
                int c0 = kv0 + nt * 8 + 2 * (lane & 3);
                if (c0     > r0g)     s[nt][0] = -1e30f;
                if (c0 + 1 > r0g)     s[nt][1] = -1e30f;
                if (c0     > r0g + 8) s[nt][2] = -1e30f;
                if (c0 + 1 > r0g + 8) s[nt][3] = -1e30f;
            }
        }

        float rm0 = -1e30f, rm1 = -1e30f;
        #pragma unroll
        for (int nt = 0; nt < 8; nt++) {
            rm0 = fmaxf(rm0, fmaxf(s[nt][0], s[nt][1]));
            rm1 = fmaxf(rm1, fmaxf(s[nt][2], s[nt][3]));
        }
        rm0 = fmaxf(rm0, __shfl_xor_sync(0xffffffffu, rm0, 1));
        rm0 = fmaxf(rm0, __shfl_xor_sync(0xffffffffu, rm0, 2));
        rm1 = fmaxf(rm1, __shfl_xor_sync(0xffffffffu, rm1, 1));
        rm1 = fmaxf(rm1, __shfl_xor_sync(0xffffffffu, rm1, 2));
        float mn0 = fmaxf(m0, rm0), mn1 = fmaxf(m1, rm1);
        float corr0 = __expf(m0 - mn0), corr1 = __expf(m1 - mn1);
        m0 = mn0; m1 = mn1;
        float sum0 = 0.f, sum1 = 0.f;
        #pragma unroll
        for (int nt = 0; nt < 8; nt++) {
            s[nt][0] = __expf(s[nt][0] - mn0);
            s[nt][1] = __expf(s[nt][1] - mn0);
            s[nt][2] = __expf(s[nt][2] - mn1);
            s[nt][3] = __expf(s[nt][3] - mn1);
            sum0 += s[nt][0] + s[nt][1];
            sum1 += s[nt][2] + s[nt][3];
        }
        sum0 += __shfl_xor_sync(0xffffffffu, sum0, 1);
        sum0 += __shfl_xor_sync(0xffffffffu, sum0, 2);
        sum1 += __shfl_xor_sync(0xffffffffu, sum1, 1);
        sum1 += __shfl_xor_sync(0xffffffffu, sum1, 2);
        l0 = l0 * corr0 + sum0;
        l1 = l1 * corr1 + sum1;
        #pragma unroll
        for (int nt = 0; nt < 8; nt++) {
            o[nt][0] *= corr0; o[nt][1] *= corr0;
            o[nt][2] *= corr1; o[nt][3] *= corr1;
        }

        #pragma unroll
        for (int k = 0; k < 4; k++) {
            uint32_t ph[4], pl[4];
            {
                float a0 = s[2*k][0],   a1 = s[2*k][1],   a2 = s[2*k][2],   a3 = s[2*k][3];
                float b0 = s[2*k+1][0], b1 = s[2*k+1][1], b2 = s[2*k+1][2], b3 = s[2*k+1][3];
                __half ha0 = __float2half(a0), ha1 = __float2half(a1);
                __half ha2 = __float2half(a2), ha3 = __float2half(a3);
                __half hb0 = __float2half(b0), hb1 = __float2half(b1);
                __half hb2 = __float2half(b2), hb3 = __float2half(b3);
                ph[0] = pack_h2(ha0, ha1); ph[1] = pack_h2(ha2, ha3);
                ph[2] = pack_h2(hb0, hb1); ph[3] = pack_h2(hb2, hb3);
                pl[0] = pack_h2(__float2half(a0 - __half2float(ha0)), __float2half(a1 - __half2float(ha1)));
                pl[1] = pack_h2(__float2half(a2 - __half2float(ha2)), __float2half(a3 - __half2float(ha3)));
                pl[2] = pack_h2(__float2half(b0 - __half2float(hb0)), __float2half(b1 - __half2float(hb1)));
                pl[3] = pack_h2(__float2half(b2 - __half2float(hb2)), __float2half(b3 - __half2float(hb3)));
            }
            #pragma unroll
            for (int nt = 0; nt < 8; nt++) {
                uint32_t bf[2];
                ldsm_x2t(bf, svh_b + (uint32_t)(((k * 16 + (lane & 15)) * ASTR + nt * 8) * 2));
                mma_f16(o[nt], ph, bf);
                mma_f16(o[nt], pl, bf);
            }
        }
    }

    float inv0 = 1.0f / l0, inv1 = 1.0f / l1;
    #pragma unroll
    for (int nt = 0; nt < 8; nt++) {
        int col = h * 64 + nt * 8 + 2 * (lane & 3);
        size_t p0 = ((size_t)(b * T_ + r0g)) * C_ + col;
        size_t p1 = ((size_t)(b * T_ + r0g + 8)) * C_ + col;
        *(uint32_t*)(Yh + p0) = pack_h2(__float2half(o[nt][0] * inv0), __float2half(o[nt][1] * inv0));
        *(uint32_t*)(Yh + p1) = pack_h2(__float2half(o[nt][2] * inv1), __float2half(o[nt][3] * inv1));
    }
}

// ---------------- host side ----------------
template<typename Tp>
static Tp* sym_addr(const void* sym) {
    void* p = nullptr;
    cudaGetSymbolAddress(&p, sym);
    return (Tp*)p;
}

struct GemmArgs {
    const uint16_t *Ah, *Bh;
    float* C; uint16_t *Ch;
    int M, N, K, lda, ldb, ldc;
};

template<int TM, int EPI, bool ACC, bool WSPLIT, bool WF32>
static void launch_g(const GemmArgs& a, cudaStream_t st = 0) {
    constexpr int STRIDE = (TM * 144) + 17408;
    constexpr int DSMEM  = 3 * STRIDE + 128;
    static bool done = false;
    if (!done) {
        cudaFuncSetAttribute(gemm_16<TM, EPI, ACC, WSPLIT, WF32>,
                             cudaFuncAttributeMaxDynamicSharedMemorySize, DSMEM);
        done = true;
    }
    dim3 grid(a.M / TM, (a.N + 127) / 128);
    gemm_16<TM, EPI, ACC, WSPLIT, WF32><<<grid, 256, DSMEM, st>>>(
        a.Ah, a.Bh, a.C, a.Ch, a.M, a.N, a.K, a.lda, a.ldb, a.ldc);
}

static void split_w16(const float* src, uint16_t* hi, size_t n, cudaStream_t st) {
    int n8 = (int)(n / 8);
    split16_kernel<<<(n8 + 1023) / 1024, 256, 0, st>>>(src, hi, n8);
}

extern "C" void kernel_launch(void* const* d_in, const int* in_sizes, int n_in,
                              void* d_out, int out_size)
{
    (void)in_sizes; (void)n_in; (void)out_size;
    const int*   idx   = (const int*)  d_in[0];
    const float* cosb  = (const float*)d_in[1];
    const float* sinb  = (const float*)d_in[2];
    const float* wte   = (const float*)d_in[3];
    const float* vetab = (const float*)d_in[4];
    const float* wd    = (const float*)d_in[5];
    const float* wukv  = (const float*)d_in[6];
    const float* wuq   = (const float*)d_in[7];
    const float* vg    = (const float*)d_in[8];
    const float* ap    = (const float*)d_in[9];
    const float* fc    = (const float*)d_in[10];
    const float* pj    = (const float*)d_in[11];
    const float* rl    = (const float*)d_in[12];
    const float* xl    = (const float*)d_in[13];
    const float* lmh   = (const float*)d_in[14];
    float* out = (float*)d_out;

    static cudaStream_t s1 = nullptr, s2 = nullptr;
    static cudaEvent_t ev_fork = nullptr, ev_small = nullptr,
                       ev_fc = nullptr, ev_pj = nullptr, ev_lmh = nullptr,
                       ev_wd = nullptr, ev_q = nullptr;
    if (!s1) {
        cudaStreamCreateWithFlags(&s1, cudaStreamNonBlocking);
        cudaStreamCreateWithFlags(&s2, cudaStreamNonBlocking);
        cudaEventCreateWithFlags(&ev_fork,  cudaEventDisableTiming);
        cudaEventCreateWithFlags(&ev_small, cudaEventDisableTiming);
        cudaEventCreateWithFlags(&ev_fc,    cudaEventDisableTiming);
        cudaEventCreateWithFlags(&ev_pj,    cudaEventDisableTiming);
        cudaEventCreateWithFlags(&ev_lmh,   cudaEventDisableTiming);
        cudaEventCreateWithFlags(&ev_wd,    cudaEventDisableTiming);
        cudaEventCreateWithFlags(&ev_q,     cudaEventDisableTiming);
    }

    float* px    = sym_addr<float>(g_x);
    float* px0   = sym_addr<float>(g_x0);
    float* pxn   = sym_addr<float>(g_xn);
    float* pdown = sym_addr<float>(g_down);
    float* pkv   = sym_addr<float>(g_kv);
    float* pqraw = sym_addr<float>(g_qraw);

    uint16_t *pqh = sym_addr<uint16_t>(g_qh), *pql = sym_addr<uint16_t>(g_ql);
    uint16_t *pkh = sym_addr<uint16_t>(g_kh), *pvh = sym_addr<uint16_t>(g_vh);

    uint16_t *wdh = sym_addr<uint16_t>(s_wd_h);
    uint16_t *ukh = sym_addr<uint16_t>(s_wukv_h);
    uint16_t *uqh = sym_addr<uint16_t>(s_wuq_h);
    uint16_t *aph = sym_addr<uint16_t>(s_ap_h);
    uint16_t *fch = sym_addr<uint16_t>(s_fc_h);
    uint16_t *pjh = sym_addr<uint16_t>(s_pj_h);
    uint16_t *lmhh = sym_addr<uint16_t>(s_lmh_h);
    uint16_t *xnh = sym_addr<uint16_t>(s_xn_h);
    uint16_t *dnh = sym_addr<uint16_t>(s_dn_h);
    uint16_t *hhh = sym_addr<uint16_t>(s_h_h);
    uint16_t *yh  = sym_addr<uint16_t>(s_y_h);

    cudaEventRecord(ev_fork, 0);
    cudaStreamWaitEvent(s1, ev_fork, 0);
    split_w16(wd,   wdh,  (size_t)L_ * C_ * DOWN, s1);
    split_w16(wukv, ukh,  (size_t)L_ * DC * KVW,  s1);
    split_w16(wuq,  uqh,  (size_t)L_ * DC1 * C_,  s1);
    split_w16(ap,   aph,  (size_t)L_ * C_ * C_,   s1);
    cudaEventRecord(ev_small, s1);
    split_w16(fc,   fch,  (size_t)L_ * C_ * 4096, s1);
    cudaEventRecord(ev_fc, s1);
    split_w16(pj,   pjh,  (size_t)L_ * 4096 * C_, s1);
    cudaEventRecord(ev_pj, s1);
    split_w16(lmh,  lmhh, (size_t)C_ * VSZ,       s1);
    cudaEventRecord(ev_lmh, s1);

    embed_kernel<<<TKN, 256>>>(idx, wte, px, px0);
    cudaStreamWaitEvent(0, ev_small, 0);

    for (int l = 0; l < L_; l++) {
        mixnorm_kernel<<<TKN, 256>>>(px, px0, rl, xl, l, pxn, xnh);

        launch_g<64, 0, false, true, true>({ xnh,
            wdh + (size_t)l * C_ * DOWN,
            pdown, dnh, TKN, DOWN, C_, C_, DOWN, DOWN });
        cudaEventRecord(ev_wd, 0);

        cudaStreamWaitEvent(s2, ev_wd, 0);
        launch_g<64, 0, false, false, true>({ dnh + DC,
            uqh + (size_t)l * DC1 * C_,
            pqraw, nullptr, TKN, C_, DC1, DOWN, C_, C_ }, s2);
        cudaEventRecord(ev_q, s2);

        launch_g<64, 0, false, false, true>({ dnh,
            ukh + (size_t)l * DC * KVW,
            pkv, nullptr, TKN, KVW, DC, DOWN, KVW, KVW });

        cudaStreamWaitEvent(0, ev_q, 0);
        prep_kernel<<<TKN, 512>>>(pdown, pkv, pqraw, pxn, cosb, sinb,
                                  vg + (size_t)l * GC * H_,
                                  vetab + (size_t)l * VSZ * C_,
                                  idx, pqh, pql, pkh, pvh);

        attn_tc_kernel<<<dim3(T_ / 64, B_ * H_), 128>>>(pqh, pql, pkh, pvh, yh);

        launch_g<64, 0, true, false, true>({ yh,
            aph + (size_t)l * C_ * C_,
            px, nullptr, TKN, C_, C_, C_, C_, C_ });

        rmsnorm16_kernel<<<TKN, 256>>>(px, xnh);

        if (l == 0) cudaStreamWaitEvent(0, ev_fc, 0);
        launch_g<128, 1, false, true, false>({ xnh,
            fch + (size_t)l * C_ * 4096,
            nullptr, hhh, TKN, 4096, C_, C_, 4096, 4096 });
        if (l == 0) cudaStreamWaitEvent(0, ev_pj, 0);
        launch_g<64, 0, true, false, true>({ hhh,
            pjh + (size_t)l * 4096 * C_,
            px, nullptr, TKN, C_, 4096, 4096, C_, C_ });
    }

    rmsnorm16_kernel<<<TKN, 256>>>(px, xnh);
    cudaStreamWaitEvent(0, ev_lmh, 0);
    launch_g<128, 2, false, false, true>({ xnh, lmhh,
        out, nullptr, TKN, VSZ, C_, C_, VSZ, VSZ });
}